// round 1
// baseline (speedup 1.0000x reference)
#include <cuda_runtime.h>
#include <cstdint>

#define NN 50000
#define NE 300000
#define HD 256
#define NB 8
#define NL 4

// ---------------- scratch (static device globals; no allocs allowed) -------
__device__ float g_h [NN*HD];
__device__ float g_d1[NN*HD];
__device__ float g_d2[NN*HD];
__device__ float g_d3[NN*HD];
__device__ float g_ae[NN*HD];
__device__ float g_deg[NN];
__device__ float g_ps[24*HD];
__device__ float g_pc[24];

__device__ __forceinline__ void redAdd4(float* p, float4 v) {
    asm volatile("red.global.add.v4.f32 [%0], {%1,%2,%3,%4};"
                 :: "l"(p), "f"(v.x), "f"(v.y), "f"(v.z), "f"(v.w) : "memory");
}

// ---------------- GEMM: C[M,256] = A@W (+A2@W2) (+bias[*rowscale]) (relu) --
// BM=128, BN=64, BK=16, 256 threads, 8x4 micro-tile per thread.
template<bool DUAL, bool RELU, bool ROWSCALE>
__global__ void __launch_bounds__(256) gemm_k(
    const float* __restrict__ A,  const float* __restrict__ W,
    const float* __restrict__ A2, const float* __restrict__ W2,
    const float* __restrict__ bias, const float* __restrict__ rowscale,
    float* __restrict__ C, int M)
{
    __shared__ float As[16][128];
    __shared__ float Ws[16][64];
    const int bm = blockIdx.x * 128;
    const int bn = blockIdx.y * 64;
    const int tid = threadIdx.x;
    const int tx = tid & 15, ty = tid >> 4;
    const int r = tid >> 2, q = tid & 3;
    const int wk = tid >> 4, wq = tid & 15;
    float acc[8][4] = {};

    const int npass = DUAL ? 2 : 1;
    for (int pass = 0; pass < npass; ++pass) {
        const float* Ap = (DUAL && pass) ? A2 : A;
        const float* Wp = (DUAL && pass) ? W2 : W;
        for (int k0 = 0; k0 < 256; k0 += 16) {
            #pragma unroll
            for (int rr = 0; rr < 2; ++rr) {
                int row = bm + r + rr*64;
                float4 v = make_float4(0.f,0.f,0.f,0.f);
                if (row < M) v = *(const float4*)(Ap + (size_t)row*256 + k0 + q*4);
                As[q*4+0][r+rr*64] = v.x;
                As[q*4+1][r+rr*64] = v.y;
                As[q*4+2][r+rr*64] = v.z;
                As[q*4+3][r+rr*64] = v.w;
            }
            *(float4*)&Ws[wk][wq*4] =
                *(const float4*)(Wp + (size_t)(k0+wk)*256 + bn + wq*4);
            __syncthreads();
            #pragma unroll
            for (int k = 0; k < 16; ++k) {
                float4 w4 = *(float4*)&Ws[k][tx*4];
                #pragma unroll
                for (int i = 0; i < 8; ++i) {
                    float a = As[k][ty*8+i];
                    acc[i][0] += a*w4.x; acc[i][1] += a*w4.y;
                    acc[i][2] += a*w4.z; acc[i][3] += a*w4.w;
                }
            }
            __syncthreads();
        }
    }

    float4 bv = make_float4(0.f,0.f,0.f,0.f);
    if (bias) bv = *(const float4*)(bias + bn + tx*4);
    #pragma unroll
    for (int i = 0; i < 8; ++i) {
        int row = bm + ty*8 + i;
        if (row >= M) break;
        float s = ROWSCALE ? rowscale[row] : 1.f;
        float4 o;
        o.x = acc[i][0] + bv.x*s;
        o.y = acc[i][1] + bv.y*s;
        o.z = acc[i][2] + bv.z*s;
        o.w = acc[i][3] + bv.w*s;
        if (RELU) {
            o.x = fmaxf(o.x,0.f); o.y = fmaxf(o.y,0.f);
            o.z = fmaxf(o.z,0.f); o.w = fmaxf(o.w,0.f);
        }
        *(float4*)(C + (size_t)row*256 + bn + tx*4) = o;
    }
}

// ---------------- node encoder: h1 = relu(cat(relu(x128@geoW+b), x[128:])@W1+b1)
__global__ void __launch_bounds__(256) node_encode_k(
    const float* __restrict__ x,
    const float* __restrict__ geo_w, const float* __restrict__ geo_b,
    const float* __restrict__ w1, const float* __restrict__ b1,
    float* __restrict__ out)
{
    extern __shared__ float sm[];
    float* gws = sm;              // 128*32
    float* gbs = gws + 4096;      // 32
    float* w1s = gbs + 32;        // 64*256
    float* b1s = w1s + 16384;     // 256
    float* xin = b1s + 256;       // 8*64
    for (int i = threadIdx.x; i < 4096;  i += 256) gws[i] = geo_w[i];
    for (int i = threadIdx.x; i < 16384; i += 256) w1s[i] = w1[i];
    if (threadIdx.x < 32)  gbs[threadIdx.x] = geo_b[threadIdx.x];
    b1s[threadIdx.x] = b1[threadIdx.x];
    __syncthreads();

    const int warp = threadIdx.x >> 5, lane = threadIdx.x & 31;
    for (int n0 = blockIdx.x*8; n0 < NN; n0 += gridDim.x*8) {
        int n = n0 + warp;
        if (n < NN) {
            const float* xr = x + (size_t)n*160;
            float s = gbs[lane];
            #pragma unroll
            for (int k = 0; k < 128; ++k) s += __ldg(xr+k) * gws[k*32 + lane];
            xin[warp*64 + lane]      = fmaxf(s, 0.f);
            xin[warp*64 + 32 + lane] = __ldg(xr + 128 + lane);
        }
        __syncthreads();
        #pragma unroll
        for (int p = 0; p < 8; ++p) {
            int n2 = n0 + p;
            if (n2 >= NN) break;
            float acc = b1s[threadIdx.x];
            #pragma unroll
            for (int k = 0; k < 64; ++k) acc += xin[p*64+k] * w1s[k*256 + threadIdx.x];
            out[(size_t)n2*256 + threadIdx.x] = fmaxf(acc, 0.f);
        }
        __syncthreads();
    }
}

// ---------------- edge encoder + scatter: At[dst] += relu(ea@W1+b1); deg[dst]++
__global__ void __launch_bounds__(256) edge_encode_k(
    const float* __restrict__ ea, const int* __restrict__ eidx,
    const float* __restrict__ w1, const float* __restrict__ b1,
    float* __restrict__ At, float* __restrict__ deg)
{
    __shared__ float w1s[16*256];
    __shared__ float b1s[256];
    __shared__ float ts[8][256];
    for (int i = threadIdx.x; i < 4096; i += 256) w1s[i] = w1[i];
    b1s[threadIdx.x] = b1[threadIdx.x];
    __syncthreads();

    const int warp = threadIdx.x >> 5, lane = threadIdx.x & 31;
    for (int e0 = blockIdx.x*8; e0 < NE; e0 += gridDim.x*8) {
        int e = e0 + warp;
        if (e < NE) {
            const float* row = ea + (size_t)e*16;
            float eav[16];
            #pragma unroll
            for (int k = 0; k < 16; ++k) eav[k] = __ldg(row+k);
            #pragma unroll
            for (int i = 0; i < 8; ++i) {
                int col = lane + 32*i;
                float s = b1s[col];
                #pragma unroll
                for (int k = 0; k < 16; ++k) s += eav[k] * w1s[k*256 + col];
                ts[warp][col] = fmaxf(s, 0.f);
            }
            __syncwarp();
            int dst = eidx[NE + e];
            float* dp = At + (size_t)dst*256;
            int c = lane*8;
            redAdd4(dp + c,     *(float4*)&ts[warp][c]);
            redAdd4(dp + c + 4, *(float4*)&ts[warp][c+4]);
            if (lane == 0) atomicAdd(deg + dst, 1.f);
        }
    }
}

// ---------------- SpMM scatter: agg[dst] += h[src] --------------------------
__global__ void __launch_bounds__(256) spmm_k(
    const float* __restrict__ h, const int* __restrict__ eidx,
    float* __restrict__ agg)
{
    int gw = (blockIdx.x*blockDim.x + threadIdx.x) >> 5;
    int lane = threadIdx.x & 31;
    int nw = (gridDim.x*blockDim.x) >> 5;
    for (int e = gw; e < NE; e += nw) {
        int src = eidx[e];
        int dst = eidx[NE + e];
        const float* hp = h + (size_t)src*256;
        float* ap = agg + (size_t)dst*256;
        int c = lane*8;
        float4 v0 = *(const float4*)(hp + c);
        float4 v1 = *(const float4*)(hp + c + 4);
        redAdd4(ap + c,     v0);
        redAdd4(ap + c + 4, v1);
    }
}

// ---------------- residual + layernorm (warp per row) -----------------------
__global__ void __launch_bounds__(256) ln_k(
    float* __restrict__ h, const float* __restrict__ u,
    const float* __restrict__ g, const float* __restrict__ b)
{
    int gw = (blockIdx.x*blockDim.x + threadIdx.x) >> 5;
    int lane = threadIdx.x & 31;
    int nw = (gridDim.x*blockDim.x) >> 5;
    for (int n = gw; n < NN; n += nw) {
        float* hp = h + (size_t)n*256;
        const float* up = u + (size_t)n*256;
        float v[8];
        float4 h0 = *(float4*)(hp + lane*8),       h1 = *(float4*)(hp + lane*8 + 4);
        float4 u0 = *(const float4*)(up + lane*8), u1 = *(const float4*)(up + lane*8 + 4);
        v[0]=h0.x+u0.x; v[1]=h0.y+u0.y; v[2]=h0.z+u0.z; v[3]=h0.w+u0.w;
        v[4]=h1.x+u1.x; v[5]=h1.y+u1.y; v[6]=h1.z+u1.z; v[7]=h1.w+u1.w;
        float s = 0.f;
        #pragma unroll
        for (int i = 0; i < 8; ++i) s += v[i];
        #pragma unroll
        for (int o = 16; o > 0; o >>= 1) s += __shfl_xor_sync(0xffffffffu, s, o);
        float mu = s * (1.f/256.f);
        float qq = 0.f;
        #pragma unroll
        for (int i = 0; i < 8; ++i) { float d = v[i]-mu; qq += d*d; }
        #pragma unroll
        for (int o = 16; o > 0; o >>= 1) qq += __shfl_xor_sync(0xffffffffu, qq, o);
        float rstd = rsqrtf(qq*(1.f/256.f) + 1e-5f);
        #pragma unroll
        for (int i = 0; i < 8; ++i) {
            int c = lane*8 + i;
            v[i] = (v[i]-mu)*rstd*__ldg(g+c) + __ldg(b+c);
        }
        *(float4*)(hp + lane*8)     = make_float4(v[0],v[1],v[2],v[3]);
        *(float4*)(hp + lane*8 + 4) = make_float4(v[4],v[5],v[6],v[7]);
    }
}

// ---------------- typed mean-pool partial sums -------------------------------
__global__ void __launch_bounds__(256) pool_k(
    const float* __restrict__ h, const int* __restrict__ batch,
    const int* __restrict__ ntype, float* __restrict__ ps, float* __restrict__ pc)
{
    __shared__ float acc[24][256];
    __shared__ float cnt[24];
    for (int i = threadIdx.x; i < 24*256; i += 256) (&acc[0][0])[i] = 0.f;
    if (threadIdx.x < 24) cnt[threadIdx.x] = 0.f;
    __syncthreads();
    int per = (NN + gridDim.x - 1) / gridDim.x;
    int start = blockIdx.x * per;
    int end = start + per; if (end > NN) end = NN;
    for (int n = start; n < end; ++n) {
        int idx = __ldg(ntype+n)*8 + __ldg(batch+n);
        acc[idx][threadIdx.x] += h[(size_t)n*256 + threadIdx.x];
        if (threadIdx.x == 0) cnt[idx] += 1.f;
    }
    __syncthreads();
    for (int i = threadIdx.x; i < 24*256; i += 256) atomicAdd(&ps[i], (&acc[0][0])[i]);
    if (threadIdx.x < 24) atomicAdd(&pc[threadIdx.x], cnt[threadIdx.x]);
}

// ---------------- final write: z | h | batch ---------------------------------
__global__ void __launch_bounds__(256) writeout_k(
    const float* __restrict__ ps, const float* __restrict__ pc,
    const float* __restrict__ h, const int* __restrict__ batch,
    float* __restrict__ out, int out_size)
{
    const int total = 24*256 + NN*HD + NN;
    for (int i = blockIdx.x*blockDim.x + threadIdx.x; i < total;
         i += gridDim.x*blockDim.x) {
        float v; int o;
        if (i < 6144) {
            int c = i & 255, kb = i >> 8, k = kb >> 3, bb = kb & 7;
            float cc = pc[kb]; if (cc < 1.f) cc = 1.f;
            v = ps[i] / cc;
            o = bb*768 + k*256 + c;
        } else if (i < 6144 + NN*HD) {
            v = h[i - 6144]; o = i;
        } else {
            v = (float)batch[i - 6144 - NN*HD]; o = i;
        }
        if (o < out_size) out[o] = v;
    }
}

// ---------------- launcher ----------------------------------------------------
extern "C" void kernel_launch(void* const* d_in, const int* in_sizes, int n_in,
                              void* d_out, int out_size)
{
    const float* x       = (const float*)d_in[0];
    const float* ea      = (const float*)d_in[1];
    const float* geo_w   = (const float*)d_in[2];
    const float* geo_b   = (const float*)d_in[3];
    const float* nin_w1  = (const float*)d_in[4];
    const float* nin_b1  = (const float*)d_in[5];
    const float* nin_w2  = (const float*)d_in[6];
    const float* nin_b2  = (const float*)d_in[7];
    const float* ee_w1   = (const float*)d_in[8];
    const float* ee_b1   = (const float*)d_in[9];
    const float* ee_w2   = (const float*)d_in[10];
    const float* ee_b2   = (const float*)d_in[11];
    const float* msgx    = (const float*)d_in[12];
    const float* msge    = (const float*)d_in[13];
    const float* upd_w1  = (const float*)d_in[14];
    const float* upd_b1  = (const float*)d_in[15];
    const float* upd_w2  = (const float*)d_in[16];
    const float* upd_b2  = (const float*)d_in[17];
    const float* ln_g    = (const float*)d_in[18];
    const float* ln_b    = (const float*)d_in[19];
    const int*   eidx    = (const int*)d_in[20];
    const int*   batch   = (const int*)d_in[21];
    const int*   ntype   = (const int*)d_in[22];
    float* out = (float*)d_out;

    float *h_, *d1_, *d2_, *d3_, *ae_, *deg_, *ps_, *pc_;
    cudaGetSymbolAddress((void**)&h_,  g_h);
    cudaGetSymbolAddress((void**)&d1_, g_d1);
    cudaGetSymbolAddress((void**)&d2_, g_d2);
    cudaGetSymbolAddress((void**)&d3_, g_d3);
    cudaGetSymbolAddress((void**)&ae_, g_ae);
    cudaGetSymbolAddress((void**)&deg_, g_deg);
    cudaGetSymbolAddress((void**)&ps_, g_ps);
    cudaGetSymbolAddress((void**)&pc_, g_pc);

    const int NE_SMEM = (4096 + 32 + 16384 + 256 + 512) * 4;   // 85120 B
    cudaFuncSetAttribute(node_encode_k,
        cudaFuncAttributeMaxDynamicSharedMemorySize, NE_SMEM);

    dim3 gg(391, 4);   // ceil(50000/128) x (256/64)

    // node input encoder: d1 = h1
    node_encode_k<<<625, 256, NE_SMEM>>>(x, geo_w, geo_b, nin_w1, nin_b1, d1_);
    // h = h1 @ nin_w2 + nin_b2
    gemm_k<false,false,false><<<gg, 256>>>(d1_, nin_w2, nullptr, nullptr,
                                           nin_b2, nullptr, h_, NN);
    // edge encoder scatter: d2 = segsum(relu(ea@W1+b1)), deg = indegree
    cudaMemsetAsync(d2_, 0, (size_t)NN*HD*sizeof(float));
    cudaMemsetAsync(deg_, 0, (size_t)NN*sizeof(float));
    edge_encode_k<<<592, 256>>>(ea, eidx, ee_w1, ee_b1, d2_, deg_);
    // Ae = d2 @ ee_w2 + deg * ee_b2
    gemm_k<false,false,true><<<gg, 256>>>(d2_, ee_w2, nullptr, nullptr,
                                          ee_b2, deg_, ae_, NN);

    for (int l = 0; l < NL; ++l) {
        const float* mx = msgx + (size_t)l*65536;
        const float* me = msge + (size_t)l*65536;
        const float* u1 = upd_w1 + (size_t)l*65536;
        const float* u2 = upd_w2 + (size_t)l*65536;
        // agg = A @ h
        cudaMemsetAsync(d1_, 0, (size_t)NN*HD*sizeof(float));
        spmm_k<<<1184, 256>>>(h_, eidx, d1_);
        // d2 = agg@msgx + Ae@msge
        gemm_k<true,false,false><<<gg, 256>>>(d1_, mx, ae_, me,
                                              nullptr, nullptr, d2_, NN);
        // d3 = relu(d2@upd_w1 + b1)
        gemm_k<false,true,false><<<gg, 256>>>(d2_, u1, nullptr, nullptr,
                                              upd_b1 + l*256, nullptr, d3_, NN);
        // d1 = d3@upd_w2 + b2
        gemm_k<false,false,false><<<gg, 256>>>(d3_, u2, nullptr, nullptr,
                                               upd_b2 + l*256, nullptr, d1_, NN);
        // h = LN(h + d1)
        ln_k<<<784, 256>>>(h_, d1_, ln_g + l*256, ln_b + l*256);
    }

    cudaMemsetAsync(ps_, 0, 24*HD*sizeof(float));
    cudaMemsetAsync(pc_, 0, 24*sizeof(float));
    pool_k<<<256, 256>>>(h_, batch, ntype, ps_, pc_);
    writeout_k<<<8192, 256>>>(ps_, pc_, h_, batch, out, out_size);
}

// round 3
// speedup vs baseline: 1.3003x; 1.3003x over previous
#include <cuda_runtime.h>
#include <cstdint>

#define NN 50000
#define NE 300000
#define HD 256
#define NB 8
#define NL 4

// ---------------- scratch (static device globals; no allocs allowed) -------
__device__ float g_h [NN*HD];
__device__ float g_d1[NN*HD];
__device__ float g_d2[NN*HD];
__device__ float g_d3[NN*HD];
__device__ float g_ae[NN*HD];
__device__ float g_deg[NN];
__device__ float g_ps[24*HD];
__device__ float g_pc[24];
__device__ float g_wt[18*65536];   // transposed+tf32-rounded weights [N,K]

// ---------------- helpers ------------------------------------------------
__device__ __forceinline__ float tf32r(float x) {
    float r;
    asm("cvt.rna.tf32.f32 %0, %1;" : "=f"(r) : "f"(x));
    return r;
}
__device__ __forceinline__ void redAdd4(float* p, float4 v) {
    asm volatile("red.global.add.v4.f32 [%0], {%1,%2,%3,%4};"
                 :: "l"(p), "f"(v.x), "f"(v.y), "f"(v.z), "f"(v.w) : "memory");
}
#define MMA_TF32(c, a4, b0, b1)                                              \
    asm volatile("mma.sync.aligned.m16n8k8.row.col.f32.tf32.tf32.f32 "      \
        "{%0,%1,%2,%3}, {%4,%5,%6,%7}, {%8,%9}, {%0,%1,%2,%3};"             \
        : "+f"((c)[0]), "+f"((c)[1]), "+f"((c)[2]), "+f"((c)[3])            \
        : "r"((a4).x), "r"((a4).y), "r"((a4).z), "r"((a4).w),               \
          "r"(b0), "r"(b1))

// ---------------- weight transpose + tf32 round: Wt[n,k] = rna(W[k,n]) -----
struct WPtrs { const float* p[18]; };

__global__ void __launch_bounds__(256) wtrans_k(WPtrs wp, float* __restrict__ out) {
    __shared__ float t[32][33];
    const float* W = wp.p[blockIdx.z];
    float* O = out + (size_t)blockIdx.z * 65536;
    int n0 = blockIdx.x * 32, k0 = blockIdx.y * 32;
    int tx = threadIdx.x & 31, ty = threadIdx.x >> 5;  // 32x8
    #pragma unroll
    for (int i = 0; i < 32; i += 8)
        t[ty + i][tx] = W[(size_t)(k0 + ty + i) * 256 + n0 + tx];
    __syncthreads();
    #pragma unroll
    for (int i = 0; i < 32; i += 8)
        O[(size_t)(n0 + ty + i) * 256 + k0 + tx] = tf32r(t[tx][ty + i]);
}

// ---------------- tensor-core GEMM via mma.sync tf32 ------------------------
// C[M,256] = A@W (+A2@W2) (+bias[*rowscale]) (relu)
// CTA: BM=128, BN=128, BK=32 double-buffered; 8 warps = 4(M) x 2(N);
// warp tile 32x64 = 2x8 m16n8k8 tiles. Fragment-major smem staging.
#define GEMM_SMEM 65536

template<bool DUAL, bool RELU, bool ROWSCALE>
__global__ void __launch_bounds__(256) gemm_mma(
    const float* __restrict__ A,  const float* __restrict__ Wt,
    const float* __restrict__ A2, const float* __restrict__ Wt2,
    const float* __restrict__ bias, const float* __restrict__ rowscale,
    float* __restrict__ C, int M)
{
    extern __shared__ float smf[];
    float* sA = smf;            // 2 x 4096 floats
    float* sB = smf + 8192;     // 2 x 4096 floats

    const int tid = threadIdx.x;
    const int wid = tid >> 5, lane = tid & 31;
    const int warp_m = wid & 3, warp_n = wid >> 2;
    const int bm = blockIdx.x * 128;
    const int bn = blockIdx.y * 128;

    const int ar = tid >> 1;            // row within tile (0..127)
    const int aq = (tid & 1) * 16;      // col half (0 / 16)
    const int arow = bm + ar;
    // A fragment store constants
    const int a_mtile = ar >> 4;
    const int a_rowbit = (ar >> 3) & 1;
    const int a_lhi = (ar & 7) << 2;
    // B fragment store constants (n_local = ar)
    const int b_nin = ar & 7;
    const int b_p = ar >> 4;            // (ar>>3)>>1
    const int b_half = (ar >> 3) & 1;

    float acc[2][8][4];
    #pragma unroll
    for (int t = 0; t < 2; ++t)
        #pragma unroll
        for (int j = 0; j < 8; ++j)
            #pragma unroll
            for (int q = 0; q < 4; ++q) acc[t][j][q] = 0.f;

    const int NCH = DUAL ? 16 : 8;
    float4 Areg[4], Breg[4];

    auto load_chunk = [&](int c) {
        const float* Ap; const float* Wp; int k0;
        if (DUAL && c >= 8) { Ap = A2; Wp = Wt2; k0 = (c - 8) * 32; }
        else                { Ap = A;  Wp = Wt;  k0 = c * 32; }
        const float* as = Ap + (size_t)arow * 256 + k0 + aq;
        #pragma unroll
        for (int i = 0; i < 4; ++i)
            Areg[i] = (arow < M) ? *(const float4*)(as + i * 4)
                                 : make_float4(0.f, 0.f, 0.f, 0.f);
        const float* bs = Wp + (size_t)(bn + ar) * 256 + k0 + aq;
        #pragma unroll
        for (int i = 0; i < 4; ++i)
            Breg[i] = *(const float4*)(bs + i * 4);
    };

    auto store_chunk = [&](int buf) {
        float* a = sA + buf * 4096;
        float* b = sB + buf * 4096;
        #pragma unroll
        for (int i = 0; i < 4; ++i) {
            float v[4] = {Areg[i].x, Areg[i].y, Areg[i].z, Areg[i].w};
            #pragma unroll
            for (int e = 0; e < 4; ++e) {
                int col = aq + i * 4 + e;
                int lane_w = a_lhi | (col & 3);
                int r = (((col >> 2) & 1) << 1) | a_rowbit;
                int kstep = col >> 3;
                a[((a_mtile * 4 + kstep) * 32 + lane_w) * 4 + r] = tf32r(v[e]);
            }
        }
        #pragma unroll
        for (int i = 0; i < 4; ++i) {
            float v[4] = {Breg[i].x, Breg[i].y, Breg[i].z, Breg[i].w};
            #pragma unroll
            for (int e = 0; e < 4; ++e) {
                int k = aq + i * 4 + e;
                int kstep = k >> 3, kk = k & 7;
                int lane_w = (b_nin << 2) | (kk & 3);
                int f = b_half * 2 + (kk >> 2);
                b[((kstep * 8 + b_p) * 32 + lane_w) * 4 + f] = v[e];
            }
        }
    };

    auto compute = [&](int buf) {
        const uint32_t* a = (const uint32_t*)(sA + buf * 4096);
        const uint32_t* b = (const uint32_t*)(sB + buf * 4096);
        #pragma unroll
        for (int ks = 0; ks < 4; ++ks) {
            uint4 av[2], bv[4];
            #pragma unroll
            for (int t = 0; t < 2; ++t)
                av[t] = *(const uint4*)(a + (((warp_m*2 + t)*4 + ks)*32 + lane)*4);
            #pragma unroll
            for (int pp = 0; pp < 4; ++pp)
                bv[pp] = *(const uint4*)(b + ((ks*8 + warp_n*4 + pp)*32 + lane)*4);
            #pragma unroll
            for (int t = 0; t < 2; ++t)
                #pragma unroll
                for (int j = 0; j < 8; ++j) {
                    uint32_t b0 = (j & 1) ? bv[j>>1].z : bv[j>>1].x;
                    uint32_t b1 = (j & 1) ? bv[j>>1].w : bv[j>>1].y;
                    MMA_TF32(acc[t][j], av[t], b0, b1);
                }
        }
    };

    load_chunk(0);
    store_chunk(0);
    __syncthreads();
    for (int c = 0; c < NCH; ++c) {
        if (c + 1 < NCH) load_chunk(c + 1);
        compute(c & 1);
        if (c + 1 < NCH) store_chunk((c + 1) & 1);
        __syncthreads();
    }

    // ---- epilogue ----
    const int row_base = bm + warp_m * 32 + (lane >> 2);
    const int col_base = bn + warp_n * 64 + (lane & 3) * 2;
    #pragma unroll
    for (int t = 0; t < 2; ++t) {
        int r0 = row_base + t * 16;
        int r1 = r0 + 8;
        float s0 = 1.f, s1 = 1.f;
        if (ROWSCALE) {
            s0 = (r0 < M) ? rowscale[r0] : 0.f;
            s1 = (r1 < M) ? rowscale[r1] : 0.f;
        }
        #pragma unroll
        for (int j = 0; j < 8; ++j) {
            int col = col_base + j * 8;
            float bb0 = 0.f, bb1 = 0.f;
            if (bias) { bb0 = __ldg(bias + col); bb1 = __ldg(bias + col + 1); }
            float v00 = acc[t][j][0] + bb0 * s0;
            float v01 = acc[t][j][1] + bb1 * s0;
            float v10 = acc[t][j][2] + bb0 * s1;
            float v11 = acc[t][j][3] + bb1 * s1;
            if (RELU) {
                v00 = fmaxf(v00, 0.f); v01 = fmaxf(v01, 0.f);
                v10 = fmaxf(v10, 0.f); v11 = fmaxf(v11, 0.f);
            }
            if (r0 < M) *(float2*)(C + (size_t)r0 * 256 + col) = make_float2(v00, v01);
            if (r1 < M) *(float2*)(C + (size_t)r1 * 256 + col) = make_float2(v10, v11);
        }
    }
}

// ---------------- node encoder: h1 = relu(cat(relu(x128@geoW+b), x[128:])@W1+b1)
__global__ void __launch_bounds__(256) node_encode_k(
    const float* __restrict__ x,
    const float* __restrict__ geo_w, const float* __restrict__ geo_b,
    const float* __restrict__ w1, const float* __restrict__ b1,
    float* __restrict__ out)
{
    extern __shared__ float sm[];
    float* gws = sm;              // 128*32
    float* gbs = gws + 4096;      // 32
    float* w1s = gbs + 32;        // 64*256
    float* b1s = w1s + 16384;     // 256
    float* xin = b1s + 256;       // 8*64
    for (int i = threadIdx.x; i < 4096;  i += 256) gws[i] = geo_w[i];
    for (int i = threadIdx.x; i < 16384; i += 256) w1s[i] = w1[i];
    if (threadIdx.x < 32)  gbs[threadIdx.x] = geo_b[threadIdx.x];
    b1s[threadIdx.x] = b1[threadIdx.x];
    __syncthreads();

    const int warp = threadIdx.x >> 5, lane = threadIdx.x & 31;
    for (int n0 = blockIdx.x*8; n0 < NN; n0 += gridDim.x*8) {
        int n = n0 + warp;
        if (n < NN) {
            const float* xr = x + (size_t)n*160;
            float s = gbs[lane];
            #pragma unroll
            for (int k = 0; k < 128; ++k) s += __ldg(xr+k) * gws[k*32 + lane];
            xin[warp*64 + lane]      = fmaxf(s, 0.f);
            xin[warp*64 + 32 + lane] = __ldg(xr + 128 + lane);
        }
        __syncthreads();
        #pragma unroll
        for (int p = 0; p < 8; ++p) {
            int n2 = n0 + p;
            if (n2 >= NN) break;
            float acc = b1s[threadIdx.x];
            #pragma unroll
            for (int k = 0; k < 64; ++k) acc += xin[p*64+k] * w1s[k*256 + threadIdx.x];
            out[(size_t)n2*256 + threadIdx.x] = fmaxf(acc, 0.f);
        }
        __syncthreads();
    }
}

// ---------------- edge encoder + scatter: At[dst] += relu(ea@W1+b1); deg[dst]++
__global__ void __launch_bounds__(256) edge_encode_k(
    const float* __restrict__ ea, const int* __restrict__ eidx,
    const float* __restrict__ w1, const float* __restrict__ b1,
    float* __restrict__ At, float* __restrict__ deg)
{
    __shared__ float w1s[16*256];
    __shared__ float b1s[256];
    __shared__ float ts[8][256];
    for (int i = threadIdx.x; i < 4096; i += 256) w1s[i] = w1[i];
    b1s[threadIdx.x] = b1[threadIdx.x];
    __syncthreads();

    const int warp = threadIdx.x >> 5, lane = threadIdx.x & 31;
    for (int e0 = blockIdx.x*8; e0 < NE; e0 += gridDim.x*8) {
        int e = e0 + warp;
        if (e < NE) {
            const float* row = ea + (size_t)e*16;
            float eav[16];
            #pragma unroll
            for (int k = 0; k < 16; ++k) eav[k] = __ldg(row+k);
            #pragma unroll
            for (int i = 0; i < 8; ++i) {
                int col = lane + 32*i;
                float s = b1s[col];
                #pragma unroll
                for (int k = 0; k < 16; ++k) s += eav[k] * w1s[k*256 + col];
                ts[warp][col] = fmaxf(s, 0.f);
            }
            __syncwarp();
            int dst = eidx[NE + e];
            float* dp = At + (size_t)dst*256;
            int c = lane*8;
            redAdd4(dp + c,     *(float4*)&ts[warp][c]);
            redAdd4(dp + c + 4, *(float4*)&ts[warp][c+4]);
            if (lane == 0) atomicAdd(deg + dst, 1.f);
        }
    }
}

// ---------------- SpMM scatter: agg[dst] += h[src] --------------------------
__global__ void __launch_bounds__(256) spmm_k(
    const float* __restrict__ h, const int* __restrict__ eidx,
    float* __restrict__ agg)
{
    int gw = (blockIdx.x*blockDim.x + threadIdx.x) >> 5;
    int lane = threadIdx.x & 31;
    int nw = (gridDim.x*blockDim.x) >> 5;
    for (int e = gw; e < NE; e += nw) {
        int src = eidx[e];
        int dst = eidx[NE + e];
        const float* hp = h + (size_t)src*256;
        float* ap = agg + (size_t)dst*256;
        int c = lane*8;
        float4 v0 = *(const float4*)(hp + c);
        float4 v1 = *(const float4*)(hp + c + 4);
        redAdd4(ap + c,     v0);
        redAdd4(ap + c + 4, v1);
    }
}

// ---------------- residual + layernorm (warp per row) -----------------------
__global__ void __launch_bounds__(256) ln_k(
    float* __restrict__ h, const float* __restrict__ u,
    const float* __restrict__ g, const float* __restrict__ b)
{
    int gw = (blockIdx.x*blockDim.x + threadIdx.x) >> 5;
    int lane = threadIdx.x & 31;
    int nw = (gridDim.x*blockDim.x) >> 5;
    for (int n = gw; n < NN; n += nw) {
        float* hp = h + (size_t)n*256;
        const float* up = u + (size_t)n*256;
        float v[8];
        float4 h0 = *(float4*)(hp + lane*8),       h1 = *(float4*)(hp + lane*8 + 4);
        float4 u0 = *(const float4*)(up + lane*8), u1 = *(const float4*)(up + lane*8 + 4);
        v[0]=h0.x+u0.x; v[1]=h0.y+u0.y; v[2]=h0.z+u0.z; v[3]=h0.w+u0.w;
        v[4]=h1.x+u1.x; v[5]=h1.y+u1.y; v[6]=h1.z+u1.z; v[7]=h1.w+u1.w;
        float s = 0.f;
        #pragma unroll
        for (int i = 0; i < 8; ++i) s += v[i];
        #pragma unroll
        for (int o = 16; o > 0; o >>= 1) s += __shfl_xor_sync(0xffffffffu, s, o);
        float mu = s * (1.f/256.f);
        float qq = 0.f;
        #pragma unroll
        for (int i = 0; i < 8; ++i) { float d = v[i]-mu; qq += d*d; }
        #pragma unroll
        for (int o = 16; o > 0; o >>= 1) qq += __shfl_xor_sync(0xffffffffu, qq, o);
        float rstd = rsqrtf(qq*(1.f/256.f) + 1e-5f);
        #pragma unroll
        for (int i = 0; i < 8; ++i) {
            int c = lane*8 + i;
            v[i] = (v[i]-mu)*rstd*__ldg(g+c) + __ldg(b+c);
        }
        *(float4*)(hp + lane*8)     = make_float4(v[0],v[1],v[2],v[3]);
        *(float4*)(hp + lane*8 + 4) = make_float4(v[4],v[5],v[6],v[7]);
    }
}

// ---------------- typed mean-pool partial sums -------------------------------
__global__ void __launch_bounds__(256) pool_k(
    const float* __restrict__ h, const int* __restrict__ batch,
    const int* __restrict__ ntype, float* __restrict__ ps, float* __restrict__ pc)
{
    __shared__ float acc[24][256];
    __shared__ float cnt[24];
    for (int i = threadIdx.x; i < 24*256; i += 256) (&acc[0][0])[i] = 0.f;
    if (threadIdx.x < 24) cnt[threadIdx.x] = 0.f;
    __syncthreads();
    int per = (NN + gridDim.x - 1) / gridDim.x;
    int start = blockIdx.x * per;
    int end = start + per; if (end > NN) end = NN;
    for (int n = start; n < end; ++n) {
        int idx = __ldg(ntype+n)*8 + __ldg(batch+n);
        acc[idx][threadIdx.x] += h[(size_t)n*256 + threadIdx.x];
        if (threadIdx.x == 0) cnt[idx] += 1.f;
    }
    __syncthreads();
    for (int i = threadIdx.x; i < 24*256; i += 256) atomicAdd(&ps[i], (&acc[0][0])[i]);
    if (threadIdx.x < 24) atomicAdd(&pc[threadIdx.x], cnt[threadIdx.x]);
}

// ---------------- final write: z | h | batch ---------------------------------
__global__ void __launch_bounds__(256) writeout_k(
    const float* __restrict__ ps, const float* __restrict__ pc,
    const float* __restrict__ h, const int* __restrict__ batch,
    float* __restrict__ out, int out_size)
{
    const int total = 24*256 + NN*HD + NN;
    for (int i = blockIdx.x*blockDim.x + threadIdx.x; i < total;
         i += gridDim.x*blockDim.x) {
        float v; int o;
        if (i < 6144) {
            int c = i & 255, kb = i >> 8, k = kb >> 3, bb = kb & 7;
            float cc = pc[kb]; if (cc < 1.f) cc = 1.f;
            v = ps[i] / cc;
            o = bb*768 + k*256 + c;
        } else if (i < 6144 + NN*HD) {
            v = h[i - 6144]; o = i;
        } else {
            v = (float)batch[i - 6144 - NN*HD]; o = i;
        }
        if (o < out_size) out[o] = v;
    }
}

// ---------------- launcher ----------------------------------------------------
extern "C" void kernel_launch(void* const* d_in, const int* in_sizes, int n_in,
                              void* d_out, int out_size)
{
    const float* x       = (const float*)d_in[0];
    const float* ea      = (const float*)d_in[1];
    const float* geo_w   = (const float*)d_in[2];
    const float* geo_b   = (const float*)d_in[3];
    const float* nin_w1  = (const float*)d_in[4];
    const float* nin_b1  = (const float*)d_in[5];
    const float* nin_w2  = (const float*)d_in[6];
    const float* nin_b2  = (const float*)d_in[7];
    const float* ee_w1   = (const float*)d_in[8];
    const float* ee_b1   = (const float*)d_in[9];
    const float* ee_w2   = (const float*)d_in[10];
    const float* ee_b2   = (const float*)d_in[11];
    const float* msgx    = (const float*)d_in[12];
    const float* msge    = (const float*)d_in[13];
    const float* upd_w1  = (const float*)d_in[14];
    const float* upd_b1  = (const float*)d_in[15];
    const float* upd_w2  = (const float*)d_in[16];
    const float* upd_b2  = (const float*)d_in[17];
    const float* ln_g    = (const float*)d_in[18];
    const float* ln_b    = (const float*)d_in[19];
    const int*   eidx    = (const int*)d_in[20];
    const int*   batch   = (const int*)d_in[21];
    const int*   ntype   = (const int*)d_in[22];
    float* out = (float*)d_out;

    float *h_, *d1_, *d2_, *d3_, *ae_, *deg_, *ps_, *pc_, *wt_;
    cudaGetSymbolAddress((void**)&h_,  g_h);
    cudaGetSymbolAddress((void**)&d1_, g_d1);
    cudaGetSymbolAddress((void**)&d2_, g_d2);
    cudaGetSymbolAddress((void**)&d3_, g_d3);
    cudaGetSymbolAddress((void**)&ae_, g_ae);
    cudaGetSymbolAddress((void**)&deg_, g_deg);
    cudaGetSymbolAddress((void**)&ps_, g_ps);
    cudaGetSymbolAddress((void**)&pc_, g_pc);
    cudaGetSymbolAddress((void**)&wt_, g_wt);

    const int NE_SMEM = (4096 + 32 + 16384 + 256 + 512) * 4;
    cudaFuncSetAttribute(node_encode_k,
        cudaFuncAttributeMaxDynamicSharedMemorySize, NE_SMEM);
    cudaFuncSetAttribute(gemm_mma<false,false,false>,
        cudaFuncAttributeMaxDynamicSharedMemorySize, GEMM_SMEM);
    cudaFuncSetAttribute(gemm_mma<false,false,true>,
        cudaFuncAttributeMaxDynamicSharedMemorySize, GEMM_SMEM);
    cudaFuncSetAttribute(gemm_mma<true,false,false>,
        cudaFuncAttributeMaxDynamicSharedMemorySize, GEMM_SMEM);
    cudaFuncSetAttribute(gemm_mma<false,true,false>,
        cudaFuncAttributeMaxDynamicSharedMemorySize, GEMM_SMEM);

    // weight order: 0 nin_w2, 1 ee_w2, 2..5 msgx, 6..9 msge, 10..13 upd_w1, 14..17 upd_w2
    WPtrs wp;
    wp.p[0] = nin_w2; wp.p[1] = ee_w2;
    for (int l = 0; l < 4; ++l) {
        wp.p[2 + l]  = msgx   + (size_t)l*65536;
        wp.p[6 + l]  = msge   + (size_t)l*65536;
        wp.p[10 + l] = upd_w1 + (size_t)l*65536;
        wp.p[14 + l] = upd_w2 + (size_t)l*65536;
    }
    wtrans_k<<<dim3(8, 8, 18), 256>>>(wp, wt_);

    dim3 gg(391, 2);   // ceil(50000/128) x (256/128)

    // node input encoder: d1 = h1
    node_encode_k<<<625, 256, NE_SMEM>>>(x, geo_w, geo_b, nin_w1, nin_b1, d1_);
    // h = h1 @ nin_w2 + nin_b2
    gemm_mma<false,false,false><<<gg, 256, GEMM_SMEM>>>(
        d1_, wt_ + 0*65536, nullptr, nullptr, nin_b2, nullptr, h_, NN);
    // edge encoder scatter: d2 = segsum(relu(ea@W1+b1)), deg = indegree
    cudaMemsetAsync(d2_, 0, (size_t)NN*HD*sizeof(float));
    cudaMemsetAsync(deg_, 0, (size_t)NN*sizeof(float));
    edge_encode_k<<<592, 256>>>(ea, eidx, ee_w1, ee_b1, d2_, deg_);
    // Ae = d2 @ ee_w2 + deg * ee_b2
    gemm_mma<false,false,true><<<gg, 256, GEMM_SMEM>>>(
        d2_, wt_ + 1*65536, nullptr, nullptr, ee_b2, deg_, ae_, NN);

    for (int l = 0; l < NL; ++l) {
        // agg = A @ h
        cudaMemsetAsync(d1_, 0, (size_t)NN*HD*sizeof(float));
        spmm_k<<<1184, 256>>>(h_, eidx, d1_);
        // d2 = agg@msgx + Ae@msge
        gemm_mma<true,false,false><<<gg, 256, GEMM_SMEM>>>(
            d1_, wt_ + (size_t)(2+l)*65536, ae_, wt_ + (size_t)(6+l)*65536,
            nullptr, nullptr, d2_, NN);
        // d3 = relu(d2@upd_w1 + b1)
        gemm_mma<false,true,false><<<gg, 256, GEMM_SMEM>>>(
            d2_, wt_ + (size_t)(10+l)*65536, nullptr, nullptr,
            upd_b1 + l*256, nullptr, d3_, NN);
        // d1 = d3@upd_w2 + b2
        gemm_mma<false,false,false><<<gg, 256, GEMM_SMEM>>>(
            d3_, wt_ + (size_t)(14+l)*65536, nullptr, nullptr,
            upd_b2 + l*256, nullptr, d1_, NN);
        // h = LN(h + d1)
        ln_k<<<784, 256>>>(h_, d1_, ln_g + l*256, ln_b + l*256);
    }

    cudaMemsetAsync(ps_, 0, 24*HD*sizeof(float));
    cudaMemsetAsync(pc_, 0, 24*sizeof(float));
    pool_k<<<256, 256>>>(h_, batch, ntype, ps_, pc_);
    writeout_k<<<8192, 256>>>(ps_, pc_, h_, batch, out, out_size);
}

// round 4
// speedup vs baseline: 1.5506x; 1.1925x over previous
#include <cuda_runtime.h>
#include <cstdint>

#define NN 50000
#define NE 300000
#define HD 256
#define NB 8
#define NL 4

// ---------------- scratch (static device globals; no allocs allowed) -------
__device__ float g_h [NN*HD];
__device__ float g_d1[NN*HD];
__device__ float g_d2[NN*HD];
__device__ float g_d3[NN*HD];
__device__ float g_ae[NN*HD];
__device__ float g_deg[NN];
__device__ float g_ps[24*HD];
__device__ float g_pc[24];
__device__ float g_wt[18*65536];   // transposed+tf32-rounded weights [N=256][K=256]
__device__ float g_wt1[256*64];    // nin_w1 transposed [256][64]

// ---------------- helpers ------------------------------------------------
__device__ __forceinline__ float tf32r(float x) {
    float r;
    asm("cvt.rna.tf32.f32 %0, %1;" : "=f"(r) : "f"(x));
    return r;
}
__device__ __forceinline__ void redAdd4(float* p, float4 v) {
    asm volatile("red.global.add.v4.f32 [%0], {%1,%2,%3,%4};"
                 :: "l"(p), "f"(v.x), "f"(v.y), "f"(v.z), "f"(v.w) : "memory");
}
#define MMA_TF32(c, a, b0, b1)                                               \
    asm volatile("mma.sync.aligned.m16n8k8.row.col.f32.tf32.tf32.f32 "      \
        "{%0,%1,%2,%3}, {%4,%5,%6,%7}, {%8,%9}, {%0,%1,%2,%3};"             \
        : "+f"((c)[0]), "+f"((c)[1]), "+f"((c)[2]), "+f"((c)[3])            \
        : "r"((a)[0]), "r"((a)[1]), "r"((a)[2]), "r"((a)[3]),               \
          "r"(b0), "r"(b1))

// ---------------- weight transpose + tf32 round: Wt[n,k] = rna(W[k,n]) -----
struct WPtrs { const float* p[18]; };

__global__ void __launch_bounds__(256) wtrans_k(WPtrs wp, float* __restrict__ out) {
    __shared__ float t[32][33];
    const float* W = wp.p[blockIdx.z];
    float* O = out + (size_t)blockIdx.z * 65536;
    int n0 = blockIdx.x * 32, k0 = blockIdx.y * 32;
    int tx = threadIdx.x & 31, ty = threadIdx.x >> 5;  // 32x8
    #pragma unroll
    for (int i = 0; i < 32; i += 8)
        t[ty + i][tx] = W[(size_t)(k0 + ty + i) * 256 + n0 + tx];
    __syncthreads();
    #pragma unroll
    for (int i = 0; i < 32; i += 8)
        O[(size_t)(n0 + ty + i) * 256 + k0 + tx] = tf32r(t[tx][ty + i]);
}

// nin_w1 [64,256] -> [256,64]
__global__ void __launch_bounds__(256) wtrans64_k(
    const float* __restrict__ W, float* __restrict__ O) {
    __shared__ float t[32][33];
    int n0 = blockIdx.x * 32, k0 = blockIdx.y * 32;
    int tx = threadIdx.x & 31, ty = threadIdx.x >> 5;
    #pragma unroll
    for (int i = 0; i < 32; i += 8)
        t[ty + i][tx] = W[(size_t)(k0 + ty + i) * 256 + n0 + tx];
    __syncthreads();
    #pragma unroll
    for (int i = 0; i < 32; i += 8)
        O[(size_t)(n0 + ty + i) * 64 + k0 + tx] = tf32r(t[tx][ty + i]);
}

// ---------------- tensor-core GEMM via mma.sync tf32 ------------------------
// C[M,256] = A@W (+A2@W2) (+bias[*rowscale]) (relu)
// CTA 128x128, 4 warps (2x2), warp tile 64x64. BK=32 double-buffered.
// Fragment-major smem, reg-major inner order: STS.128 write / scalar LDS read.
#define GEMM_SMEM 65536

template<int KROW, bool DUAL, bool RELU, bool ROWSCALE>
__global__ void __launch_bounds__(128) gemm_mma(
    const float* __restrict__ A,  const float* __restrict__ Wt,
    const float* __restrict__ A2, const float* __restrict__ Wt2,
    const float* __restrict__ bias, const float* __restrict__ rowscale,
    float* __restrict__ C, int M)
{
    extern __shared__ float smf[];
    float* sA = smf;            // 2 x 4096 floats
    float* sB = smf + 8192;     // 2 x 4096 floats

    const int tid = threadIdx.x;
    const int wid = tid >> 5, lane = tid & 31;
    const int warp_m = wid & 1, warp_n = wid >> 1;
    const int bm = blockIdx.x * 128;
    const int bn = blockIdx.y * 128;

    const int arow = bm + tid;           // staged A row
    const int s_mt = tid >> 4;           // mtile / p
    const int s_rb = (tid >> 3) & 1;     // rowbit / halfbit
    const int s_lh = (tid & 7) << 2;     // lane base *4

    float acc[4][8][4];
    #pragma unroll
    for (int t = 0; t < 4; ++t)
        #pragma unroll
        for (int j = 0; j < 8; ++j)
            #pragma unroll
            for (int q = 0; q < 4; ++q) acc[t][j][q] = 0.f;

    const int KC = KROW / 32;
    const int NCHUNK = (DUAL ? 2 : 1) * KC;
    float4 ra[8], rb[8];

    auto ldgA = [&](int c) {
        const float* Ap = (DUAL && c >= KC) ? A2 : A;
        int k0 = (DUAL && c >= KC) ? (c - KC) * 32 : c * 32;
        const float* p = Ap + (size_t)arow * KROW + k0;
        #pragma unroll
        for (int i = 0; i < 8; ++i)
            ra[i] = (arow < M) ? *(const float4*)(p + i * 4)
                               : make_float4(0.f, 0.f, 0.f, 0.f);
    };
    auto ldgB = [&](int c) {
        const float* Wp = (DUAL && c >= KC) ? Wt2 : Wt;
        int k0 = (DUAL && c >= KC) ? (c - KC) * 32 : c * 32;
        const float* p = Wp + (size_t)(bn + tid) * KROW + k0;
        #pragma unroll
        for (int i = 0; i < 8; ++i) rb[i] = *(const float4*)(p + i * 4);
    };
    auto stsA = [&](int buf) {
        float* a = sA + buf * 4096;
        #pragma unroll
        for (int g = 0; g < 8; ++g) {
            int ks = g >> 1;
            int r = ((g & 1) << 1) | s_rb;
            float4 v = ra[g];
            v.x = tf32r(v.x); v.y = tf32r(v.y);
            v.z = tf32r(v.z); v.w = tf32r(v.w);
            *(float4*)&a[(s_mt * 4 + ks) * 128 + r * 32 + s_lh] = v;
        }
    };
    auto stsB = [&](int buf) {
        float* b = sB + buf * 4096;
        #pragma unroll
        for (int g = 0; g < 8; ++g) {
            int ks = g >> 1;
            int f = (s_rb << 1) | (g & 1);
            *(float4*)&b[(ks * 8 + s_mt) * 128 + f * 32 + s_lh] = rb[g];
        }
    };
    auto compute_ks = [&](int buf, int ks) {
        const float* a = sA + buf * 4096;
        const float* b = sB + buf * 4096;
        uint32_t av[4][4], bv[4][4];
        #pragma unroll
        for (int t = 0; t < 4; ++t) {
            int base = ((warp_m * 4 + t) * 4 + ks) * 128 + lane;
            av[t][0] = __float_as_uint(a[base]);
            av[t][1] = __float_as_uint(a[base + 32]);
            av[t][2] = __float_as_uint(a[base + 64]);
            av[t][3] = __float_as_uint(a[base + 96]);
        }
        #pragma unroll
        for (int pp = 0; pp < 4; ++pp) {
            int base = (ks * 8 + warp_n * 4 + pp) * 128 + lane;
            bv[pp][0] = __float_as_uint(b[base]);
            bv[pp][1] = __float_as_uint(b[base + 32]);
            bv[pp][2] = __float_as_uint(b[base + 64]);
            bv[pp][3] = __float_as_uint(b[base + 96]);
        }
        #pragma unroll
        for (int t = 0; t < 4; ++t)
            #pragma unroll
            for (int j = 0; j < 8; ++j) {
                int pp = j >> 1, half = j & 1;
                MMA_TF32(acc[t][j], av[t], bv[pp][half * 2], bv[pp][half * 2 + 1]);
            }
    };

    ldgA(0); ldgB(0);
    stsA(0); stsB(0);
    __syncthreads();
    for (int c = 0; c < NCHUNK; ++c) {
        const int buf = c & 1;
        if (c + 1 < NCHUNK) ldgA(c + 1);
        compute_ks(buf, 0);
        compute_ks(buf, 1);
        if (c + 1 < NCHUNK) { stsA(buf ^ 1); ldgB(c + 1); }
        compute_ks(buf, 2);
        compute_ks(buf, 3);
        if (c + 1 < NCHUNK) stsB(buf ^ 1);
        __syncthreads();
    }

    // ---- epilogue ----
    const int row_base = bm + warp_m * 64 + (lane >> 2);
    const int col_base = bn + warp_n * 64 + (lane & 3) * 2;
    #pragma unroll
    for (int t = 0; t < 4; ++t) {
        int r0 = row_base + t * 16;
        int r1 = r0 + 8;
        float s0 = 1.f, s1 = 1.f;
        if (ROWSCALE) {
            s0 = (r0 < M) ? rowscale[r0] : 0.f;
            s1 = (r1 < M) ? rowscale[r1] : 0.f;
        }
        #pragma unroll
        for (int j = 0; j < 8; ++j) {
            int col = col_base + j * 8;
            float bb0 = 0.f, bb1 = 0.f;
            if (bias) { bb0 = __ldg(bias + col); bb1 = __ldg(bias + col + 1); }
            float v00 = acc[t][j][0] + bb0 * s0;
            float v01 = acc[t][j][1] + bb1 * s0;
            float v10 = acc[t][j][2] + bb0 * s1;
            float v11 = acc[t][j][3] + bb1 * s1;
            if (RELU) {
                v00 = fmaxf(v00, 0.f); v01 = fmaxf(v01, 0.f);
                v10 = fmaxf(v10, 0.f); v11 = fmaxf(v11, 0.f);
            }
            if (r0 < M) *(float2*)(C + (size_t)r0 * 256 + col) = make_float2(v00, v01);
            if (r1 < M) *(float2*)(C + (size_t)r1 * 256 + col) = make_float2(v10, v11);
        }
    }
}

// ---------------- geo stage: xin[n] = [relu(x[:,:128]@geoW+b) | x[:,128:160]] --
__global__ void __launch_bounds__(256) geo_k(
    const float* __restrict__ x,
    const float* __restrict__ geo_w, const float* __restrict__ geo_b,
    float* __restrict__ out)   // [NN, 64]
{
    __shared__ float gws[4096];
    __shared__ float gbs[32];
    for (int i = threadIdx.x; i < 4096; i += 256) gws[i] = geo_w[i];
    if (threadIdx.x < 32) gbs[threadIdx.x] = geo_b[threadIdx.x];
    __syncthreads();
    const int warp = threadIdx.x >> 5, lane = threadIdx.x & 31;
    for (int n0 = blockIdx.x * 8; n0 < NN; n0 += gridDim.x * 8) {
        int n = n0 + warp;
        if (n < NN) {
            const float* xr = x + (size_t)n * 160;
            float s = gbs[lane];
            #pragma unroll
            for (int k = 0; k < 128; ++k) s += __ldg(xr + k) * gws[k * 32 + lane];
            out[(size_t)n * 64 + lane]      = fmaxf(s, 0.f);
            out[(size_t)n * 64 + 32 + lane] = __ldg(xr + 128 + lane);
        }
    }
}

// ---------------- edge encoder + scatter (weights in registers) -------------
// At[dst] += relu(ea@W1 + b1); deg[dst] += 1
__global__ void __launch_bounds__(256) edge_encode_k(
    const float* __restrict__ ea, const int* __restrict__ eidx,
    const float* __restrict__ w1, const float* __restrict__ b1,
    float* __restrict__ At, float* __restrict__ deg)
{
    const int tid = threadIdx.x;
    const int c0 = (tid & 63) * 4;
    const int slot = tid >> 6;
    float4 wreg[16];
    #pragma unroll
    for (int k = 0; k < 16; ++k)
        wreg[k] = *(const float4*)(w1 + k * 256 + c0);
    const float4 b1v = *(const float4*)(b1 + c0);

    __shared__ float eav[4][16];
    __shared__ int dsts[4];

    for (int base = blockIdx.x * 4; base < NE; base += gridDim.x * 4) {
        if (tid < 64) ((float*)eav)[tid] = ea[(size_t)base * 16 + tid];
        if (tid < 4) dsts[tid] = eidx[NE + base + tid];
        __syncthreads();
        float4 acc = b1v;
        #pragma unroll
        for (int k = 0; k < 16; ++k) {
            float e = eav[slot][k];
            acc.x += wreg[k].x * e;
            acc.y += wreg[k].y * e;
            acc.z += wreg[k].z * e;
            acc.w += wreg[k].w * e;
        }
        acc.x = fmaxf(acc.x, 0.f); acc.y = fmaxf(acc.y, 0.f);
        acc.z = fmaxf(acc.z, 0.f); acc.w = fmaxf(acc.w, 0.f);
        int dst = dsts[slot];
        redAdd4(At + (size_t)dst * 256 + c0, acc);
        if ((tid & 63) == 0) atomicAdd(deg + dst, 1.f);
        __syncthreads();
    }
}

// ---------------- SpMM scatter: agg[dst] += h[src] --------------------------
__global__ void __launch_bounds__(256) spmm_k(
    const float* __restrict__ h, const int* __restrict__ eidx,
    float* __restrict__ agg)
{
    int gw = (blockIdx.x*blockDim.x + threadIdx.x) >> 5;
    int lane = threadIdx.x & 31;
    int nw = (gridDim.x*blockDim.x) >> 5;
    for (int e = gw; e < NE; e += nw) {
        int src = eidx[e];
        int dst = eidx[NE + e];
        const float* hp = h + (size_t)src*256;
        float* ap = agg + (size_t)dst*256;
        int c = lane*8;
        float4 v0 = *(const float4*)(hp + c);
        float4 v1 = *(const float4*)(hp + c + 4);
        redAdd4(ap + c,     v0);
        redAdd4(ap + c + 4, v1);
    }
}

// ---------------- residual + layernorm (warp per row) -----------------------
__global__ void __launch_bounds__(256) ln_k(
    float* __restrict__ h, const float* __restrict__ u,
    const float* __restrict__ g, const float* __restrict__ b)
{
    int gw = (blockIdx.x*blockDim.x + threadIdx.x) >> 5;
    int lane = threadIdx.x & 31;
    int nw = (gridDim.x*blockDim.x) >> 5;
    for (int n = gw; n < NN; n += nw) {
        float* hp = h + (size_t)n*256;
        const float* up = u + (size_t)n*256;
        float v[8];
        float4 h0 = *(float4*)(hp + lane*8),       h1 = *(float4*)(hp + lane*8 + 4);
        float4 u0 = *(const float4*)(up + lane*8), u1 = *(const float4*)(up + lane*8 + 4);
        v[0]=h0.x+u0.x; v[1]=h0.y+u0.y; v[2]=h0.z+u0.z; v[3]=h0.w+u0.w;
        v[4]=h1.x+u1.x; v[5]=h1.y+u1.y; v[6]=h1.z+u1.z; v[7]=h1.w+u1.w;
        float s = 0.f;
        #pragma unroll
        for (int i = 0; i < 8; ++i) s += v[i];
        #pragma unroll
        for (int o = 16; o > 0; o >>= 1) s += __shfl_xor_sync(0xffffffffu, s, o);
        float mu = s * (1.f/256.f);
        float qq = 0.f;
        #pragma unroll
        for (int i = 0; i < 8; ++i) { float d = v[i]-mu; qq += d*d; }
        #pragma unroll
        for (int o = 16; o > 0; o >>= 1) qq += __shfl_xor_sync(0xffffffffu, qq, o);
        float rstd = rsqrtf(qq*(1.f/256.f) + 1e-5f);
        #pragma unroll
        for (int i = 0; i < 8; ++i) {
            int c = lane*8 + i;
            v[i] = (v[i]-mu)*rstd*__ldg(g+c) + __ldg(b+c);
        }
        *(float4*)(hp + lane*8)     = make_float4(v[0],v[1],v[2],v[3]);
        *(float4*)(hp + lane*8 + 4) = make_float4(v[4],v[5],v[6],v[7]);
    }
}

// ---------------- typed mean-pool partial sums -------------------------------
__global__ void __launch_bounds__(256) pool_k(
    const float* __restrict__ h, const int* __restrict__ batch,
    const int* __restrict__ ntype, float* __restrict__ ps, float* __restrict__ pc)
{
    __shared__ float acc[24][256];
    __shared__ float cnt[24];
    for (int i = threadIdx.x; i < 24*256; i += 256) (&acc[0][0])[i] = 0.f;
    if (threadIdx.x < 24) cnt[threadIdx.x] = 0.f;
    __syncthreads();
    int per = (NN + gridDim.x - 1) / gridDim.x;
    int start = blockIdx.x * per;
    int end = start + per; if (end > NN) end = NN;
    for (int n = start; n < end; ++n) {
        int idx = __ldg(ntype+n)*8 + __ldg(batch+n);
        acc[idx][threadIdx.x] += h[(size_t)n*256 + threadIdx.x];
        if (threadIdx.x == 0) cnt[idx] += 1.f;
    }
    __syncthreads();
    for (int i = threadIdx.x; i < 24*256; i += 256) atomicAdd(&ps[i], (&acc[0][0])[i]);
    if (threadIdx.x < 24) atomicAdd(&pc[threadIdx.x], cnt[threadIdx.x]);
}

// ---------------- final write: z | h | batch ---------------------------------
__global__ void __launch_bounds__(256) writeout_k(
    const float* __restrict__ ps, const float* __restrict__ pc,
    const float* __restrict__ h, const int* __restrict__ batch,
    float* __restrict__ out, int out_size)
{
    const int total = 24*256 + NN*HD + NN;
    for (int i = blockIdx.x*blockDim.x + threadIdx.x; i < total;
         i += gridDim.x*blockDim.x) {
        float v; int o;
        if (i < 6144) {
            int c = i & 255, kb = i >> 8, k = kb >> 3, bb = kb & 7;
            float cc = pc[kb]; if (cc < 1.f) cc = 1.f;
            v = ps[i] / cc;
            o = bb*768 + k*256 + c;
        } else if (i < 6144 + NN*HD) {
            v = h[i - 6144]; o = i;
        } else {
            v = (float)batch[i - 6144 - NN*HD]; o = i;
        }
        if (o < out_size) out[o] = v;
    }
}

// ---------------- launcher ----------------------------------------------------
extern "C" void kernel_launch(void* const* d_in, const int* in_sizes, int n_in,
                              void* d_out, int out_size)
{
    const float* x       = (const float*)d_in[0];
    const float* ea      = (const float*)d_in[1];
    const float* geo_w   = (const float*)d_in[2];
    const float* geo_b   = (const float*)d_in[3];
    const float* nin_w1  = (const float*)d_in[4];
    const float* nin_b1  = (const float*)d_in[5];
    const float* nin_w2  = (const float*)d_in[6];
    const float* nin_b2  = (const float*)d_in[7];
    const float* ee_w1   = (const float*)d_in[8];
    const float* ee_b1   = (const float*)d_in[9];
    const float* ee_w2   = (const float*)d_in[10];
    const float* ee_b2   = (const float*)d_in[11];
    const float* msgx    = (const float*)d_in[12];
    const float* msge    = (const float*)d_in[13];
    const float* upd_w1  = (const float*)d_in[14];
    const float* upd_b1  = (const float*)d_in[15];
    const float* upd_w2  = (const float*)d_in[16];
    const float* upd_b2  = (const float*)d_in[17];
    const float* ln_g    = (const float*)d_in[18];
    const float* ln_b    = (const float*)d_in[19];
    const int*   eidx    = (const int*)d_in[20];
    const int*   batch   = (const int*)d_in[21];
    const int*   ntype   = (const int*)d_in[22];
    float* out = (float*)d_out;

    float *h_, *d1_, *d2_, *d3_, *ae_, *deg_, *ps_, *pc_, *wt_, *wt1_;
    cudaGetSymbolAddress((void**)&h_,  g_h);
    cudaGetSymbolAddress((void**)&d1_, g_d1);
    cudaGetSymbolAddress((void**)&d2_, g_d2);
    cudaGetSymbolAddress((void**)&d3_, g_d3);
    cudaGetSymbolAddress((void**)&ae_, g_ae);
    cudaGetSymbolAddress((void**)&deg_, g_deg);
    cudaGetSymbolAddress((void**)&ps_, g_ps);
    cudaGetSymbolAddress((void**)&pc_, g_pc);
    cudaGetSymbolAddress((void**)&wt_, g_wt);
    cudaGetSymbolAddress((void**)&wt1_, g_wt1);

    cudaFuncSetAttribute(gemm_mma<256,false,false,false>,
        cudaFuncAttributeMaxDynamicSharedMemorySize, GEMM_SMEM);
    cudaFuncSetAttribute(gemm_mma<256,false,false,true>,
        cudaFuncAttributeMaxDynamicSharedMemorySize, GEMM_SMEM);
    cudaFuncSetAttribute(gemm_mma<256,true,false,false>,
        cudaFuncAttributeMaxDynamicSharedMemorySize, GEMM_SMEM);
    cudaFuncSetAttribute(gemm_mma<256,false,true,false>,
        cudaFuncAttributeMaxDynamicSharedMemorySize, GEMM_SMEM);
    cudaFuncSetAttribute(gemm_mma<64,false,true,false>,
        cudaFuncAttributeMaxDynamicSharedMemorySize, GEMM_SMEM);

    // weight order: 0 nin_w2, 1 ee_w2, 2..5 msgx, 6..9 msge, 10..13 upd_w1, 14..17 upd_w2
    WPtrs wp;
    wp.p[0] = nin_w2; wp.p[1] = ee_w2;
    for (int l = 0; l < 4; ++l) {
        wp.p[2 + l]  = msgx   + (size_t)l*65536;
        wp.p[6 + l]  = msge   + (size_t)l*65536;
        wp.p[10 + l] = upd_w1 + (size_t)l*65536;
        wp.p[14 + l] = upd_w2 + (size_t)l*65536;
    }
    wtrans_k<<<dim3(8, 8, 18), 256>>>(wp, wt_);
    wtrans64_k<<<dim3(8, 2), 256>>>(nin_w1, wt1_);

    dim3 gg(391, 2);   // ceil(50000/128) x (256/128)

    // node encoder: xin (d3 as [NN,64]) -> d1 = relu(xin@W1+b1) -> h = d1@W2+b2
    geo_k<<<625, 256>>>(x, geo_w, geo_b, d3_);
    gemm_mma<64,false,true,false><<<gg, 128, GEMM_SMEM>>>(
        d3_, wt1_, nullptr, nullptr, nin_b1, nullptr, d1_, NN);
    gemm_mma<256,false,false,false><<<gg, 128, GEMM_SMEM>>>(
        d1_, wt_ + 0*65536, nullptr, nullptr, nin_b2, nullptr, h_, NN);

    // edge encoder scatter: d2 = segsum(relu(ea@W1+b1)), deg = indegree
    cudaMemsetAsync(d2_, 0, (size_t)NN*HD*sizeof(float));
    cudaMemsetAsync(deg_, 0, (size_t)NN*sizeof(float));
    edge_encode_k<<<1184, 256>>>(ea, eidx, ee_w1, ee_b1, d2_, deg_);
    // Ae = d2 @ ee_w2 + deg * ee_b2
    gemm_mma<256,false,false,true><<<gg, 128, GEMM_SMEM>>>(
        d2_, wt_ + 1*65536, nullptr, nullptr, ee_b2, deg_, ae_, NN);

    for (int l = 0; l < NL; ++l) {
        // agg = A @ h
        cudaMemsetAsync(d1_, 0, (size_t)NN*HD*sizeof(float));
        spmm_k<<<1184, 256>>>(h_, eidx, d1_);
        // d2 = agg@msgx + Ae@msge
        gemm_mma<256,true,false,false><<<gg, 128, GEMM_SMEM>>>(
            d1_, wt_ + (size_t)(2+l)*65536, ae_, wt_ + (size_t)(6+l)*65536,
            nullptr, nullptr, d2_, NN);
        // d3 = relu(d2@upd_w1 + b1)
        gemm_mma<256,false,true,false><<<gg, 128, GEMM_SMEM>>>(
            d2_, wt_ + (size_t)(10+l)*65536, nullptr, nullptr,
            upd_b1 + l*256, nullptr, d3_, NN);
        // d1 = d3@upd_w2 + b2
        gemm_mma<256,false,false,false><<<gg, 128, GEMM_SMEM>>>(
            d3_, wt_ + (size_t)(14+l)*65536, nullptr, nullptr,
            upd_b2 + l*256, nullptr, d1_, NN);
        // h = LN(h + d1)
        ln_k<<<784, 256>>>(h_, d1_, ln_g + l*256, ln_b + l*256);
    }

    cudaMemsetAsync(ps_, 0, 24*HD*sizeof(float));
    cudaMemsetAsync(pc_, 0, 24*sizeof(float));
    pool_k<<<512, 256>>>(h_, batch, ntype, ps_, pc_);
    writeout_k<<<8192, 256>>>(ps_, pc_, h_, batch, out, out_size);
}

// round 5
// speedup vs baseline: 1.7970x; 1.1589x over previous
#include <cuda_runtime.h>
#include <cstdint>

#define NN 50000
#define NE 300000
#define HD 256
#define NB 8
#define NL 4

// ---------------- scratch (static device globals; no allocs allowed) -------
__device__ float g_h [NN*HD];
__device__ float g_d1[NN*HD];
__device__ float g_d2[NN*HD];
__device__ float g_d3[NN*HD];
__device__ float g_ae[NN*HD];
__device__ float g_deg[NN];
__device__ float g_ps[24*HD];
__device__ float g_pc[24];
__device__ float g_wt[18*65536];   // fragment-permuted tf32 weights, 256-K mats
__device__ float g_wt1[16384];     // fragment-permuted nin_w1 (K=64)

// ---------------- helpers ------------------------------------------------
__device__ __forceinline__ float tf32r(float x) {
    float r;
    asm("cvt.rna.tf32.f32 %0, %1;" : "=f"(r) : "f"(x));
    return r;
}
__device__ __forceinline__ void redAdd4(float* p, float4 v) {
    asm volatile("red.global.add.v4.f32 [%0], {%1,%2,%3,%4};"
                 :: "l"(p), "f"(v.x), "f"(v.y), "f"(v.z), "f"(v.w) : "memory");
}
__device__ __forceinline__ uint32_t smem_u32(const void* p) {
    uint32_t a;
    asm("{ .reg .u64 t; cvta.to.shared.u64 t, %1; cvt.u32.u64 %0, t; }"
        : "=r"(a) : "l"(p));
    return a;
}
__device__ __forceinline__ void cp_async16(uint32_t sdst, const void* gsrc) {
    asm volatile("cp.async.ca.shared.global [%0], [%1], 16;"
                 :: "r"(sdst), "l"(gsrc) : "memory");
}
#define CP_COMMIT() asm volatile("cp.async.commit_group;" ::: "memory")
#define CP_WAIT0()  asm volatile("cp.async.wait_group 0;" ::: "memory")

#define MMA_TF32(c, a, b0, b1)                                               \
    asm volatile("mma.sync.aligned.m16n8k8.row.col.f32.tf32.tf32.f32 "      \
        "{%0,%1,%2,%3}, {%4,%5,%6,%7}, {%8,%9}, {%0,%1,%2,%3};"             \
        : "+f"((c)[0]), "+f"((c)[1]), "+f"((c)[2]), "+f"((c)[3])            \
        : "r"((a)[0]), "r"((a)[1]), "r"((a)[2]), "r"((a)[3]),               \
          "r"(b0), "r"(b1))

// ---------------- weight -> fragment-major blocks ---------------------------
// Block layout per (kc, nb): 4096 floats; element (n_local, kk):
// idx = ((kk>>3)*8 + (n_local>>4))*128
//     + ((((n_local>>3)&1)<<1) | ((kk>>2)&1))*32 + (n_local&7)*4 + (kk&3)
struct WPtrs { const float* p[18]; };

__global__ void __launch_bounds__(256) wfrag_k(WPtrs wp, float* __restrict__ out) {
    const float* W = wp.p[blockIdx.y];
    float* O = out + (size_t)blockIdx.y * 65536 + blockIdx.x * 4096;
    const int kc = blockIdx.x >> 1, nb = blockIdx.x & 1;
    const int nl = threadIdx.x >> 1;
    const int khalf = (threadIdx.x & 1) * 16;
    const int n = nb * 128 + nl;
    #pragma unroll
    for (int g = 0; g < 4; ++g) {
        int kk = khalf + g * 4;
        int k = kc * 32 + kk;
        float4 v;
        v.x = tf32r(W[(size_t)(k+0)*256 + n]);
        v.y = tf32r(W[(size_t)(k+1)*256 + n]);
        v.z = tf32r(W[(size_t)(k+2)*256 + n]);
        v.w = tf32r(W[(size_t)(k+3)*256 + n]);
        int idx = ((kk>>3)*8 + (nl>>4))*128
                + ((((nl>>3)&1)<<1) | ((kk>>2)&1))*32 + (nl&7)*4;
        *(float4*)&O[idx] = v;
    }
}

__global__ void __launch_bounds__(256) wfrag64_k(
    const float* __restrict__ W, float* __restrict__ out) {
    float* O = out + blockIdx.x * 4096;
    const int kc = blockIdx.x >> 1, nb = blockIdx.x & 1;
    const int nl = threadIdx.x >> 1;
    const int khalf = (threadIdx.x & 1) * 16;
    const int n = nb * 128 + nl;
    #pragma unroll
    for (int g = 0; g < 4; ++g) {
        int kk = khalf + g * 4;
        int k = kc * 32 + kk;
        float4 v;
        v.x = tf32r(W[(size_t)(k+0)*256 + n]);
        v.y = tf32r(W[(size_t)(k+1)*256 + n]);
        v.z = tf32r(W[(size_t)(k+2)*256 + n]);
        v.w = tf32r(W[(size_t)(k+3)*256 + n]);
        int idx = ((kk>>3)*8 + (nl>>4))*128
                + ((((nl>>3)&1)<<1) | ((kk>>2)&1))*32 + (nl&7)*4;
        *(float4*)&O[idx] = v;
    }
}

// ---------------- tensor-core GEMM via mma.sync tf32 ------------------------
// C[M,256] = A@W (+A2@W2) (+bias[*rowscale]) (relu)
// CTA 128x128, 256 threads, 8 warps (2M x 4N), warp tile 64x32.
// B pre-permuted -> cp.async; A fragment-staged via 16 regs, 2-chunk pipeline.
#define GEMM_SMEM 65536

template<int KROW, bool DUAL, bool RELU, bool ROWSCALE>
__global__ void __launch_bounds__(256, 2) gemm_mma(
    const float* __restrict__ A,  const float* __restrict__ Wf,
    const float* __restrict__ A2, const float* __restrict__ Wf2,
    const float* __restrict__ bias, const float* __restrict__ rowscale,
    float* __restrict__ C, int M)
{
    extern __shared__ float smf[];
    float* sA = smf;            // 2 x 4096
    float* sB = smf + 8192;     // 2 x 4096
    const uint32_t sB_u = smem_u32(sB);

    const int tid = threadIdx.x;
    const int wid = tid >> 5, lane = tid & 31;
    const int warp_m = wid & 1, warp_n = wid >> 1;   // 2M x 4N
    const int bm = blockIdx.x * 128;
    const int nb = blockIdx.y;                        // 128-col block

    const int am = tid >> 1;                  // staged A row (0..127)
    const int khalf = (tid & 1) * 16;
    const int arow = bm + am;
    // A fragment-store constants
    const int a_mt4 = (am >> 4) * 4;
    const int a_rb = (am >> 3) & 1;
    const int a_lh = (am & 7) * 4;

    float acc[4][4][4];
    #pragma unroll
    for (int t = 0; t < 4; ++t)
        #pragma unroll
        for (int j = 0; j < 4; ++j)
            #pragma unroll
            for (int q = 0; q < 4; ++q) acc[t][j][q] = 0.f;

    const int KC = KROW / 32;
    const int NCHUNK = (DUAL ? 2 : 1) * KC;
    float4 ra[4];

    auto ldgA = [&](int c) {
        const float* Ap = (DUAL && c >= KC) ? A2 : A;
        int k0 = ((DUAL && c >= KC) ? (c - KC) : c) * 32 + khalf;
        const float* p = Ap + (size_t)arow * KROW + k0;
        #pragma unroll
        for (int i = 0; i < 4; ++i)
            ra[i] = (arow < M) ? *(const float4*)(p + i * 4)
                               : make_float4(0.f, 0.f, 0.f, 0.f);
    };
    auto stsA = [&](int buf) {
        float* a = sA + buf * 4096;
        #pragma unroll
        for (int g = 0; g < 4; ++g) {
            int kk = khalf + g * 4;
            int r = ((((kk >> 2) & 1) << 1) | a_rb);
            float4 v = ra[g];
            v.x = tf32r(v.x); v.y = tf32r(v.y);
            v.z = tf32r(v.z); v.w = tf32r(v.w);
            *(float4*)&a[(a_mt4 + (kk >> 3)) * 128 + r * 32 + a_lh] = v;
        }
    };
    auto cpB = [&](int c, int buf) {
        const float* Wp = (DUAL && c >= KC) ? Wf2 : Wf;
        int cc = (DUAL && c >= KC) ? (c - KC) : c;
        const float* src = Wp + ((size_t)cc * 2 + nb) * 4096 + tid * 16;
        uint32_t dst = sB_u + buf * 16384 + tid * 64;
        #pragma unroll
        for (int i = 0; i < 4; ++i)
            cp_async16(dst + i * 16, src + i * 4);
    };
    auto compute_ks = [&](int buf, int ks) {
        const float* a = sA + buf * 4096;
        const float* b = sB + buf * 4096;
        uint32_t av[4][4], bv[2][4];
        #pragma unroll
        for (int t = 0; t < 4; ++t) {
            int base = ((warp_m * 4 + t) * 4 + ks) * 128 + lane;
            av[t][0] = __float_as_uint(a[base]);
            av[t][1] = __float_as_uint(a[base + 32]);
            av[t][2] = __float_as_uint(a[base + 64]);
            av[t][3] = __float_as_uint(a[base + 96]);
        }
        #pragma unroll
        for (int p = 0; p < 2; ++p) {
            int base = (ks * 8 + warp_n * 2 + p) * 128 + lane;
            bv[p][0] = __float_as_uint(b[base]);
            bv[p][1] = __float_as_uint(b[base + 32]);
            bv[p][2] = __float_as_uint(b[base + 64]);
            bv[p][3] = __float_as_uint(b[base + 96]);
        }
        #pragma unroll
        for (int t = 0; t < 4; ++t)
            #pragma unroll
            for (int j = 0; j < 4; ++j) {
                int p = j >> 1, half = j & 1;
                MMA_TF32(acc[t][j], av[t], bv[p][half * 2], bv[p][half * 2 + 1]);
            }
    };

    // prologue
    ldgA(0);
    cpB(0, 0); CP_COMMIT();
    stsA(0);
    if (NCHUNK > 1) ldgA(1);
    CP_WAIT0();
    __syncthreads();

    for (int c = 0; c < NCHUNK; ++c) {
        const int buf = c & 1;
        if (c + 1 < NCHUNK) {
            cpB(c + 1, buf ^ 1); CP_COMMIT();
            stsA(buf ^ 1);
            if (c + 2 < NCHUNK) ldgA(c + 2);
        }
        compute_ks(buf, 0);
        compute_ks(buf, 1);
        compute_ks(buf, 2);
        compute_ks(buf, 3);
        if (c + 1 < NCHUNK) {
            CP_WAIT0();
            __syncthreads();
        }
    }

    // ---- epilogue ----
    const int row_base = bm + warp_m * 64 + (lane >> 2);
    const int col_base = nb * 128 + warp_n * 32 + (lane & 3) * 2;
    #pragma unroll
    for (int t = 0; t < 4; ++t) {
        int r0 = row_base + t * 16;
        int r1 = r0 + 8;
        float s0 = 1.f, s1 = 1.f;
        if (ROWSCALE) {
            s0 = (r0 < M) ? rowscale[r0] : 0.f;
            s1 = (r1 < M) ? rowscale[r1] : 0.f;
        }
        #pragma unroll
        for (int j = 0; j < 4; ++j) {
            int col = col_base + j * 8;
            float bb0 = 0.f, bb1 = 0.f;
            if (bias) { bb0 = __ldg(bias + col); bb1 = __ldg(bias + col + 1); }
            float v00 = acc[t][j][0] + bb0 * s0;
            float v01 = acc[t][j][1] + bb1 * s0;
            float v10 = acc[t][j][2] + bb0 * s1;
            float v11 = acc[t][j][3] + bb1 * s1;
            if (RELU) {
                v00 = fmaxf(v00, 0.f); v01 = fmaxf(v01, 0.f);
                v10 = fmaxf(v10, 0.f); v11 = fmaxf(v11, 0.f);
            }
            if (r0 < M) *(float2*)(C + (size_t)r0 * 256 + col) = make_float2(v00, v01);
            if (r1 < M) *(float2*)(C + (size_t)r1 * 256 + col) = make_float2(v10, v11);
        }
    }
}

// ---------------- geo stage: xin[n] = [relu(x[:,:128]@geoW+b) | x[:,128:160]] --
__global__ void __launch_bounds__(256) geo_k(
    const float* __restrict__ x,
    const float* __restrict__ geo_w, const float* __restrict__ geo_b,
    float* __restrict__ out)   // [NN, 64]
{
    __shared__ float gws[4096];
    __shared__ float gbs[32];
    for (int i = threadIdx.x; i < 4096; i += 256) gws[i] = geo_w[i];
    if (threadIdx.x < 32) gbs[threadIdx.x] = geo_b[threadIdx.x];
    __syncthreads();
    const int warp = threadIdx.x >> 5, lane = threadIdx.x & 31;
    for (int n0 = blockIdx.x * 8; n0 < NN; n0 += gridDim.x * 8) {
        int n = n0 + warp;
        if (n < NN) {
            const float* xr = x + (size_t)n * 160;
            float s = gbs[lane];
            #pragma unroll
            for (int k = 0; k < 128; ++k) s += __ldg(xr + k) * gws[k * 32 + lane];
            out[(size_t)n * 64 + lane]      = fmaxf(s, 0.f);
            out[(size_t)n * 64 + 32 + lane] = __ldg(xr + 128 + lane);
        }
    }
}

// ---------------- edge encoder + scatter (weights in registers) -------------
__global__ void __launch_bounds__(256) edge_encode_k(
    const float* __restrict__ ea, const int* __restrict__ eidx,
    const float* __restrict__ w1, const float* __restrict__ b1,
    float* __restrict__ At, float* __restrict__ deg)
{
    const int tid = threadIdx.x;
    const int c0 = (tid & 63) * 4;
    const int slot = tid >> 6;
    float4 wreg[16];
    #pragma unroll
    for (int k = 0; k < 16; ++k)
        wreg[k] = *(const float4*)(w1 + k * 256 + c0);
    const float4 b1v = *(const float4*)(b1 + c0);

    __shared__ float eav[4][16];
    __shared__ int dsts[4];

    for (int base = blockIdx.x * 4; base < NE; base += gridDim.x * 4) {
        if (tid < 64) ((float*)eav)[tid] = ea[(size_t)base * 16 + tid];
        if (tid < 4) dsts[tid] = eidx[NE + base + tid];
        __syncthreads();
        float4 acc = b1v;
        #pragma unroll
        for (int k = 0; k < 16; ++k) {
            float e = eav[slot][k];
            acc.x += wreg[k].x * e;
            acc.y += wreg[k].y * e;
            acc.z += wreg[k].z * e;
            acc.w += wreg[k].w * e;
        }
        acc.x = fmaxf(acc.x, 0.f); acc.y = fmaxf(acc.y, 0.f);
        acc.z = fmaxf(acc.z, 0.f); acc.w = fmaxf(acc.w, 0.f);
        int dst = dsts[slot];
        redAdd4(At + (size_t)dst * 256 + c0, acc);
        if ((tid & 63) == 0) atomicAdd(deg + dst, 1.f);
        __syncthreads();
    }
}

// ---------------- SpMM scatter: agg[dst] += h[src] --------------------------
__global__ void __launch_bounds__(256) spmm_k(
    const float* __restrict__ h, const int* __restrict__ eidx,
    float* __restrict__ agg)
{
    int gw = (blockIdx.x*blockDim.x + threadIdx.x) >> 5;
    int lane = threadIdx.x & 31;
    int nw = (gridDim.x*blockDim.x) >> 5;
    for (int e = gw; e < NE; e += nw) {
        int src = eidx[e];
        int dst = eidx[NE + e];
        const float* hp = h + (size_t)src*256;
        float* ap = agg + (size_t)dst*256;
        int c = lane*8;
        float4 v0 = *(const float4*)(hp + c);
        float4 v1 = *(const float4*)(hp + c + 4);
        redAdd4(ap + c,     v0);
        redAdd4(ap + c + 4, v1);
    }
}

// ---------------- residual + layernorm (warp per row) -----------------------
__global__ void __launch_bounds__(256) ln_k(
    float* __restrict__ h, const float* __restrict__ u,
    const float* __restrict__ g, const float* __restrict__ b)
{
    int gw = (blockIdx.x*blockDim.x + threadIdx.x) >> 5;
    int lane = threadIdx.x & 31;
    int nw = (gridDim.x*blockDim.x) >> 5;
    for (int n = gw; n < NN; n += nw) {
        float* hp = h + (size_t)n*256;
        const float* up = u + (size_t)n*256;
        float v[8];
        float4 h0 = *(float4*)(hp + lane*8),       h1 = *(float4*)(hp + lane*8 + 4);
        float4 u0 = *(const float4*)(up + lane*8), u1 = *(const float4*)(up + lane*8 + 4);
        v[0]=h0.x+u0.x; v[1]=h0.y+u0.y; v[2]=h0.z+u0.z; v[3]=h0.w+u0.w;
        v[4]=h1.x+u1.x; v[5]=h1.y+u1.y; v[6]=h1.z+u1.z; v[7]=h1.w+u1.w;
        float s = 0.f;
        #pragma unroll
        for (int i = 0; i < 8; ++i) s += v[i];
        #pragma unroll
        for (int o = 16; o > 0; o >>= 1) s += __shfl_xor_sync(0xffffffffu, s, o);
        float mu = s * (1.f/256.f);
        float qq = 0.f;
        #pragma unroll
        for (int i = 0; i < 8; ++i) { float d = v[i]-mu; qq += d*d; }
        #pragma unroll
        for (int o = 16; o > 0; o >>= 1) qq += __shfl_xor_sync(0xffffffffu, qq, o);
        float rstd = rsqrtf(qq*(1.f/256.f) + 1e-5f);
        #pragma unroll
        for (int i = 0; i < 8; ++i) {
            int c = lane*8 + i;
            v[i] = (v[i]-mu)*rstd*__ldg(g+c) + __ldg(b+c);
        }
        *(float4*)(hp + lane*8)     = make_float4(v[0],v[1],v[2],v[3]);
        *(float4*)(hp + lane*8 + 4) = make_float4(v[4],v[5],v[6],v[7]);
    }
}

// ---------------- typed mean-pool partial sums -------------------------------
__global__ void __launch_bounds__(256) pool_k(
    const float* __restrict__ h, const int* __restrict__ batch,
    const int* __restrict__ ntype, float* __restrict__ ps, float* __restrict__ pc)
{
    __shared__ float acc[24][256];
    __shared__ float cnt[24];
    for (int i = threadIdx.x; i < 24*256; i += 256) (&acc[0][0])[i] = 0.f;
    if (threadIdx.x < 24) cnt[threadIdx.x] = 0.f;
    __syncthreads();
    int per = (NN + gridDim.x - 1) / gridDim.x;
    int start = blockIdx.x * per;
    int end = start + per; if (end > NN) end = NN;
    for (int n = start; n < end; ++n) {
        int idx = __ldg(ntype+n)*8 + __ldg(batch+n);
        acc[idx][threadIdx.x] += h[(size_t)n*256 + threadIdx.x];
        if (threadIdx.x == 0) cnt[idx] += 1.f;
    }
    __syncthreads();
    for (int i = threadIdx.x; i < 24*256; i += 256) atomicAdd(&ps[i], (&acc[0][0])[i]);
    if (threadIdx.x < 24) atomicAdd(&pc[threadIdx.x], cnt[threadIdx.x]);
}

// ---------------- final write: z | h | batch ---------------------------------
__global__ void __launch_bounds__(256) writeout_k(
    const float* __restrict__ ps, const float* __restrict__ pc,
    const float* __restrict__ h, const int* __restrict__ batch,
    float* __restrict__ out, int out_size)
{
    const int total = 24*256 + NN*HD + NN;
    for (int i = blockIdx.x*blockDim.x + threadIdx.x; i < total;
         i += gridDim.x*blockDim.x) {
        float v; int o;
        if (i < 6144) {
            int c = i & 255, kb = i >> 8, k = kb >> 3, bb = kb & 7;
            float cc = pc[kb]; if (cc < 1.f) cc = 1.f;
            v = ps[i] / cc;
            o = bb*768 + k*256 + c;
        } else if (i < 6144 + NN*HD) {
            v = h[i - 6144]; o = i;
        } else {
            v = (float)batch[i - 6144 - NN*HD]; o = i;
        }
        if (o < out_size) out[o] = v;
    }
}

// ---------------- launcher ----------------------------------------------------
extern "C" void kernel_launch(void* const* d_in, const int* in_sizes, int n_in,
                              void* d_out, int out_size)
{
    const float* x       = (const float*)d_in[0];
    const float* ea      = (const float*)d_in[1];
    const float* geo_w   = (const float*)d_in[2];
    const float* geo_b   = (const float*)d_in[3];
    const float* nin_w1  = (const float*)d_in[4];
    const float* nin_b1  = (const float*)d_in[5];
    const float* nin_w2  = (const float*)d_in[6];
    const float* nin_b2  = (const float*)d_in[7];
    const float* ee_w1   = (const float*)d_in[8];
    const float* ee_b1   = (const float*)d_in[9];
    const float* ee_w2   = (const float*)d_in[10];
    const float* ee_b2   = (const float*)d_in[11];
    const float* msgx    = (const float*)d_in[12];
    const float* msge    = (const float*)d_in[13];
    const float* upd_w1  = (const float*)d_in[14];
    const float* upd_b1  = (const float*)d_in[15];
    const float* upd_w2  = (const float*)d_in[16];
    const float* upd_b2  = (const float*)d_in[17];
    const float* ln_g    = (const float*)d_in[18];
    const float* ln_b    = (const float*)d_in[19];
    const int*   eidx    = (const int*)d_in[20];
    const int*   batch   = (const int*)d_in[21];
    const int*   ntype   = (const int*)d_in[22];
    float* out = (float*)d_out;

    float *h_, *d1_, *d2_, *d3_, *ae_, *deg_, *ps_, *pc_, *wt_, *wt1_;
    cudaGetSymbolAddress((void**)&h_,  g_h);
    cudaGetSymbolAddress((void**)&d1_, g_d1);
    cudaGetSymbolAddress((void**)&d2_, g_d2);
    cudaGetSymbolAddress((void**)&d3_, g_d3);
    cudaGetSymbolAddress((void**)&ae_, g_ae);
    cudaGetSymbolAddress((void**)&deg_, g_deg);
    cudaGetSymbolAddress((void**)&ps_, g_ps);
    cudaGetSymbolAddress((void**)&pc_, g_pc);
    cudaGetSymbolAddress((void**)&wt_, g_wt);
    cudaGetSymbolAddress((void**)&wt1_, g_wt1);

    cudaFuncSetAttribute(gemm_mma<256,false,false,false>,
        cudaFuncAttributeMaxDynamicSharedMemorySize, GEMM_SMEM);
    cudaFuncSetAttribute(gemm_mma<256,false,false,true>,
        cudaFuncAttributeMaxDynamicSharedMemorySize, GEMM_SMEM);
    cudaFuncSetAttribute(gemm_mma<256,true,false,false>,
        cudaFuncAttributeMaxDynamicSharedMemorySize, GEMM_SMEM);
    cudaFuncSetAttribute(gemm_mma<256,false,true,false>,
        cudaFuncAttributeMaxDynamicSharedMemorySize, GEMM_SMEM);
    cudaFuncSetAttribute(gemm_mma<64,false,true,false>,
        cudaFuncAttributeMaxDynamicSharedMemorySize, GEMM_SMEM);

    // weight order: 0 nin_w2, 1 ee_w2, 2..5 msgx, 6..9 msge, 10..13 upd_w1, 14..17 upd_w2
    WPtrs wp;
    wp.p[0] = nin_w2; wp.p[1] = ee_w2;
    for (int l = 0; l < 4; ++l) {
        wp.p[2 + l]  = msgx   + (size_t)l*65536;
        wp.p[6 + l]  = msge   + (size_t)l*65536;
        wp.p[10 + l] = upd_w1 + (size_t)l*65536;
        wp.p[14 + l] = upd_w2 + (size_t)l*65536;
    }
    wfrag_k<<<dim3(16, 18), 256>>>(wp, wt_);
    wfrag64_k<<<4, 256>>>(nin_w1, wt1_);

    dim3 gg(391, 2);   // ceil(50000/128) x (256/128)

    // node encoder: xin (d3 as [NN,64]) -> d1 = relu(xin@W1+b1) -> h = d1@W2+b2
    geo_k<<<625, 256>>>(x, geo_w, geo_b, d3_);
    gemm_mma<64,false,true,false><<<gg, 256, GEMM_SMEM>>>(
        d3_, wt1_, nullptr, nullptr, nin_b1, nullptr, d1_, NN);
    gemm_mma<256,false,false,false><<<gg, 256, GEMM_SMEM>>>(
        d1_, wt_ + 0*65536, nullptr, nullptr, nin_b2, nullptr, h_, NN);

    // edge encoder scatter: d2 = segsum(relu(ea@W1+b1)), deg = indegree
    cudaMemsetAsync(d2_, 0, (size_t)NN*HD*sizeof(float));
    cudaMemsetAsync(deg_, 0, (size_t)NN*sizeof(float));
    edge_encode_k<<<1184, 256>>>(ea, eidx, ee_w1, ee_b1, d2_, deg_);
    // Ae = d2 @ ee_w2 + deg * ee_b2
    gemm_mma<256,false,false,true><<<gg, 256, GEMM_SMEM>>>(
        d2_, wt_ + 1*65536, nullptr, nullptr, ee_b2, deg_, ae_, NN);

    for (int l = 0; l < NL; ++l) {
        // agg = A @ h
        cudaMemsetAsync(d1_, 0, (size_t)NN*HD*sizeof(float));
        spmm_k<<<1184, 256>>>(h_, eidx, d1_);
        // d2 = agg@msgx + Ae@msge
        gemm_mma<256,true,false,false><<<gg, 256, GEMM_SMEM>>>(
            d1_, wt_ + (size_t)(2+l)*65536, ae_, wt_ + (size_t)(6+l)*65536,
            nullptr, nullptr, d2_, NN);
        // d3 = relu(d2@upd_w1 + b1)
        gemm_mma<256,false,true,false><<<gg, 256, GEMM_SMEM>>>(
            d2_, wt_ + (size_t)(10+l)*65536, nullptr, nullptr,
            upd_b1 + l*256, nullptr, d3_, NN);
        // d1 = d3@upd_w2 + b2
        gemm_mma<256,false,false,false><<<gg, 256, GEMM_SMEM>>>(
            d3_, wt_ + (size_t)(14+l)*65536, nullptr, nullptr,
            upd_b2 + l*256, nullptr, d1_, NN);
        // h = LN(h + d1)
        ln_k<<<784, 256>>>(h_, d1_, ln_g + l*256, ln_b + l*256);
    }

    cudaMemsetAsync(ps_, 0, 24*HD*sizeof(float));
    cudaMemsetAsync(pc_, 0, 24*sizeof(float));
    pool_k<<<512, 256>>>(h_, batch, ntype, ps_, pc_);
    writeout_k<<<8192, 256>>>(ps_, pc_, h_, batch, out, out_size);
}

// round 6
// speedup vs baseline: 1.9735x; 1.0982x over previous
#include <cuda_runtime.h>
#include <cstdint>

#define NN 50000
#define NE 300000
#define HD 256
#define NB 8
#define NL 4

// ---------------- scratch (static device globals; no allocs allowed) -------
__device__ float g_h [NN*HD];
__device__ float g_d1[NN*HD];
__device__ float g_d2[NN*HD];
__device__ float g_d3[NN*HD];
__device__ float g_ae[NN*HD];
__device__ float g_deg[NN];
__device__ float g_ps[24*HD];
__device__ float g_pc[24];
__device__ float g_wt[18*65536];   // fragment-permuted tf32 weights, 256-K mats
__device__ float g_wt1[16384];     // fragment-permuted nin_w1 (K=64)
__device__ int   g_rp[NN+1];       // CSR row pointer (by dst)
__device__ int   g_cur[NN];        // counts, then cursors
__device__ int   g_el[NE];         // CSR column (src) list

// ---------------- helpers ------------------------------------------------
__device__ __forceinline__ float tf32r(float x) {
    float r;
    asm("cvt.rna.tf32.f32 %0, %1;" : "=f"(r) : "f"(x));
    return r;
}
__device__ __forceinline__ void redAdd4(float* p, float4 v) {
    asm volatile("red.global.add.v4.f32 [%0], {%1,%2,%3,%4};"
                 :: "l"(p), "f"(v.x), "f"(v.y), "f"(v.z), "f"(v.w) : "memory");
}
__device__ __forceinline__ uint32_t smem_u32(const void* p) {
    uint32_t a;
    asm("{ .reg .u64 t; cvta.to.shared.u64 t, %1; cvt.u32.u64 %0, t; }"
        : "=r"(a) : "l"(p));
    return a;
}
__device__ __forceinline__ void cp_async16(uint32_t sdst, const void* gsrc) {
    asm volatile("cp.async.ca.shared.global [%0], [%1], 16;"
                 :: "r"(sdst), "l"(gsrc) : "memory");
}
#define CP_COMMIT() asm volatile("cp.async.commit_group;" ::: "memory")
#define CP_WAIT1()  asm volatile("cp.async.wait_group 1;" ::: "memory")

#define MMA_TF32(c, a, b0, b1)                                               \
    asm volatile("mma.sync.aligned.m16n8k8.row.col.f32.tf32.tf32.f32 "      \
        "{%0,%1,%2,%3}, {%4,%5,%6,%7}, {%8,%9}, {%0,%1,%2,%3};"             \
        : "+f"((c)[0]), "+f"((c)[1]), "+f"((c)[2]), "+f"((c)[3])            \
        : "r"((a)[0]), "r"((a)[1]), "r"((a)[2]), "r"((a)[3]),               \
          "r"(b0), "r"(b1))

// ---------------- weight -> fragment-major blocks ---------------------------
struct WPtrs { const float* p[18]; };

__global__ void __launch_bounds__(256) wfrag_k(WPtrs wp, float* __restrict__ out) {
    const float* W = wp.p[blockIdx.y];
    float* O = out + (size_t)blockIdx.y * 65536 + blockIdx.x * 4096;
    const int kc = blockIdx.x >> 1, nb = blockIdx.x & 1;
    const int nl = threadIdx.x >> 1;
    const int khalf = (threadIdx.x & 1) * 16;
    const int n = nb * 128 + nl;
    #pragma unroll
    for (int g = 0; g < 4; ++g) {
        int kk = khalf + g * 4;
        int k = kc * 32 + kk;
        float4 v;
        v.x = tf32r(W[(size_t)(k+0)*256 + n]);
        v.y = tf32r(W[(size_t)(k+1)*256 + n]);
        v.z = tf32r(W[(size_t)(k+2)*256 + n]);
        v.w = tf32r(W[(size_t)(k+3)*256 + n]);
        int idx = ((kk>>3)*8 + (nl>>4))*128
                + ((((nl>>3)&1)<<1) | ((kk>>2)&1))*32 + (nl&7)*4;
        *(float4*)&O[idx] = v;
    }
}

__global__ void __launch_bounds__(256) wfrag64_k(
    const float* __restrict__ W, float* __restrict__ out) {
    float* O = out + blockIdx.x * 4096;
    const int kc = blockIdx.x >> 1, nb = blockIdx.x & 1;
    const int nl = threadIdx.x >> 1;
    const int khalf = (threadIdx.x & 1) * 16;
    const int n = nb * 128 + nl;
    #pragma unroll
    for (int g = 0; g < 4; ++g) {
        int kk = khalf + g * 4;
        int k = kc * 32 + kk;
        float4 v;
        v.x = tf32r(W[(size_t)(k+0)*256 + n]);
        v.y = tf32r(W[(size_t)(k+1)*256 + n]);
        v.z = tf32r(W[(size_t)(k+2)*256 + n]);
        v.w = tf32r(W[(size_t)(k+3)*256 + n]);
        int idx = ((kk>>3)*8 + (nl>>4))*128
                + ((((nl>>3)&1)<<1) | ((kk>>2)&1))*32 + (nl&7)*4;
        *(float4*)&O[idx] = v;
    }
}

// ---------------- tensor-core GEMM via mma.sync tf32 ------------------------
// CTA 128x128, 256 threads, 8 warps (2M x 4N), warp tile 64x32.
// 3-stage cp.async pipeline; A row-major XOR-swizzled, B pre-permuted.
// tf32 RNA rounding applied after LDS on A (numerics == round-then-mma).
#define GEMM_SMEM 98304

template<int KROW, bool DUAL, bool RELU, bool ROWSCALE>
__global__ void __launch_bounds__(256, 2) gemm_mma(
    const float* __restrict__ A,  const float* __restrict__ Wf,
    const float* __restrict__ A2, const float* __restrict__ Wf2,
    const float* __restrict__ bias, const float* __restrict__ rowscale,
    float* __restrict__ C, int M)
{
    extern __shared__ float smf[];   // stage s: A at s*8192, B at s*8192+4096
    const uint32_t sbase = smem_u32(smf);

    const int tid = threadIdx.x;
    const int wid = tid >> 5, lane = tid & 31;
    const int warp_m = wid & 1, warp_n = wid >> 1;   // 2M x 4N
    const int bm = blockIdx.x * 128;
    const int nb = blockIdx.y;

    const int a_row = tid >> 1;
    const int a_half = tid & 1;
    const int arow = bm + a_row;
    const int a_sw = a_row & 7;

    float acc[4][4][4];
    #pragma unroll
    for (int t = 0; t < 4; ++t)
        #pragma unroll
        for (int j = 0; j < 4; ++j)
            #pragma unroll
            for (int q = 0; q < 4; ++q) acc[t][j][q] = 0.f;

    const int KC = KROW / 32;
    const int NCHUNK = (DUAL ? 2 : 1) * KC;

    auto cpA = [&](int c, int s) {
        const float* Ap = (DUAL && c >= KC) ? A2 : A;
        int k0 = ((DUAL && c >= KC) ? (c - KC) : c) * 32;
        if (arow < M) {
            const float* src = Ap + (size_t)arow * KROW + k0 + a_half * 16;
            uint32_t drow = sbase + s * 32768 + a_row * 128;
            #pragma unroll
            for (int j = 0; j < 4; ++j) {
                int chunk = a_half * 4 + j;
                cp_async16(drow + ((chunk ^ a_sw) << 4), src + j * 4);
            }
        } else {
            float* drow = smf + s * 8192 + a_row * 32;
            #pragma unroll
            for (int j = 0; j < 4; ++j) {
                int chunk = a_half * 4 + j;
                *(float4*)(drow + ((chunk ^ a_sw) << 2)) =
                    make_float4(0.f, 0.f, 0.f, 0.f);
            }
        }
    };
    auto cpB = [&](int c, int s) {
        const float* Wp = (DUAL && c >= KC) ? Wf2 : Wf;
        int cc = (DUAL && c >= KC) ? (c - KC) : c;
        const float* src = Wp + ((size_t)cc * 2 + nb) * 4096 + tid * 16;
        uint32_t dst = sbase + s * 32768 + 16384 + tid * 64;
        #pragma unroll
        for (int i = 0; i < 4; ++i)
            cp_async16(dst + i * 16, src + i * 4);
    };
    auto compute_ks = [&](int s, int ks) {
        const float* a = smf + s * 8192;
        const float* b = smf + s * 8192 + 4096;
        const int lr = lane >> 2, lc = lane & 3;
        uint32_t av[4][4], bv[2][4];
        #pragma unroll
        for (int t = 0; t < 4; ++t) {
            int m0 = warp_m * 64 + t * 16 + lr;
            #pragma unroll
            for (int i = 0; i < 4; ++i) {
                int row = m0 + (i & 1) * 8;
                int chunk = 2 * ks + (i >> 1);
                float v = a[row * 32 + ((chunk ^ lr) << 2) + lc];
                av[t][i] = __float_as_uint(tf32r(v));
            }
        }
        #pragma unroll
        for (int p = 0; p < 2; ++p) {
            int base = (ks * 8 + warp_n * 2 + p) * 128 + lane;
            bv[p][0] = __float_as_uint(b[base]);
            bv[p][1] = __float_as_uint(b[base + 32]);
            bv[p][2] = __float_as_uint(b[base + 64]);
            bv[p][3] = __float_as_uint(b[base + 96]);
        }
        #pragma unroll
        for (int t = 0; t < 4; ++t)
            #pragma unroll
            for (int j = 0; j < 4; ++j) {
                int p = j >> 1, half = j & 1;
                MMA_TF32(acc[t][j], av[t], bv[p][half * 2], bv[p][half * 2 + 1]);
            }
    };

    // prologue: stages 0,1
    #pragma unroll
    for (int s = 0; s < 2; ++s) {
        if (s < NCHUNK) { cpA(s, s); cpB(s, s); }
        CP_COMMIT();
    }
    for (int c = 0; c < NCHUNK; ++c) {
        CP_WAIT1();
        __syncthreads();
        int sl = c + 2;
        if (sl < NCHUNK) { cpA(sl, sl % 3); cpB(sl, sl % 3); }
        CP_COMMIT();
        int s = c % 3;
        compute_ks(s, 0);
        compute_ks(s, 1);
        compute_ks(s, 2);
        compute_ks(s, 3);
    }

    // ---- epilogue ----
    const int row_base = bm + warp_m * 64 + (lane >> 2);
    const int col_base = nb * 128 + warp_n * 32 + (lane & 3) * 2;
    #pragma unroll
    for (int t = 0; t < 4; ++t) {
        int r0 = row_base + t * 16;
        int r1 = r0 + 8;
        float s0 = 1.f, s1 = 1.f;
        if (ROWSCALE) {
            s0 = (r0 < M) ? rowscale[r0] : 0.f;
            s1 = (r1 < M) ? rowscale[r1] : 0.f;
        }
        #pragma unroll
        for (int j = 0; j < 4; ++j) {
            int col = col_base + j * 8;
            float bb0 = 0.f, bb1 = 0.f;
            if (bias) { bb0 = __ldg(bias + col); bb1 = __ldg(bias + col + 1); }
            float v00 = acc[t][j][0] + bb0 * s0;
            float v01 = acc[t][j][1] + bb1 * s0;
            float v10 = acc[t][j][2] + bb0 * s1;
            float v11 = acc[t][j][3] + bb1 * s1;
            if (RELU) {
                v00 = fmaxf(v00, 0.f); v01 = fmaxf(v01, 0.f);
                v10 = fmaxf(v10, 0.f); v11 = fmaxf(v11, 0.f);
            }
            if (r0 < M) *(float2*)(C + (size_t)r0 * 256 + col) = make_float2(v00, v01);
            if (r1 < M) *(float2*)(C + (size_t)r1 * 256 + col) = make_float2(v10, v11);
        }
    }
}

// ---------------- CSR build (by dst) -----------------------------------------
__global__ void __launch_bounds__(256) hist_k(
    const int* __restrict__ eidx, int* __restrict__ cnt) {
    int i = blockIdx.x * blockDim.x + threadIdx.x;
    if (i < NE) atomicAdd(&cnt[eidx[NE + i]], 1);
}

__global__ void __launch_bounds__(1024) scan_k(
    int* __restrict__ cnt, int* __restrict__ rp) {
    __shared__ int part[1024];
    const int t = threadIdx.x;
    const int ITEMS = (NN + 1023) / 1024;   // 49
    const int base = t * ITEMS;
    int s = 0;
    for (int j = 0; j < ITEMS; ++j) {
        int idx = base + j;
        if (idx < NN) s += cnt[idx];
    }
    part[t] = s;
    __syncthreads();
    for (int off = 1; off < 1024; off <<= 1) {
        int v = (t >= off) ? part[t - off] : 0;
        __syncthreads();
        part[t] += v;
        __syncthreads();
    }
    int run = (t == 0) ? 0 : part[t - 1];
    for (int j = 0; j < ITEMS; ++j) {
        int idx = base + j;
        if (idx < NN) {
            int c = cnt[idx];
            rp[idx] = run;
            cnt[idx] = run;   // becomes cursor
            run += c;
        }
    }
    if (t == 1023) rp[NN] = run;
}

__global__ void __launch_bounds__(256) scatter_k(
    const int* __restrict__ eidx, int* __restrict__ cur, int* __restrict__ el) {
    int e = blockIdx.x * blockDim.x + threadIdx.x;
    if (e < NE) {
        int pos = atomicAdd(&cur[eidx[NE + e]], 1);
        el[pos] = eidx[e];
    }
}

// ---------------- SpMM gather: agg[n] = sum_{e in-edges(n)} h[src(e)] --------
__global__ void __launch_bounds__(256) spmm_gather_k(
    const float* __restrict__ h, const int* __restrict__ rp,
    const int* __restrict__ el, float* __restrict__ agg)
{
    int n = (blockIdx.x * 256 + threadIdx.x) >> 5;
    if (n >= NN) return;
    const int lane = threadIdx.x & 31;
    const int c = lane * 8;
    int s = rp[n], e = rp[n + 1];
    float4 a0 = make_float4(0.f,0.f,0.f,0.f);
    float4 a1 = make_float4(0.f,0.f,0.f,0.f);
    for (int i = s; i < e; ++i) {
        const float* hp = h + (size_t)el[i] * 256 + c;
        float4 v0 = *(const float4*)hp;
        float4 v1 = *(const float4*)(hp + 4);
        a0.x += v0.x; a0.y += v0.y; a0.z += v0.z; a0.w += v0.w;
        a1.x += v1.x; a1.y += v1.y; a1.z += v1.z; a1.w += v1.w;
    }
    float* ap = agg + (size_t)n * 256 + c;
    *(float4*)ap       = a0;
    *(float4*)(ap + 4) = a1;
}

// ---------------- geo stage ---------------------------------------------------
__global__ void __launch_bounds__(256) geo_k(
    const float* __restrict__ x,
    const float* __restrict__ geo_w, const float* __restrict__ geo_b,
    float* __restrict__ out)   // [NN, 64]
{
    __shared__ float gws[4096];
    __shared__ float gbs[32];
    for (int i = threadIdx.x; i < 4096; i += 256) gws[i] = geo_w[i];
    if (threadIdx.x < 32) gbs[threadIdx.x] = geo_b[threadIdx.x];
    __syncthreads();
    const int warp = threadIdx.x >> 5, lane = threadIdx.x & 31;
    for (int n0 = blockIdx.x * 8; n0 < NN; n0 += gridDim.x * 8) {
        int n = n0 + warp;
        if (n < NN) {
            const float* xr = x + (size_t)n * 160;
            float s = gbs[lane];
            #pragma unroll
            for (int k = 0; k < 128; ++k) s += __ldg(xr + k) * gws[k * 32 + lane];
            out[(size_t)n * 64 + lane]      = fmaxf(s, 0.f);
            out[(size_t)n * 64 + 32 + lane] = __ldg(xr + 128 + lane);
        }
    }
}

// ---------------- edge encoder + scatter (weights in registers) -------------
__global__ void __launch_bounds__(256) edge_encode_k(
    const float* __restrict__ ea, const int* __restrict__ eidx,
    const float* __restrict__ w1, const float* __restrict__ b1,
    float* __restrict__ At, float* __restrict__ deg)
{
    const int tid = threadIdx.x;
    const int c0 = (tid & 63) * 4;
    const int slot = tid >> 6;
    float4 wreg[16];
    #pragma unroll
    for (int k = 0; k < 16; ++k)
        wreg[k] = *(const float4*)(w1 + k * 256 + c0);
    const float4 b1v = *(const float4*)(b1 + c0);

    __shared__ float eav[4][16];
    __shared__ int dsts[4];

    for (int base = blockIdx.x * 4; base < NE; base += gridDim.x * 4) {
        if (tid < 64) ((float*)eav)[tid] = ea[(size_t)base * 16 + tid];
        if (tid < 4) dsts[tid] = eidx[NE + base + tid];
        __syncthreads();
        float4 acc = b1v;
        #pragma unroll
        for (int k = 0; k < 16; ++k) {
            float e = eav[slot][k];
            acc.x += wreg[k].x * e;
            acc.y += wreg[k].y * e;
            acc.z += wreg[k].z * e;
            acc.w += wreg[k].w * e;
        }
        acc.x = fmaxf(acc.x, 0.f); acc.y = fmaxf(acc.y, 0.f);
        acc.z = fmaxf(acc.z, 0.f); acc.w = fmaxf(acc.w, 0.f);
        int dst = dsts[slot];
        redAdd4(At + (size_t)dst * 256 + c0, acc);
        if ((tid & 63) == 0) atomicAdd(deg + dst, 1.f);
        __syncthreads();
    }
}

// ---------------- residual + layernorm (warp per row) -----------------------
__global__ void __launch_bounds__(256) ln_k(
    float* __restrict__ h, const float* __restrict__ u,
    const float* __restrict__ g, const float* __restrict__ b)
{
    int gw = (blockIdx.x*blockDim.x + threadIdx.x) >> 5;
    int lane = threadIdx.x & 31;
    int nw = (gridDim.x*blockDim.x) >> 5;
    for (int n = gw; n < NN; n += nw) {
        float* hp = h + (size_t)n*256;
        const float* up = u + (size_t)n*256;
        float v[8];
        float4 h0 = *(float4*)(hp + lane*8),       h1 = *(float4*)(hp + lane*8 + 4);
        float4 u0 = *(const float4*)(up + lane*8), u1 = *(const float4*)(up + lane*8 + 4);
        v[0]=h0.x+u0.x; v[1]=h0.y+u0.y; v[2]=h0.z+u0.z; v[3]=h0.w+u0.w;
        v[4]=h1.x+u1.x; v[5]=h1.y+u1.y; v[6]=h1.z+u1.z; v[7]=h1.w+u1.w;
        float s = 0.f;
        #pragma unroll
        for (int i = 0; i < 8; ++i) s += v[i];
        #pragma unroll
        for (int o = 16; o > 0; o >>= 1) s += __shfl_xor_sync(0xffffffffu, s, o);
        float mu = s * (1.f/256.f);
        float qq = 0.f;
        #pragma unroll
        for (int i = 0; i < 8; ++i) { float d = v[i]-mu; qq += d*d; }
        #pragma unroll
        for (int o = 16; o > 0; o >>= 1) qq += __shfl_xor_sync(0xffffffffu, qq, o);
        float rstd = rsqrtf(qq*(1.f/256.f) + 1e-5f);
        #pragma unroll
        for (int i = 0; i < 8; ++i) {
            int c = lane*8 + i;
            v[i] = (v[i]-mu)*rstd*__ldg(g+c) + __ldg(b+c);
        }
        *(float4*)(hp + lane*8)     = make_float4(v[0],v[1],v[2],v[3]);
        *(float4*)(hp + lane*8 + 4) = make_float4(v[4],v[5],v[6],v[7]);
    }
}

// ---------------- typed mean-pool partial sums -------------------------------
__global__ void __launch_bounds__(256) pool_k(
    const float* __restrict__ h, const int* __restrict__ batch,
    const int* __restrict__ ntype, float* __restrict__ ps, float* __restrict__ pc)
{
    __shared__ float acc[24][256];
    __shared__ float cnt[24];
    for (int i = threadIdx.x; i < 24*256; i += 256) (&acc[0][0])[i] = 0.f;
    if (threadIdx.x < 24) cnt[threadIdx.x] = 0.f;
    __syncthreads();
    int per = (NN + gridDim.x - 1) / gridDim.x;
    int start = blockIdx.x * per;
    int end = start + per; if (end > NN) end = NN;
    for (int n = start; n < end; ++n) {
        int idx = __ldg(ntype+n)*8 + __ldg(batch+n);
        acc[idx][threadIdx.x] += h[(size_t)n*256 + threadIdx.x];
        if (threadIdx.x == 0) cnt[idx] += 1.f;
    }
    __syncthreads();
    for (int i = threadIdx.x; i < 24*256; i += 256) atomicAdd(&ps[i], (&acc[0][0])[i]);
    if (threadIdx.x < 24) atomicAdd(&pc[threadIdx.x], cnt[threadIdx.x]);
}

// ---------------- final write: z | h | batch ---------------------------------
__global__ void __launch_bounds__(256) writeout_k(
    const float* __restrict__ ps, const float* __restrict__ pc,
    const float* __restrict__ h, const int* __restrict__ batch,
    float* __restrict__ out, int out_size)
{
    const int total = 24*256 + NN*HD + NN;
    for (int i = blockIdx.x*blockDim.x + threadIdx.x; i < total;
         i += gridDim.x*blockDim.x) {
        float v; int o;
        if (i < 6144) {
            int c = i & 255, kb = i >> 8, k = kb >> 3, bb = kb & 7;
            float cc = pc[kb]; if (cc < 1.f) cc = 1.f;
            v = ps[i] / cc;
            o = bb*768 + k*256 + c;
        } else if (i < 6144 + NN*HD) {
            v = h[i - 6144]; o = i;
        } else {
            v = (float)batch[i - 6144 - NN*HD]; o = i;
        }
        if (o < out_size) out[o] = v;
    }
}

// ---------------- launcher ----------------------------------------------------
extern "C" void kernel_launch(void* const* d_in, const int* in_sizes, int n_in,
                              void* d_out, int out_size)
{
    const float* x       = (const float*)d_in[0];
    const float* ea      = (const float*)d_in[1];
    const float* geo_w   = (const float*)d_in[2];
    const float* geo_b   = (const float*)d_in[3];
    const float* nin_w1  = (const float*)d_in[4];
    const float* nin_b1  = (const float*)d_in[5];
    const float* nin_w2  = (const float*)d_in[6];
    const float* nin_b2  = (const float*)d_in[7];
    const float* ee_w1   = (const float*)d_in[8];
    const float* ee_b1   = (const float*)d_in[9];
    const float* ee_w2   = (const float*)d_in[10];
    const float* ee_b2   = (const float*)d_in[11];
    const float* msgx    = (const float*)d_in[12];
    const float* msge    = (const float*)d_in[13];
    const float* upd_w1  = (const float*)d_in[14];
    const float* upd_b1  = (const float*)d_in[15];
    const float* upd_w2  = (const float*)d_in[16];
    const float* upd_b2  = (const float*)d_in[17];
    const float* ln_g    = (const float*)d_in[18];
    const float* ln_b    = (const float*)d_in[19];
    const int*   eidx    = (const int*)d_in[20];
    const int*   batch   = (const int*)d_in[21];
    const int*   ntype   = (const int*)d_in[22];
    float* out = (float*)d_out;

    float *h_, *d1_, *d2_, *d3_, *ae_, *deg_, *ps_, *pc_, *wt_, *wt1_;
    int *rp_, *cur_, *el_;
    cudaGetSymbolAddress((void**)&h_,  g_h);
    cudaGetSymbolAddress((void**)&d1_, g_d1);
    cudaGetSymbolAddress((void**)&d2_, g_d2);
    cudaGetSymbolAddress((void**)&d3_, g_d3);
    cudaGetSymbolAddress((void**)&ae_, g_ae);
    cudaGetSymbolAddress((void**)&deg_, g_deg);
    cudaGetSymbolAddress((void**)&ps_, g_ps);
    cudaGetSymbolAddress((void**)&pc_, g_pc);
    cudaGetSymbolAddress((void**)&wt_, g_wt);
    cudaGetSymbolAddress((void**)&wt1_, g_wt1);
    cudaGetSymbolAddress((void**)&rp_, g_rp);
    cudaGetSymbolAddress((void**)&cur_, g_cur);
    cudaGetSymbolAddress((void**)&el_, g_el);

    cudaFuncSetAttribute(gemm_mma<256,false,false,false>,
        cudaFuncAttributeMaxDynamicSharedMemorySize, GEMM_SMEM);
    cudaFuncSetAttribute(gemm_mma<256,false,false,true>,
        cudaFuncAttributeMaxDynamicSharedMemorySize, GEMM_SMEM);
    cudaFuncSetAttribute(gemm_mma<256,true,false,false>,
        cudaFuncAttributeMaxDynamicSharedMemorySize, GEMM_SMEM);
    cudaFuncSetAttribute(gemm_mma<256,false,true,false>,
        cudaFuncAttributeMaxDynamicSharedMemorySize, GEMM_SMEM);
    cudaFuncSetAttribute(gemm_mma<64,false,true,false>,
        cudaFuncAttributeMaxDynamicSharedMemorySize, GEMM_SMEM);

    // weight order: 0 nin_w2, 1 ee_w2, 2..5 msgx, 6..9 msge, 10..13 upd_w1, 14..17 upd_w2
    WPtrs wp;
    wp.p[0] = nin_w2; wp.p[1] = ee_w2;
    for (int l = 0; l < 4; ++l) {
        wp.p[2 + l]  = msgx   + (size_t)l*65536;
        wp.p[6 + l]  = msge   + (size_t)l*65536;
        wp.p[10 + l] = upd_w1 + (size_t)l*65536;
        wp.p[14 + l] = upd_w2 + (size_t)l*65536;
    }
    wfrag_k<<<dim3(16, 18), 256>>>(wp, wt_);
    wfrag64_k<<<4, 256>>>(nin_w1, wt1_);

    // CSR build (by dst)
    cudaMemsetAsync(cur_, 0, NN*sizeof(int));
    hist_k<<<(NE+255)/256, 256>>>(eidx, cur_);
    scan_k<<<1, 1024>>>(cur_, rp_);
    scatter_k<<<(NE+255)/256, 256>>>(eidx, cur_, el_);

    dim3 gg(391, 2);   // ceil(50000/128) x (256/128)

    // node encoder
    geo_k<<<625, 256>>>(x, geo_w, geo_b, d3_);
    gemm_mma<64,false,true,false><<<gg, 256, GEMM_SMEM>>>(
        d3_, wt1_, nullptr, nullptr, nin_b1, nullptr, d1_, NN);
    gemm_mma<256,false,false,false><<<gg, 256, GEMM_SMEM>>>(
        d1_, wt_ + 0*65536, nullptr, nullptr, nin_b2, nullptr, h_, NN);

    // edge encoder scatter
    cudaMemsetAsync(d2_, 0, (size_t)NN*HD*sizeof(float));
    cudaMemsetAsync(deg_, 0, (size_t)NN*sizeof(float));
    edge_encode_k<<<1184, 256>>>(ea, eidx, ee_w1, ee_b1, d2_, deg_);
    gemm_mma<256,false,false,true><<<gg, 256, GEMM_SMEM>>>(
        d2_, wt_ + 1*65536, nullptr, nullptr, ee_b2, deg_, ae_, NN);

    for (int l = 0; l < NL; ++l) {
        // agg = A @ h (gather, no atomics, no memset)
        spmm_gather_k<<<6250, 256>>>(h_, rp_, el_, d1_);
        gemm_mma<256,true,false,false><<<gg, 256, GEMM_SMEM>>>(
            d1_, wt_ + (size_t)(2+l)*65536, ae_, wt_ + (size_t)(6+l)*65536,
            nullptr, nullptr, d2_, NN);
        gemm_mma<256,false,true,false><<<gg, 256, GEMM_SMEM>>>(
            d2_, wt_ + (size_t)(10+l)*65536, nullptr, nullptr,
            upd_b1 + l*256, nullptr, d3_, NN);
        gemm_mma<256,false,false,false><<<gg, 256, GEMM_SMEM>>>(
            d3_, wt_ + (size_t)(14+l)*65536, nullptr, nullptr,
            upd_b2 + l*256, nullptr, d1_, NN);
        ln_k<<<784, 256>>>(h_, d1_, ln_g + l*256, ln_b + l*256);
    }

    cudaMemsetAsync(ps_, 0, 24*HD*sizeof(float));
    cudaMemsetAsync(pc_, 0, 24*sizeof(float));
    pool_k<<<512, 256>>>(h_, batch, ntype, ps_, pc_);
    writeout_k<<<8192, 256>>>(ps_, pc_, h_, batch, out, out_size);
}

// round 7
// speedup vs baseline: 2.1117x; 1.0700x over previous
#include <cuda_runtime.h>
#include <cstdint>

#define NN 50000
#define NE 300000
#define HD 256
#define NB 8
#define NL 4
#define NBK 196   // ceil(NN/256)

// ---------------- scratch (static device globals; no allocs allowed) -------
__device__ float g_h [NN*HD];
__device__ float g_d1[NN*HD];
__device__ float g_d2[NN*HD];
__device__ float g_d3[NN*HD];
__device__ float g_ae[NN*HD];
__device__ float g_deg[NN];
__device__ float g_ps[24*HD];
__device__ float g_pc[24];
__device__ float g_wt[18*65536];   // fragment-permuted tf32 weights, 256-K mats
__device__ float g_wt1[16384];     // fragment-permuted nin_w1 (K=64)
__device__ int   g_rp[NN+1];       // CSR row pointer (by dst)
__device__ int   g_cur[NN];        // counts, then cursors
__device__ int   g_el[NE];         // CSR column (src) list
__device__ int   g_bs[256];        // block sums for scan

// ---------------- helpers ------------------------------------------------
__device__ __forceinline__ float tf32r(float x) {
    float r;
    asm("cvt.rna.tf32.f32 %0, %1;" : "=f"(r) : "f"(x));
    return r;
}
__device__ __forceinline__ void redAdd4(float* p, float4 v) {
    asm volatile("red.global.add.v4.f32 [%0], {%1,%2,%3,%4};"
                 :: "l"(p), "f"(v.x), "f"(v.y), "f"(v.z), "f"(v.w) : "memory");
}
__device__ __forceinline__ uint32_t smem_u32(const void* p) {
    uint32_t a;
    asm("{ .reg .u64 t; cvta.to.shared.u64 t, %1; cvt.u32.u64 %0, t; }"
        : "=r"(a) : "l"(p));
    return a;
}
__device__ __forceinline__ void cp_async16(uint32_t sdst, const void* gsrc) {
    asm volatile("cp.async.ca.shared.global [%0], [%1], 16;"
                 :: "r"(sdst), "l"(gsrc) : "memory");
}
#define CP_COMMIT() asm volatile("cp.async.commit_group;" ::: "memory")
#define CP_WAIT1()  asm volatile("cp.async.wait_group 1;" ::: "memory")

#define MMA_TF32(c, a, b0, b1)                                               \
    asm volatile("mma.sync.aligned.m16n8k8.row.col.f32.tf32.tf32.f32 "      \
        "{%0,%1,%2,%3}, {%4,%5,%6,%7}, {%8,%9}, {%0,%1,%2,%3};"             \
        : "+f"((c)[0]), "+f"((c)[1]), "+f"((c)[2]), "+f"((c)[3])            \
        : "r"((a)[0]), "r"((a)[1]), "r"((a)[2]), "r"((a)[3]),               \
          "r"(b0), "r"(b1))

// ---------------- weight -> fragment-major blocks ---------------------------
struct WPtrs { const float* p[18]; };

__global__ void __launch_bounds__(256) wfrag_k(WPtrs wp, float* __restrict__ out) {
    const float* W = wp.p[blockIdx.y];
    float* O = out + (size_t)blockIdx.y * 65536 + blockIdx.x * 4096;
    const int kc = blockIdx.x >> 1, nb = blockIdx.x & 1;
    const int nl = threadIdx.x >> 1;
    const int khalf = (threadIdx.x & 1) * 16;
    const int n = nb * 128 + nl;
    #pragma unroll
    for (int g = 0; g < 4; ++g) {
        int kk = khalf + g * 4;
        int k = kc * 32 + kk;
        float4 v;
        v.x = tf32r(W[(size_t)(k+0)*256 + n]);
        v.y = tf32r(W[(size_t)(k+1)*256 + n]);
        v.z = tf32r(W[(size_t)(k+2)*256 + n]);
        v.w = tf32r(W[(size_t)(k+3)*256 + n]);
        int idx = ((kk>>3)*8 + (nl>>4))*128
                + ((((nl>>3)&1)<<1) | ((kk>>2)&1))*32 + (nl&7)*4;
        *(float4*)&O[idx] = v;
    }
}

__global__ void __launch_bounds__(256) wfrag64_k(
    const float* __restrict__ W, float* __restrict__ out) {
    float* O = out + blockIdx.x * 4096;
    const int kc = blockIdx.x >> 1, nb = blockIdx.x & 1;
    const int nl = threadIdx.x >> 1;
    const int khalf = (threadIdx.x & 1) * 16;
    const int n = nb * 128 + nl;
    #pragma unroll
    for (int g = 0; g < 4; ++g) {
        int kk = khalf + g * 4;
        int k = kc * 32 + kk;
        float4 v;
        v.x = tf32r(W[(size_t)(k+0)*256 + n]);
        v.y = tf32r(W[(size_t)(k+1)*256 + n]);
        v.z = tf32r(W[(size_t)(k+2)*256 + n]);
        v.w = tf32r(W[(size_t)(k+3)*256 + n]);
        int idx = ((kk>>3)*8 + (nl>>4))*128
                + ((((nl>>3)&1)<<1) | ((kk>>2)&1))*32 + (nl&7)*4;
        *(float4*)&O[idx] = v;
    }
}

// ---------------- tensor-core GEMM via mma.sync tf32 ------------------------
#define GEMM_SMEM 98304

template<int KROW, bool DUAL, bool RELU, bool ROWSCALE>
__global__ void __launch_bounds__(256, 2) gemm_mma(
    const float* __restrict__ A,  const float* __restrict__ Wf,
    const float* __restrict__ A2, const float* __restrict__ Wf2,
    const float* __restrict__ bias, const float* __restrict__ rowscale,
    float* __restrict__ C, int M)
{
    extern __shared__ float smf[];   // stage s: A at s*8192, B at s*8192+4096
    const uint32_t sbase = smem_u32(smf);

    const int tid = threadIdx.x;
    const int wid = tid >> 5, lane = tid & 31;
    const int warp_m = wid & 1, warp_n = wid >> 1;   // 2M x 4N
    const int bm = blockIdx.x * 128;
    const int nb = blockIdx.y;

    const int a_row = tid >> 1;
    const int a_half = tid & 1;
    const int arow = bm + a_row;
    const int a_sw = a_row & 7;

    float acc[4][4][4];
    #pragma unroll
    for (int t = 0; t < 4; ++t)
        #pragma unroll
        for (int j = 0; j < 4; ++j)
            #pragma unroll
            for (int q = 0; q < 4; ++q) acc[t][j][q] = 0.f;

    const int KC = KROW / 32;
    const int NCHUNK = (DUAL ? 2 : 1) * KC;

    auto cpA = [&](int c, int s) {
        const float* Ap = (DUAL && c >= KC) ? A2 : A;
        int k0 = ((DUAL && c >= KC) ? (c - KC) : c) * 32;
        if (arow < M) {
            const float* src = Ap + (size_t)arow * KROW + k0 + a_half * 16;
            uint32_t drow = sbase + s * 32768 + a_row * 128;
            #pragma unroll
            for (int j = 0; j < 4; ++j) {
                int chunk = a_half * 4 + j;
                cp_async16(drow + ((chunk ^ a_sw) << 4), src + j * 4);
            }
        } else {
            float* drow = smf + s * 8192 + a_row * 32;
            #pragma unroll
            for (int j = 0; j < 4; ++j) {
                int chunk = a_half * 4 + j;
                *(float4*)(drow + ((chunk ^ a_sw) << 2)) =
                    make_float4(0.f, 0.f, 0.f, 0.f);
            }
        }
    };
    auto cpB = [&](int c, int s) {
        const float* Wp = (DUAL && c >= KC) ? Wf2 : Wf;
        int cc = (DUAL && c >= KC) ? (c - KC) : c;
        const float* src = Wp + ((size_t)cc * 2 + nb) * 4096 + tid * 16;
        uint32_t dst = sbase + s * 32768 + 16384 + tid * 64;
        #pragma unroll
        for (int i = 0; i < 4; ++i)
            cp_async16(dst + i * 16, src + i * 4);
    };
    auto compute_ks = [&](int s, int ks) {
        const float* a = smf + s * 8192;
        const float* b = smf + s * 8192 + 4096;
        const int lr = lane >> 2, lc = lane & 3;
        uint32_t av[4][4], bv[2][4];
        #pragma unroll
        for (int t = 0; t < 4; ++t) {
            int m0 = warp_m * 64 + t * 16 + lr;
            #pragma unroll
            for (int i = 0; i < 4; ++i) {
                int row = m0 + (i & 1) * 8;
                int chunk = 2 * ks + (i >> 1);
                float v = a[row * 32 + ((chunk ^ lr) << 2) + lc];
                av[t][i] = __float_as_uint(tf32r(v));
            }
        }
        #pragma unroll
        for (int p = 0; p < 2; ++p) {
            int base = (ks * 8 + warp_n * 2 + p) * 128 + lane;
            bv[p][0] = __float_as_uint(b[base]);
            bv[p][1] = __float_as_uint(b[base + 32]);
            bv[p][2] = __float_as_uint(b[base + 64]);
            bv[p][3] = __float_as_uint(b[base + 96]);
        }
        #pragma unroll
        for (int t = 0; t < 4; ++t)
            #pragma unroll
            for (int j = 0; j < 4; ++j) {
                int p = j >> 1, half = j & 1;
                MMA_TF32(acc[t][j], av[t], bv[p][half * 2], bv[p][half * 2 + 1]);
            }
    };

    #pragma unroll
    for (int s = 0; s < 2; ++s) {
        if (s < NCHUNK) { cpA(s, s); cpB(s, s); }
        CP_COMMIT();
    }
    for (int c = 0; c < NCHUNK; ++c) {
        CP_WAIT1();
        __syncthreads();
        int sl = c + 2;
        if (sl < NCHUNK) { cpA(sl, sl % 3); cpB(sl, sl % 3); }
        CP_COMMIT();
        int s = c % 3;
        compute_ks(s, 0);
        compute_ks(s, 1);
        compute_ks(s, 2);
        compute_ks(s, 3);
    }

    // ---- epilogue ----
    const int row_base = bm + warp_m * 64 + (lane >> 2);
    const int col_base = nb * 128 + warp_n * 32 + (lane & 3) * 2;
    #pragma unroll
    for (int t = 0; t < 4; ++t) {
        int r0 = row_base + t * 16;
        int r1 = r0 + 8;
        float s0 = 1.f, s1 = 1.f;
        if (ROWSCALE) {
            s0 = (r0 < M) ? rowscale[r0] : 0.f;
            s1 = (r1 < M) ? rowscale[r1] : 0.f;
        }
        #pragma unroll
        for (int j = 0; j < 4; ++j) {
            int col = col_base + j * 8;
            float bb0 = 0.f, bb1 = 0.f;
            if (bias) { bb0 = __ldg(bias + col); bb1 = __ldg(bias + col + 1); }
            float v00 = acc[t][j][0] + bb0 * s0;
            float v01 = acc[t][j][1] + bb1 * s0;
            float v10 = acc[t][j][2] + bb0 * s1;
            float v11 = acc[t][j][3] + bb1 * s1;
            if (RELU) {
                v00 = fmaxf(v00, 0.f); v01 = fmaxf(v01, 0.f);
                v10 = fmaxf(v10, 0.f); v11 = fmaxf(v11, 0.f);
            }
            if (r0 < M) *(float2*)(C + (size_t)r0 * 256 + col) = make_float2(v00, v01);
            if (r1 < M) *(float2*)(C + (size_t)r1 * 256 + col) = make_float2(v10, v11);
        }
    }
}

// ---------------- CSR build (by dst) -----------------------------------------
__global__ void __launch_bounds__(256) hist_k(
    const int* __restrict__ eidx, int* __restrict__ cnt) {
    int i = blockIdx.x * blockDim.x + threadIdx.x;
    if (i < NE) atomicAdd(&cnt[eidx[NE + i]], 1);
}

// phase 1: per-block sums of cnt
__global__ void __launch_bounds__(256) scan1_k(
    const int* __restrict__ cnt, int* __restrict__ bs) {
    __shared__ int sm[256];
    int i = blockIdx.x * 256 + threadIdx.x;
    sm[threadIdx.x] = (i < NN) ? cnt[i] : 0;
    __syncthreads();
    #pragma unroll
    for (int o = 128; o > 0; o >>= 1) {
        if (threadIdx.x < o) sm[threadIdx.x] += sm[threadIdx.x + o];
        __syncthreads();
    }
    if (threadIdx.x == 0) bs[blockIdx.x] = sm[0];
}

// phase 2: exclusive scan of block sums (1 block)
__global__ void __launch_bounds__(256) scan2_k(
    int* __restrict__ bs, int* __restrict__ rp) {
    __shared__ int sm[256];
    int t = threadIdx.x;
    int v = (t < NBK) ? bs[t] : 0;
    sm[t] = v;
    __syncthreads();
    #pragma unroll
    for (int o = 1; o < 256; o <<= 1) {
        int u = (t >= o) ? sm[t - o] : 0;
        __syncthreads();
        sm[t] += u;
        __syncthreads();
    }
    if (t < NBK) bs[t] = sm[t] - v;        // exclusive block offset
    if (t == NBK - 1) rp[NN] = sm[t];      // total
}

// phase 3: local exclusive scan + block offset -> rp, cur
__global__ void __launch_bounds__(256) scan3_k(
    const int* __restrict__ bs, int* __restrict__ rp, int* __restrict__ cur) {
    __shared__ int sm[256];
    int i = blockIdx.x * 256 + threadIdx.x;
    int v = (i < NN) ? cur[i] : 0;
    sm[threadIdx.x] = v;
    __syncthreads();
    #pragma unroll
    for (int o = 1; o < 256; o <<= 1) {
        int u = (threadIdx.x >= o) ? sm[threadIdx.x - o] : 0;
        __syncthreads();
        sm[threadIdx.x] += u;
        __syncthreads();
    }
    if (i < NN) {
        int off = bs[blockIdx.x] + sm[threadIdx.x] - v;
        rp[i] = off;
        cur[i] = off;
    }
}

__global__ void __launch_bounds__(256) scatter_k(
    const int* __restrict__ eidx, int* __restrict__ cur, int* __restrict__ el) {
    int e = blockIdx.x * blockDim.x + threadIdx.x;
    if (e < NE) {
        int pos = atomicAdd(&cur[eidx[NE + e]], 1);
        el[pos] = eidx[e];
    }
}

// ---------------- SpMM gather: agg[n] = sum_{e in-edges(n)} h[src(e)] --------
__global__ void __launch_bounds__(256) spmm_gather_k(
    const float* __restrict__ h, const int* __restrict__ rp,
    const int* __restrict__ el, float* __restrict__ agg)
{
    int n = (blockIdx.x * 256 + threadIdx.x) >> 5;
    if (n >= NN) return;
    const int lane = threadIdx.x & 31;
    const int c = lane * 8;
    int s = rp[n], e = rp[n + 1];
    float4 a0 = make_float4(0.f,0.f,0.f,0.f);
    float4 a1 = make_float4(0.f,0.f,0.f,0.f);
    int i = s;
    for (; i + 1 < e; i += 2) {
        const float* hp0 = h + (size_t)el[i] * 256 + c;
        const float* hp1 = h + (size_t)el[i + 1] * 256 + c;
        float4 v0 = *(const float4*)hp0;
        float4 v1 = *(const float4*)(hp0 + 4);
        float4 w0 = *(const float4*)hp1;
        float4 w1 = *(const float4*)(hp1 + 4);
        a0.x += v0.x + w0.x; a0.y += v0.y + w0.y;
        a0.z += v0.z + w0.z; a0.w += v0.w + w0.w;
        a1.x += v1.x + w1.x; a1.y += v1.y + w1.y;
        a1.z += v1.z + w1.z; a1.w += v1.w + w1.w;
    }
    if (i < e) {
        const float* hp = h + (size_t)el[i] * 256 + c;
        float4 v0 = *(const float4*)hp;
        float4 v1 = *(const float4*)(hp + 4);
        a0.x += v0.x; a0.y += v0.y; a0.z += v0.z; a0.w += v0.w;
        a1.x += v1.x; a1.y += v1.y; a1.z += v1.z; a1.w += v1.w;
    }
    float* ap = agg + (size_t)n * 256 + c;
    *(float4*)ap       = a0;
    *(float4*)(ap + 4) = a1;
}

// ---------------- geo stage ---------------------------------------------------
__global__ void __launch_bounds__(256) geo_k(
    const float* __restrict__ x,
    const float* __restrict__ geo_w, const float* __restrict__ geo_b,
    float* __restrict__ out)   // [NN, 64]
{
    __shared__ float gws[4096];
    __shared__ float gbs[32];
    for (int i = threadIdx.x; i < 4096; i += 256) gws[i] = geo_w[i];
    if (threadIdx.x < 32) gbs[threadIdx.x] = geo_b[threadIdx.x];
    __syncthreads();
    const int warp = threadIdx.x >> 5, lane = threadIdx.x & 31;
    for (int n0 = blockIdx.x * 8; n0 < NN; n0 += gridDim.x * 8) {
        int n = n0 + warp;
        if (n < NN) {
            const float* xr = x + (size_t)n * 160;
            float s = gbs[lane];
            #pragma unroll
            for (int k = 0; k < 128; ++k) s += __ldg(xr + k) * gws[k * 32 + lane];
            out[(size_t)n * 64 + lane]      = fmaxf(s, 0.f);
            out[(size_t)n * 64 + 32 + lane] = __ldg(xr + 128 + lane);
        }
    }
}

// ---------------- edge encoder + scatter (8 edges per sync pair) -------------
__global__ void __launch_bounds__(256) edge_encode_k(
    const float* __restrict__ ea, const int* __restrict__ eidx,
    const float* __restrict__ w1, const float* __restrict__ b1,
    float* __restrict__ At, float* __restrict__ deg)
{
    const int tid = threadIdx.x;
    const int c0 = (tid & 63) * 4;
    const int slot = tid >> 6;
    float4 wreg[16];
    #pragma unroll
    for (int k = 0; k < 16; ++k)
        wreg[k] = *(const float4*)(w1 + k * 256 + c0);
    const float4 b1v = *(const float4*)(b1 + c0);

    __shared__ float eav[8][16];
    __shared__ int dsts[8];

    for (int base = blockIdx.x * 8; base < NE; base += gridDim.x * 8) {
        if (tid < 128) ((float*)eav)[tid] = ea[(size_t)base * 16 + tid];
        if (tid < 8) dsts[tid] = eidx[NE + base + tid];
        __syncthreads();
        #pragma unroll
        for (int g = 0; g < 2; ++g) {
            const int e = slot + g * 4;
            float4 acc = b1v;
            #pragma unroll
            for (int k = 0; k < 16; ++k) {
                float ev = eav[e][k];
                acc.x += wreg[k].x * ev;
                acc.y += wreg[k].y * ev;
                acc.z += wreg[k].z * ev;
                acc.w += wreg[k].w * ev;
            }
            acc.x = fmaxf(acc.x, 0.f); acc.y = fmaxf(acc.y, 0.f);
            acc.z = fmaxf(acc.z, 0.f); acc.w = fmaxf(acc.w, 0.f);
            int dst = dsts[e];
            redAdd4(At + (size_t)dst * 256 + c0, acc);
            if ((tid & 63) == 0) atomicAdd(deg + dst, 1.f);
        }
        __syncthreads();
    }
}

// ---------------- residual + layernorm (warp per row) -----------------------
__global__ void __launch_bounds__(256) ln_k(
    float* __restrict__ h, const float* __restrict__ u,
    const float* __restrict__ g, const float* __restrict__ b)
{
    int gw = (blockIdx.x*blockDim.x + threadIdx.x) >> 5;
    int lane = threadIdx.x & 31;
    int nw = (gridDim.x*blockDim.x) >> 5;
    for (int n = gw; n < NN; n += nw) {
        float* hp = h + (size_t)n*256;
        const float* up = u + (size_t)n*256;
        float v[8];
        float4 h0 = *(float4*)(hp + lane*8),       h1 = *(float4*)(hp + lane*8 + 4);
        float4 u0 = *(const float4*)(up + lane*8), u1 = *(const float4*)(up + lane*8 + 4);
        v[0]=h0.x+u0.x; v[1]=h0.y+u0.y; v[2]=h0.z+u0.z; v[3]=h0.w+u0.w;
        v[4]=h1.x+u1.x; v[5]=h1.y+u1.y; v[6]=h1.z+u1.z; v[7]=h1.w+u1.w;
        float s = 0.f;
        #pragma unroll
        for (int i = 0; i < 8; ++i) s += v[i];
        #pragma unroll
        for (int o = 16; o > 0; o >>= 1) s += __shfl_xor_sync(0xffffffffu, s, o);
        float mu = s * (1.f/256.f);
        float qq = 0.f;
        #pragma unroll
        for (int i = 0; i < 8; ++i) { float d = v[i]-mu; qq += d*d; }
        #pragma unroll
        for (int o = 16; o > 0; o >>= 1) qq += __shfl_xor_sync(0xffffffffu, qq, o);
        float rstd = rsqrtf(qq*(1.f/256.f) + 1e-5f);
        #pragma unroll
        for (int i = 0; i < 8; ++i) {
            int c = lane*8 + i;
            v[i] = (v[i]-mu)*rstd*__ldg(g+c) + __ldg(b+c);
        }
        *(float4*)(hp + lane*8)     = make_float4(v[0],v[1],v[2],v[3]);
        *(float4*)(hp + lane*8 + 4) = make_float4(v[4],v[5],v[6],v[7]);
    }
}

// ---------------- typed mean-pool partial sums -------------------------------
__global__ void __launch_bounds__(256) pool_k(
    const float* __restrict__ h, const int* __restrict__ batch,
    const int* __restrict__ ntype, float* __restrict__ ps, float* __restrict__ pc)
{
    __shared__ float acc[24][256];
    __shared__ float cnt[24];
    for (int i = threadIdx.x; i < 24*256; i += 256) (&acc[0][0])[i] = 0.f;
    if (threadIdx.x < 24) cnt[threadIdx.x] = 0.f;
    __syncthreads();
    int per = (NN + gridDim.x - 1) / gridDim.x;
    int start = blockIdx.x * per;
    int end = start + per; if (end > NN) end = NN;
    for (int n = start; n < end; ++n) {
        int idx = __ldg(ntype+n)*8 + __ldg(batch+n);
        acc[idx][threadIdx.x] += h[(size_t)n*256 + threadIdx.x];
        if (threadIdx.x == 0) cnt[idx] += 1.f;
    }
    __syncthreads();
    for (int i = threadIdx.x; i < 24*256; i += 256) atomicAdd(&ps[i], (&acc[0][0])[i]);
    if (threadIdx.x < 24) atomicAdd(&pc[threadIdx.x], cnt[threadIdx.x]);
}

// ---------------- final write: z | h | batch ---------------------------------
__global__ void __launch_bounds__(256) writeout_k(
    const float* __restrict__ ps, const float* __restrict__ pc,
    const float* __restrict__ h, const int* __restrict__ batch,
    float* __restrict__ out, int out_size)
{
    const int total = 24*256 + NN*HD + NN;
    for (int i = blockIdx.x*blockDim.x + threadIdx.x; i < total;
         i += gridDim.x*blockDim.x) {
        float v; int o;
        if (i < 6144) {
            int c = i & 255, kb = i >> 8, k = kb >> 3, bb = kb & 7;
            float cc = pc[kb]; if (cc < 1.f) cc = 1.f;
            v = ps[i] / cc;
            o = bb*768 + k*256 + c;
        } else if (i < 6144 + NN*HD) {
            v = h[i - 6144]; o = i;
        } else {
            v = (float)batch[i - 6144 - NN*HD]; o = i;
        }
        if (o < out_size) out[o] = v;
    }
}

// ---------------- launcher ----------------------------------------------------
extern "C" void kernel_launch(void* const* d_in, const int* in_sizes, int n_in,
                              void* d_out, int out_size)
{
    const float* x       = (const float*)d_in[0];
    const float* ea      = (const float*)d_in[1];
    const float* geo_w   = (const float*)d_in[2];
    const float* geo_b   = (const float*)d_in[3];
    const float* nin_w1  = (const float*)d_in[4];
    const float* nin_b1  = (const float*)d_in[5];
    const float* nin_w2  = (const float*)d_in[6];
    const float* nin_b2  = (const float*)d_in[7];
    const float* ee_w1   = (const float*)d_in[8];
    const float* ee_b1   = (const float*)d_in[9];
    const float* ee_w2   = (const float*)d_in[10];
    const float* ee_b2   = (const float*)d_in[11];
    const float* msgx    = (const float*)d_in[12];
    const float* msge    = (const float*)d_in[13];
    const float* upd_w1  = (const float*)d_in[14];
    const float* upd_b1  = (const float*)d_in[15];
    const float* upd_w2  = (const float*)d_in[16];
    const float* upd_b2  = (const float*)d_in[17];
    const float* ln_g    = (const float*)d_in[18];
    const float* ln_b    = (const float*)d_in[19];
    const int*   eidx    = (const int*)d_in[20];
    const int*   batch   = (const int*)d_in[21];
    const int*   ntype   = (const int*)d_in[22];
    float* out = (float*)d_out;

    float *h_, *d1_, *d2_, *d3_, *ae_, *deg_, *ps_, *pc_, *wt_, *wt1_;
    int *rp_, *cur_, *el_, *bs_;
    cudaGetSymbolAddress((void**)&h_,  g_h);
    cudaGetSymbolAddress((void**)&d1_, g_d1);
    cudaGetSymbolAddress((void**)&d2_, g_d2);
    cudaGetSymbolAddress((void**)&d3_, g_d3);
    cudaGetSymbolAddress((void**)&ae_, g_ae);
    cudaGetSymbolAddress((void**)&deg_, g_deg);
    cudaGetSymbolAddress((void**)&ps_, g_ps);
    cudaGetSymbolAddress((void**)&pc_, g_pc);
    cudaGetSymbolAddress((void**)&wt_, g_wt);
    cudaGetSymbolAddress((void**)&wt1_, g_wt1);
    cudaGetSymbolAddress((void**)&rp_, g_rp);
    cudaGetSymbolAddress((void**)&cur_, g_cur);
    cudaGetSymbolAddress((void**)&el_, g_el);
    cudaGetSymbolAddress((void**)&bs_, g_bs);

    cudaFuncSetAttribute(gemm_mma<256,false,false,false>,
        cudaFuncAttributeMaxDynamicSharedMemorySize, GEMM_SMEM);
    cudaFuncSetAttribute(gemm_mma<256,false,false,true>,
        cudaFuncAttributeMaxDynamicSharedMemorySize, GEMM_SMEM);
    cudaFuncSetAttribute(gemm_mma<256,true,false,false>,
        cudaFuncAttributeMaxDynamicSharedMemorySize, GEMM_SMEM);
    cudaFuncSetAttribute(gemm_mma<256,false,true,false>,
        cudaFuncAttributeMaxDynamicSharedMemorySize, GEMM_SMEM);
    cudaFuncSetAttribute(gemm_mma<64,false,true,false>,
        cudaFuncAttributeMaxDynamicSharedMemorySize, GEMM_SMEM);

    WPtrs wp;
    wp.p[0] = nin_w2; wp.p[1] = ee_w2;
    for (int l = 0; l < 4; ++l) {
        wp.p[2 + l]  = msgx   + (size_t)l*65536;
        wp.p[6 + l]  = msge   + (size_t)l*65536;
        wp.p[10 + l] = upd_w1 + (size_t)l*65536;
        wp.p[14 + l] = upd_w2 + (size_t)l*65536;
    }
    wfrag_k<<<dim3(16, 18), 256>>>(wp, wt_);
    wfrag64_k<<<4, 256>>>(nin_w1, wt1_);

    // CSR build (by dst) — parallel 3-phase scan
    cudaMemsetAsync(cur_, 0, NN*sizeof(int));
    hist_k<<<(NE+255)/256, 256>>>(eidx, cur_);
    scan1_k<<<NBK, 256>>>(cur_, bs_);
    scan2_k<<<1, 256>>>(bs_, rp_);
    scan3_k<<<NBK, 256>>>(bs_, rp_, cur_);
    scatter_k<<<(NE+255)/256, 256>>>(eidx, cur_, el_);

    dim3 gg(391, 2);   // ceil(50000/128) x (256/128)

    // node encoder
    geo_k<<<625, 256>>>(x, geo_w, geo_b, d3_);
    gemm_mma<64,false,true,false><<<gg, 256, GEMM_SMEM>>>(
        d3_, wt1_, nullptr, nullptr, nin_b1, nullptr, d1_, NN);
    gemm_mma<256,false,false,false><<<gg, 256, GEMM_SMEM>>>(
        d1_, wt_ + 0*65536, nullptr, nullptr, nin_b2, nullptr, h_, NN);

    // edge encoder scatter
    cudaMemsetAsync(d2_, 0, (size_t)NN*HD*sizeof(float));
    cudaMemsetAsync(deg_, 0, (size_t)NN*sizeof(float));
    edge_encode_k<<<1184, 256>>>(ea, eidx, ee_w1, ee_b1, d2_, deg_);
    gemm_mma<256,false,false,true><<<gg, 256, GEMM_SMEM>>>(
        d2_, wt_ + 1*65536, nullptr, nullptr, ee_b2, deg_, ae_, NN);

    for (int l = 0; l < NL; ++l) {
        spmm_gather_k<<<6250, 256>>>(h_, rp_, el_, d1_);
        gemm_mma<256,true,false,false><<<gg, 256, GEMM_SMEM>>>(
            d1_, wt_ + (size_t)(2+l)*65536, ae_, wt_ + (size_t)(6+l)*65536,
            nullptr, nullptr, d2_, NN);
        gemm_mma<256,false,true,false><<<gg, 256, GEMM_SMEM>>>(
            d2_, wt_ + (size_t)(10+l)*65536, nullptr, nullptr,
            upd_b1 + l*256, nullptr, d3_, NN);
        gemm_mma<256,false,false,false><<<gg, 256, GEMM_SMEM>>>(
            d3_, wt_ + (size_t)(14+l)*65536, nullptr, nullptr,
            upd_b2 + l*256, nullptr, d1_, NN);
        ln_k<<<784, 256>>>(h_, d1_, ln_g + l*256, ln_b + l*256);
    }

    cudaMemsetAsync(ps_, 0, 24*HD*sizeof(float));
    cudaMemsetAsync(pc_, 0, 24*sizeof(float));
    pool_k<<<512, 256>>>(h_, batch, ntype, ps_, pc_);
    writeout_k<<<8192, 256>>>(ps_, pc_, h_, batch, out, out_size);
}

// round 8
// speedup vs baseline: 2.4866x; 1.1775x over previous
#include <cuda_runtime.h>
#include <cstdint>

#define NN 50000
#define NE 300000
#define HD 256
#define NB 8
#define NL 4
#define NBK 196   // ceil(NN/256)

// ---------------- scratch (static device globals; no allocs allowed) -------
__device__ float g_h [NN*HD];
__device__ float g_d1[NN*HD];
__device__ float g_d2[NN*HD];
__device__ float g_d3[NN*HD];
__device__ float g_ae[NN*HD];
__device__ float g_deg[NN];
__device__ float g_ps[24*HD];
__device__ float g_pc[24];
__device__ float g_wt[18*65536];   // fragment-permuted tf32 weights
__device__ float g_wt1[16384];     // fragment-permuted nin_w1 (K=64)
__device__ int   g_rp[NN+1];       // CSR row pointer (by dst)
__device__ int   g_cur[NN];        // counts, then cursors
__device__ int   g_el[NE];         // CSR column (src) list
__device__ int   g_bs[256];        // block sums for scan

// ---------------- helpers ------------------------------------------------
__device__ __forceinline__ float tf32r(float x) {
    float r;
    asm("cvt.rna.tf32.f32 %0, %1;" : "=f"(r) : "f"(x));
    return r;
}
__device__ __forceinline__ void redAdd4(float* p, float4 v) {
    asm volatile("red.global.add.v4.f32 [%0], {%1,%2,%3,%4};"
                 :: "l"(p), "f"(v.x), "f"(v.y), "f"(v.z), "f"(v.w) : "memory");
}
__device__ __forceinline__ uint32_t smem_u32(const void* p) {
    uint32_t a;
    asm("{ .reg .u64 t; cvta.to.shared.u64 t, %1; cvt.u32.u64 %0, t; }"
        : "=r"(a) : "l"(p));
    return a;
}
__device__ __forceinline__ void cp_async16(uint32_t sdst, const void* gsrc) {
    asm volatile("cp.async.ca.shared.global [%0], [%1], 16;"
                 :: "r"(sdst), "l"(gsrc) : "memory");
}
#define CP_COMMIT() asm volatile("cp.async.commit_group;" ::: "memory")
#define CP_WAIT1()  asm volatile("cp.async.wait_group 1;" ::: "memory")

#define MMA_TF32(c, a, b0, b1)                                               \
    asm volatile("mma.sync.aligned.m16n8k8.row.col.f32.tf32.tf32.f32 "      \
        "{%0,%1,%2,%3}, {%4,%5,%6,%7}, {%8,%9}, {%0,%1,%2,%3};"             \
        : "+f"((c)[0]), "+f"((c)[1]), "+f"((c)[2]), "+f"((c)[3])            \
        : "r"((a)[0]), "r"((a)[1]), "r"((a)[2]), "r"((a)[3]),               \
          "r"(b0), "r"(b1))

// ---------------- weight -> fragment-major blocks ---------------------------
struct WPtrs { const float* p[18]; };

__global__ void __launch_bounds__(256) wfrag_k(WPtrs wp, float* __restrict__ out) {
    const float* W = wp.p[blockIdx.y];
    float* O = out + (size_t)blockIdx.y * 65536 + blockIdx.x * 4096;
    const int kc = blockIdx.x >> 1, nb = blockIdx.x & 1;
    const int nl = threadIdx.x >> 1;
    const int khalf = (threadIdx.x & 1) * 16;
    const int n = nb * 128 + nl;
    #pragma unroll
    for (int g = 0; g < 4; ++g) {
        int kk = khalf + g * 4;
        int k = kc * 32 + kk;
        float4 v;
        v.x = tf32r(W[(size_t)(k+0)*256 + n]);
        v.y = tf32r(W[(size_t)(k+1)*256 + n]);
        v.z = tf32r(W[(size_t)(k+2)*256 + n]);
        v.w = tf32r(W[(size_t)(k+3)*256 + n]);
        int idx = ((kk>>3)*8 + (nl>>4))*128
                + ((((nl>>3)&1)<<1) | ((kk>>2)&1))*32 + (nl&7)*4;
        *(float4*)&O[idx] = v;
    }
}

__global__ void __launch_bounds__(256) wfrag64_k(
    const float* __restrict__ W, float* __restrict__ out) {
    float* O = out + blockIdx.x * 4096;
    const int kc = blockIdx.x >> 1, nb = blockIdx.x & 1;
    const int nl = threadIdx.x >> 1;
    const int khalf = (threadIdx.x & 1) * 16;
    const int n = nb * 128 + nl;
    #pragma unroll
    for (int g = 0; g < 4; ++g) {
        int kk = khalf + g * 4;
        int k = kc * 32 + kk;
        float4 v;
        v.x = tf32r(W[(size_t)(k+0)*256 + n]);
        v.y = tf32r(W[(size_t)(k+1)*256 + n]);
        v.z = tf32r(W[(size_t)(k+2)*256 + n]);
        v.w = tf32r(W[(size_t)(k+3)*256 + n]);
        int idx = ((kk>>3)*8 + (nl>>4))*128
                + ((((nl>>3)&1)<<1) | ((kk>>2)&1))*32 + (nl&7)*4;
        *(float4*)&O[idx] = v;
    }
}

// ---------------- tensor-core GEMM body (tf32 mma.sync) ---------------------
#define GEMM_SMEM 98304

template<int KROW, bool DUAL, bool RELU, bool ROWSCALE>
__device__ __forceinline__ void gemm_body(
    const float* __restrict__ A,  const float* __restrict__ Wf,
    const float* __restrict__ A2, const float* __restrict__ Wf2,
    const float* __restrict__ bias, const float* __restrict__ rowscale,
    float* __restrict__ C, int M, int bmblk, int nb, float* smf)
{
    const uint32_t sbase = smem_u32(smf);
    const int tid = threadIdx.x;
    const int wid = tid >> 5, lane = tid & 31;
    const int warp_m = wid & 1, warp_n = wid >> 1;   // 2M x 4N
    const int bm = bmblk * 128;

    const int a_row = tid >> 1;
    const int a_half = tid & 1;
    const int arow = bm + a_row;
    const int a_sw = a_row & 7;

    float acc[4][4][4];
    #pragma unroll
    for (int t = 0; t < 4; ++t)
        #pragma unroll
        for (int j = 0; j < 4; ++j)
            #pragma unroll
            for (int q = 0; q < 4; ++q) acc[t][j][q] = 0.f;

    const int KC = KROW / 32;
    const int NCHUNK = (DUAL ? 2 : 1) * KC;

    auto cpA = [&](int c, int s) {
        const float* Ap = (DUAL && c >= KC) ? A2 : A;
        int k0 = ((DUAL && c >= KC) ? (c - KC) : c) * 32;
        if (arow < M) {
            const float* src = Ap + (size_t)arow * KROW + k0 + a_half * 16;
            uint32_t drow = sbase + s * 32768 + a_row * 128;
            #pragma unroll
            for (int j = 0; j < 4; ++j) {
                int chunk = a_half * 4 + j;
                cp_async16(drow + ((chunk ^ a_sw) << 4), src + j * 4);
            }
        } else {
            float* drow = smf + s * 8192 + a_row * 32;
            #pragma unroll
            for (int j = 0; j < 4; ++j) {
                int chunk = a_half * 4 + j;
                *(float4*)(drow + ((chunk ^ a_sw) << 2)) =
                    make_float4(0.f, 0.f, 0.f, 0.f);
            }
        }
    };
    auto cpB = [&](int c, int s) {
        const float* Wp = (DUAL && c >= KC) ? Wf2 : Wf;
        int cc = (DUAL && c >= KC) ? (c - KC) : c;
        const float* src = Wp + ((size_t)cc * 2 + nb) * 4096 + tid * 16;
        uint32_t dst = sbase + s * 32768 + 16384 + tid * 64;
        #pragma unroll
        for (int i = 0; i < 4; ++i)
            cp_async16(dst + i * 16, src + i * 4);
    };
    auto compute_ks = [&](int s, int ks) {
        const float* a = smf + s * 8192;
        const float* b = smf + s * 8192 + 4096;
        const int lr = lane >> 2, lc = lane & 3;
        uint32_t av[4][4], bv[2][4];
        #pragma unroll
        for (int t = 0; t < 4; ++t) {
            int m0 = warp_m * 64 + t * 16 + lr;
            #pragma unroll
            for (int i = 0; i < 4; ++i) {
                int row = m0 + (i & 1) * 8;
                int chunk = 2 * ks + (i >> 1);
                float v = a[row * 32 + ((chunk ^ lr) << 2) + lc];
                av[t][i] = __float_as_uint(tf32r(v));
            }
        }
        #pragma unroll
        for (int p = 0; p < 2; ++p) {
            int base = (ks * 8 + warp_n * 2 + p) * 128 + lane;
            bv[p][0] = __float_as_uint(b[base]);
            bv[p][1] = __float_as_uint(b[base + 32]);
            bv[p][2] = __float_as_uint(b[base + 64]);
            bv[p][3] = __float_as_uint(b[base + 96]);
        }
        #pragma unroll
        for (int t = 0; t < 4; ++t)
            #pragma unroll
            for (int j = 0; j < 4; ++j) {
                int p = j >> 1, half = j & 1;
                MMA_TF32(acc[t][j], av[t], bv[p][half * 2], bv[p][half * 2 + 1]);
            }
    };

    #pragma unroll
    for (int s = 0; s < 2; ++s) {
        if (s < NCHUNK) { cpA(s, s); cpB(s, s); }
        CP_COMMIT();
    }
    for (int c = 0; c < NCHUNK; ++c) {
        CP_WAIT1();
        __syncthreads();
        int sl = c + 2;
        if (sl < NCHUNK) { cpA(sl, sl % 3); cpB(sl, sl % 3); }
        CP_COMMIT();
        int s = c % 3;
        compute_ks(s, 0);
        compute_ks(s, 1);
        compute_ks(s, 2);
        compute_ks(s, 3);
    }

    // ---- epilogue ----
    const int row_base = bm + warp_m * 64 + (lane >> 2);
    const int col_base = nb * 128 + warp_n * 32 + (lane & 3) * 2;
    #pragma unroll
    for (int t = 0; t < 4; ++t) {
        int r0 = row_base + t * 16;
        int r1 = r0 + 8;
        float s0 = 1.f, s1 = 1.f;
        if (ROWSCALE) {
            s0 = (r0 < M) ? rowscale[r0] : 0.f;
            s1 = (r1 < M) ? rowscale[r1] : 0.f;
        }
        #pragma unroll
        for (int j = 0; j < 4; ++j) {
            int col = col_base + j * 8;
            float bb0 = 0.f, bb1 = 0.f;
            if (bias) { bb0 = __ldg(bias + col); bb1 = __ldg(bias + col + 1); }
            float v00 = acc[t][j][0] + bb0 * s0;
            float v01 = acc[t][j][1] + bb1 * s0;
            float v10 = acc[t][j][2] + bb0 * s1;
            float v11 = acc[t][j][3] + bb1 * s1;
            if (RELU) {
                v00 = fmaxf(v00, 0.f); v01 = fmaxf(v01, 0.f);
                v10 = fmaxf(v10, 0.f); v11 = fmaxf(v11, 0.f);
            }
            if (r0 < M) *(float2*)(C + (size_t)r0 * 256 + col) = make_float2(v00, v01);
            if (r1 < M) *(float2*)(C + (size_t)r1 * 256 + col) = make_float2(v10, v11);
        }
    }
}

template<int KROW, bool DUAL, bool RELU, bool ROWSCALE>
__global__ void __launch_bounds__(256, 2) gemm_mma(
    const float* __restrict__ A,  const float* __restrict__ Wf,
    const float* __restrict__ A2, const float* __restrict__ Wf2,
    const float* __restrict__ bias, const float* __restrict__ rowscale,
    float* __restrict__ C, int M)
{
    extern __shared__ float smf[];
    gemm_body<KROW,DUAL,RELU,ROWSCALE>(A, Wf, A2, Wf2, bias, rowscale,
                                       C, M, blockIdx.x, blockIdx.y, smf);
}

// batched 256x256x256: tmp[z] = A[z] @ Wf[slot 14 + (z&3)]
struct MMPtrs { const float* a[8]; };
__global__ void __launch_bounds__(256, 2) mm256_k(
    MMPtrs mp, const float* __restrict__ wtbase, float* __restrict__ tmp)
{
    extern __shared__ float smf[];
    const int z = blockIdx.z;
    gemm_body<256,false,false,false>(
        mp.a[z], wtbase + (size_t)(14 + (z & 3)) * 65536,
        nullptr, nullptr, nullptr, nullptr,
        tmp + (size_t)z * 65536, 256, blockIdx.x, blockIdx.y, smf);
}

// ---------------- CSR build (by dst) -----------------------------------------
__global__ void __launch_bounds__(256) hist_k(
    const int* __restrict__ eidx, int* __restrict__ cnt) {
    int i = blockIdx.x * blockDim.x + threadIdx.x;
    if (i < NE) atomicAdd(&cnt[eidx[NE + i]], 1);
}

__global__ void __launch_bounds__(256) scan1_k(
    const int* __restrict__ cnt, int* __restrict__ bs) {
    __shared__ int sm[256];
    int i = blockIdx.x * 256 + threadIdx.x;
    sm[threadIdx.x] = (i < NN) ? cnt[i] : 0;
    __syncthreads();
    #pragma unroll
    for (int o = 128; o > 0; o >>= 1) {
        if (threadIdx.x < o) sm[threadIdx.x] += sm[threadIdx.x + o];
        __syncthreads();
    }
    if (threadIdx.x == 0) bs[blockIdx.x] = sm[0];
}

__global__ void __launch_bounds__(256) scan2_k(
    int* __restrict__ bs, int* __restrict__ rp) {
    __shared__ int sm[256];
    int t = threadIdx.x;
    int v = (t < NBK) ? bs[t] : 0;
    sm[t] = v;
    __syncthreads();
    #pragma unroll
    for (int o = 1; o < 256; o <<= 1) {
        int u = (t >= o) ? sm[t - o] : 0;
        __syncthreads();
        sm[t] += u;
        __syncthreads();
    }
    if (t < NBK) bs[t] = sm[t] - v;
    if (t == NBK - 1) rp[NN] = sm[t];
}

__global__ void __launch_bounds__(256) scan3_k(
    const int* __restrict__ bs, int* __restrict__ rp, int* __restrict__ cur) {
    __shared__ int sm[256];
    int i = blockIdx.x * 256 + threadIdx.x;
    int v = (i < NN) ? cur[i] : 0;
    sm[threadIdx.x] = v;
    __syncthreads();
    #pragma unroll
    for (int o = 1; o < 256; o <<= 1) {
        int u = (threadIdx.x >= o) ? sm[threadIdx.x - o] : 0;
        __syncthreads();
        sm[threadIdx.x] += u;
        __syncthreads();
    }
    if (i < NN) {
        int off = bs[blockIdx.x] + sm[threadIdx.x] - v;
        rp[i] = off;
        cur[i] = off;
    }
}

__global__ void __launch_bounds__(256) scatter_k(
    const int* __restrict__ eidx, int* __restrict__ cur, int* __restrict__ el) {
    int e = blockIdx.x * blockDim.x + threadIdx.x;
    if (e < NE) {
        int pos = atomicAdd(&cur[eidx[NE + e]], 1);
        el[pos] = eidx[e];
    }
}

// ---------------- SpMM gather ------------------------------------------------
__global__ void __launch_bounds__(256) spmm_gather_k(
    const float* __restrict__ h, const int* __restrict__ rp,
    const int* __restrict__ el, float* __restrict__ agg)
{
    int n = (blockIdx.x * 256 + threadIdx.x) >> 5;
    if (n >= NN) return;
    const int lane = threadIdx.x & 31;
    const int c = lane * 8;
    int s = rp[n], e = rp[n + 1];
    float4 a0 = make_float4(0.f,0.f,0.f,0.f);
    float4 a1 = make_float4(0.f,0.f,0.f,0.f);
    int i = s;
    for (; i + 1 < e; i += 2) {
        const float* hp0 = h + (size_t)el[i] * 256 + c;
        const float* hp1 = h + (size_t)el[i + 1] * 256 + c;
        float4 v0 = *(const float4*)hp0;
        float4 v1 = *(const float4*)(hp0 + 4);
        float4 w0 = *(const float4*)hp1;
        float4 w1 = *(const float4*)(hp1 + 4);
        a0.x += v0.x + w0.x; a0.y += v0.y + w0.y;
        a0.z += v0.z + w0.z; a0.w += v0.w + w0.w;
        a1.x += v1.x + w1.x; a1.y += v1.y + w1.y;
        a1.z += v1.z + w1.z; a1.w += v1.w + w1.w;
    }
    if (i < e) {
        const float* hp = h + (size_t)el[i] * 256 + c;
        float4 v0 = *(const float4*)hp;
        float4 v1 = *(const float4*)(hp + 4);
        a0.x += v0.x; a0.y += v0.y; a0.z += v0.z; a0.w += v0.w;
        a1.x += v1.x; a1.y += v1.y; a1.z += v1.z; a1.w += v1.w;
    }
    float* ap = agg + (size_t)n * 256 + c;
    *(float4*)ap       = a0;
    *(float4*)(ap + 4) = a1;
}

// ---------------- geo stage ---------------------------------------------------
__global__ void __launch_bounds__(256) geo_k(
    const float* __restrict__ x,
    const float* __restrict__ geo_w, const float* __restrict__ geo_b,
    float* __restrict__ out)
{
    __shared__ float gws[4096];
    __shared__ float gbs[32];
    for (int i = threadIdx.x; i < 4096; i += 256) gws[i] = geo_w[i];
    if (threadIdx.x < 32) gbs[threadIdx.x] = geo_b[threadIdx.x];
    __syncthreads();
    const int warp = threadIdx.x >> 5, lane = threadIdx.x & 31;
    for (int n0 = blockIdx.x * 8; n0 < NN; n0 += gridDim.x * 8) {
        int n = n0 + warp;
        if (n < NN) {
            const float* xr = x + (size_t)n * 160;
            float s = gbs[lane];
            #pragma unroll
            for (int k = 0; k < 128; ++k) s += __ldg(xr + k) * gws[k * 32 + lane];
            out[(size_t)n * 64 + lane]      = fmaxf(s, 0.f);
            out[(size_t)n * 64 + 32 + lane] = __ldg(xr + 128 + lane);
        }
    }
}

// ---------------- edge encoder + scatter --------------------------------------
__global__ void __launch_bounds__(256) edge_encode_k(
    const float* __restrict__ ea, const int* __restrict__ eidx,
    const float* __restrict__ w1, const float* __restrict__ b1,
    float* __restrict__ At, float* __restrict__ deg)
{
    const int tid = threadIdx.x;
    const int c0 = (tid & 63) * 4;
    const int slot = tid >> 6;
    float4 wreg[16];
    #pragma unroll
    for (int k = 0; k < 16; ++k)
        wreg[k] = *(const float4*)(w1 + k * 256 + c0);
    const float4 b1v = *(const float4*)(b1 + c0);

    __shared__ float eav[8][16];
    __shared__ int dsts[8];

    for (int base = blockIdx.x * 8; base < NE; base += gridDim.x * 8) {
        if (tid < 128) ((float*)eav)[tid] = ea[(size_t)base * 16 + tid];
        if (tid < 8) dsts[tid] = eidx[NE + base + tid];
        __syncthreads();
        #pragma unroll
        for (int g = 0; g < 2; ++g) {
            const int e = slot + g * 4;
            float4 acc = b1v;
            #pragma unroll
            for (int k = 0; k < 16; ++k) {
                float ev = eav[e][k];
                acc.x += wreg[k].x * ev;
                acc.y += wreg[k].y * ev;
                acc.z += wreg[k].z * ev;
                acc.w += wreg[k].w * ev;
            }
            acc.x = fmaxf(acc.x, 0.f); acc.y = fmaxf(acc.y, 0.f);
            acc.z = fmaxf(acc.z, 0.f); acc.w = fmaxf(acc.w, 0.f);
            int dst = dsts[e];
            redAdd4(At + (size_t)dst * 256 + c0, acc);
            if ((tid & 63) == 0) atomicAdd(deg + dst, 1.f);
        }
        __syncthreads();
    }
}

// ---------------- residual + layernorm ----------------------------------------
__global__ void __launch_bounds__(256) ln_k(
    float* __restrict__ h, const float* __restrict__ u,
    const float* __restrict__ g, const float* __restrict__ b)
{
    int gw = (blockIdx.x*blockDim.x + threadIdx.x) >> 5;
    int lane = threadIdx.x & 31;
    int nw = (gridDim.x*blockDim.x) >> 5;
    for (int n = gw; n < NN; n += nw) {
        float* hp = h + (size_t)n*256;
        const float* up = u + (size_t)n*256;
        float v[8];
        float4 h0 = *(float4*)(hp + lane*8),       h1 = *(float4*)(hp + lane*8 + 4);
        float4 u0 = *(const float4*)(up + lane*8), u1 = *(const float4*)(up + lane*8 + 4);
        v[0]=h0.x+u0.x; v[1]=h0.y+u0.y; v[2]=h0.z+u0.z; v[3]=h0.w+u0.w;
        v[4]=h1.x+u1.x; v[5]=h1.y+u1.y; v[6]=h1.z+u1.z; v[7]=h1.w+u1.w;
        float s = 0.f;
        #pragma unroll
        for (int i = 0; i < 8; ++i) s += v[i];
        #pragma unroll
        for (int o = 16; o > 0; o >>= 1) s += __shfl_xor_sync(0xffffffffu, s, o);
        float mu = s * (1.f/256.f);
        float qq = 0.f;
        #pragma unroll
        for (int i = 0; i < 8; ++i) { float d = v[i]-mu; qq += d*d; }
        #pragma unroll
        for (int o = 16; o > 0; o >>= 1) qq += __shfl_xor_sync(0xffffffffu, qq, o);
        float rstd = rsqrtf(qq*(1.f/256.f) + 1e-5f);
        #pragma unroll
        for (int i = 0; i < 8; ++i) {
            int c = lane*8 + i;
            v[i] = (v[i]-mu)*rstd*__ldg(g+c) + __ldg(b+c);
        }
        *(float4*)(hp + lane*8)     = make_float4(v[0],v[1],v[2],v[3]);
        *(float4*)(hp + lane*8 + 4) = make_float4(v[4],v[5],v[6],v[7]);
    }
}

// ---------------- typed mean-pool partial sums -------------------------------
__global__ void __launch_bounds__(256) pool_k(
    const float* __restrict__ h, const int* __restrict__ batch,
    const int* __restrict__ ntype, float* __restrict__ ps, float* __restrict__ pc)
{
    __shared__ float acc[24][256];
    __shared__ float cnt[24];
    for (int i = threadIdx.x; i < 24*256; i += 256) (&acc[0][0])[i] = 0.f;
    if (threadIdx.x < 24) cnt[threadIdx.x] = 0.f;
    __syncthreads();
    int per = (NN + gridDim.x - 1) / gridDim.x;
    int start = blockIdx.x * per;
    int end = start + per; if (end > NN) end = NN;
    for (int n = start; n < end; ++n) {
        int idx = __ldg(ntype+n)*8 + __ldg(batch+n);
        acc[idx][threadIdx.x] += h[(size_t)n*256 + threadIdx.x];
        if (threadIdx.x == 0) cnt[idx] += 1.f;
    }
    __syncthreads();
    for (int i = threadIdx.x; i < 24*256; i += 256) atomicAdd(&ps[i], (&acc[0][0])[i]);
    if (threadIdx.x < 24) atomicAdd(&pc[threadIdx.x], cnt[threadIdx.x]);
}

// ---------------- final write: z | h | batch ---------------------------------
__global__ void __launch_bounds__(256) writeout_k(
    const float* __restrict__ ps, const float* __restrict__ pc,
    const float* __restrict__ h, const int* __restrict__ batch,
    float* __restrict__ out, int out_size)
{
    const int total = 24*256 + NN*HD + NN;
    for (int i = blockIdx.x*blockDim.x + threadIdx.x; i < total;
         i += gridDim.x*blockDim.x) {
        float v; int o;
        if (i < 6144) {
            int c = i & 255, kb = i >> 8, k = kb >> 3, bb = kb & 7;
            float cc = pc[kb]; if (cc < 1.f) cc = 1.f;
            v = ps[i] / cc;
            o = bb*768 + k*256 + c;
        } else if (i < 6144 + NN*HD) {
            v = h[i - 6144]; o = i;
        } else {
            v = (float)batch[i - 6144 - NN*HD]; o = i;
        }
        if (o < out_size) out[o] = v;
    }
}

// ---------------- launcher ----------------------------------------------------
extern "C" void kernel_launch(void* const* d_in, const int* in_sizes, int n_in,
                              void* d_out, int out_size)
{
    const float* x       = (const float*)d_in[0];
    const float* ea      = (const float*)d_in[1];
    const float* geo_w   = (const float*)d_in[2];
    const float* geo_b   = (const float*)d_in[3];
    const float* nin_w1  = (const float*)d_in[4];
    const float* nin_b1  = (const float*)d_in[5];
    const float* nin_w2  = (const float*)d_in[6];
    const float* nin_b2  = (const float*)d_in[7];
    const float* ee_w1   = (const float*)d_in[8];
    const float* ee_b1   = (const float*)d_in[9];
    const float* ee_w2   = (const float*)d_in[10];
    const float* ee_b2   = (const float*)d_in[11];
    const float* msgx    = (const float*)d_in[12];
    const float* msge    = (const float*)d_in[13];
    const float* upd_w1  = (const float*)d_in[14];
    const float* upd_b1  = (const float*)d_in[15];
    const float* upd_w2  = (const float*)d_in[16];
    const float* upd_b2  = (const float*)d_in[17];
    const float* ln_g    = (const float*)d_in[18];
    const float* ln_b    = (const float*)d_in[19];
    const int*   eidx    = (const int*)d_in[20];
    const int*   batch   = (const int*)d_in[21];
    const int*   ntype   = (const int*)d_in[22];
    float* out = (float*)d_out;

    float *h_, *d1_, *d2_, *d3_, *ae_, *deg_, *ps_, *pc_, *wt_, *wt1_;
    int *rp_, *cur_, *el_, *bs_;
    cudaGetSymbolAddress((void**)&h_,  g_h);
    cudaGetSymbolAddress((void**)&d1_, g_d1);
    cudaGetSymbolAddress((void**)&d2_, g_d2);
    cudaGetSymbolAddress((void**)&d3_, g_d3);
    cudaGetSymbolAddress((void**)&ae_, g_ae);
    cudaGetSymbolAddress((void**)&deg_, g_deg);
    cudaGetSymbolAddress((void**)&ps_, g_ps);
    cudaGetSymbolAddress((void**)&pc_, g_pc);
    cudaGetSymbolAddress((void**)&wt_, g_wt);
    cudaGetSymbolAddress((void**)&wt1_, g_wt1);
    cudaGetSymbolAddress((void**)&rp_, g_rp);
    cudaGetSymbolAddress((void**)&cur_, g_cur);
    cudaGetSymbolAddress((void**)&el_, g_el);
    cudaGetSymbolAddress((void**)&bs_, g_bs);

    cudaFuncSetAttribute(gemm_mma<256,false,false,false>,
        cudaFuncAttributeMaxDynamicSharedMemorySize, GEMM_SMEM);
    cudaFuncSetAttribute(gemm_mma<256,false,false,true>,
        cudaFuncAttributeMaxDynamicSharedMemorySize, GEMM_SMEM);
    cudaFuncSetAttribute(gemm_mma<256,true,true,false>,
        cudaFuncAttributeMaxDynamicSharedMemorySize, GEMM_SMEM);
    cudaFuncSetAttribute(gemm_mma<64,false,true,false>,
        cudaFuncAttributeMaxDynamicSharedMemorySize, GEMM_SMEM);
    cudaFuncSetAttribute(mm256_k,
        cudaFuncAttributeMaxDynamicSharedMemorySize, GEMM_SMEM);

    // --- weight precompute --------------------------------------------------
    // Phase 1: wfrag(upd_w1[l]) -> wt slots 14..17 (temporary)
    WPtrs wp1;
    for (int l = 0; l < 4; ++l) wp1.p[l] = upd_w1 + (size_t)l*65536;
    wfrag_k<<<dim3(16, 4), 256>>>(wp1, wt_ + (size_t)14*65536);

    // Phase 2: tmp[z] = (z<4 ? msgx[z] : msge[z-4]) @ upd_w1[z&3]  (tmp in d1)
    MMPtrs mp;
    for (int l = 0; l < 4; ++l) {
        mp.a[l]     = msgx + (size_t)l*65536;
        mp.a[4 + l] = msge + (size_t)l*65536;
    }
    mm256_k<<<dim3(2, 2, 8), 256, GEMM_SMEM>>>(mp, wt_, d1_);

    // Phase 3: wfrag all production matrices into slots 0..13
    // 0 nin_w2, 1 ee_w2, 2..5 M1, 6..9 E1, 10..13 upd_w2
    WPtrs wp;
    wp.p[0] = nin_w2; wp.p[1] = ee_w2;
    for (int l = 0; l < 4; ++l) {
        wp.p[2 + l]  = d1_ + (size_t)l*65536;        // M1
        wp.p[6 + l]  = d1_ + (size_t)(4+l)*65536;    // E1
        wp.p[10 + l] = upd_w2 + (size_t)l*65536;
    }
    wfrag_k<<<dim3(16, 14), 256>>>(wp, wt_);
    wfrag64_k<<<4, 256>>>(nin_w1, wt1_);

    // --- CSR build (by dst) ---------------------------------------------------
    cudaMemsetAsync(cur_, 0, NN*sizeof(int));
    hist_k<<<(NE+255)/256, 256>>>(eidx, cur_);
    scan1_k<<<NBK, 256>>>(cur_, bs_);
    scan2_k<<<1, 256>>>(bs_, rp_);
    scan3_k<<<NBK, 256>>>(bs_, rp_, cur_);
    scatter_k<<<(NE+255)/256, 256>>>(eidx, cur_, el_);

    dim3 gg(391, 2);

    // node encoder
    geo_k<<<625, 256>>>(x, geo_w, geo_b, d3_);
    gemm_mma<64,false,true,false><<<gg, 256, GEMM_SMEM>>>(
        d3_, wt1_, nullptr, nullptr, nin_b1, nullptr, d1_, NN);
    gemm_mma<256,false,false,false><<<gg, 256, GEMM_SMEM>>>(
        d1_, wt_ + 0*65536, nullptr, nullptr, nin_b2, nullptr, h_, NN);

    // edge encoder scatter
    cudaMemsetAsync(d2_, 0, (size_t)NN*HD*sizeof(float));
    cudaMemsetAsync(deg_, 0, (size_t)NN*sizeof(float));
    edge_encode_k<<<1184, 256>>>(ea, eidx, ee_w1, ee_b1, d2_, deg_);
    gemm_mma<256,false,false,true><<<gg, 256, GEMM_SMEM>>>(
        d2_, wt_ + 1*65536, nullptr, nullptr, ee_b2, deg_, ae_, NN);

    for (int l = 0; l < NL; ++l) {
        spmm_gather_k<<<6250, 256>>>(h_, rp_, el_, d1_);
        // d3 = relu(Ah@M1 + Ae@E1 + b1)   [fused msg+upd1]
        gemm_mma<256,true,true,false><<<gg, 256, GEMM_SMEM>>>(
            d1_, wt_ + (size_t)(2+l)*65536, ae_, wt_ + (size_t)(6+l)*65536,
            upd_b1 + l*256, nullptr, d3_, NN);
        // d1 = d3@upd_w2 + b2
        gemm_mma<256,false,false,false><<<gg, 256, GEMM_SMEM>>>(
            d3_, wt_ + (size_t)(10+l)*65536, nullptr, nullptr,
            upd_b2 + l*256, nullptr, d1_, NN);
        ln_k<<<784, 256>>>(h_, d1_, ln_g + l*256, ln_b + l*256);
    }

    cudaMemsetAsync(ps_, 0, 24*HD*sizeof(float));
    cudaMemsetAsync(pc_, 0, 24*sizeof(float));
    pool_k<<<512, 256>>>(h_, batch, ntype, ps_, pc_);
    writeout_k<<<8192, 256>>>(ps_, pc_, h_, batch, out, out_size);
}

// round 9
// speedup vs baseline: 2.6377x; 1.0608x over previous
#include <cuda_runtime.h>
#include <cstdint>

#define NN 50000
#define NE 300000
#define HD 256
#define NB 8
#define NL 4
#define NBK 196   // ceil(NN/256)

// ---------------- scratch (static device globals; no allocs allowed) -------
__device__ float g_h [NN*HD];
__device__ float g_d1[NN*HD];
__device__ float g_d2[NN*HD];
__device__ float g_d3[NN*HD];
__device__ float g_ae[NN*HD];
__device__ float g_deg[NN];
__device__ float g_ps[24*HD];
__device__ float g_pc[24];
__device__ float g_wt[18*65536];   // fragment-permuted tf32 weights
__device__ float g_wt1[16384];     // fragment-permuted nin_w1 (K=64)
__device__ int   g_rp[NN+1];       // CSR row pointer (by dst)
__device__ int   g_cur[NN];        // counts, then cursors
__device__ int   g_el[NE];         // CSR column (src) list
__device__ int   g_bs[256];        // block sums for scan

// ---------------- helpers ------------------------------------------------
__device__ __forceinline__ float tf32r(float x) {
    float r;
    asm("cvt.rna.tf32.f32 %0, %1;" : "=f"(r) : "f"(x));
    return r;
}
__device__ __forceinline__ void redAdd4(float* p, float4 v) {
    asm volatile("red.global.add.v4.f32 [%0], {%1,%2,%3,%4};"
                 :: "l"(p), "f"(v.x), "f"(v.y), "f"(v.z), "f"(v.w) : "memory");
}
__device__ __forceinline__ uint32_t smem_u32(const void* p) {
    uint32_t a;
    asm("{ .reg .u64 t; cvta.to.shared.u64 t, %1; cvt.u32.u64 %0, t; }"
        : "=r"(a) : "l"(p));
    return a;
}
__device__ __forceinline__ void cp_async16(uint32_t sdst, const void* gsrc) {
    asm volatile("cp.async.ca.shared.global [%0], [%1], 16;"
                 :: "r"(sdst), "l"(gsrc) : "memory");
}
#define CP_COMMIT() asm volatile("cp.async.commit_group;" ::: "memory")
#define CP_WAIT1()  asm volatile("cp.async.wait_group 1;" ::: "memory")

#define MMA_TF32(c, a, b0, b1)                                               \
    asm volatile("mma.sync.aligned.m16n8k8.row.col.f32.tf32.tf32.f32 "      \
        "{%0,%1,%2,%3}, {%4,%5,%6,%7}, {%8,%9}, {%0,%1,%2,%3};"             \
        : "+f"((c)[0]), "+f"((c)[1]), "+f"((c)[2]), "+f"((c)[3])            \
        : "r"((a)[0]), "r"((a)[1]), "r"((a)[2]), "r"((a)[3]),               \
          "r"(b0), "r"(b1))

// ---------------- weight -> fragment-major blocks ---------------------------
// New lane-major block layout (LDS.128 on read):
// group = (kk>>3)*8 + (nl>>4); lane = (nl&7)*4 + (kk&3);
// f = ((nl>>3)&1)*2 + ((kk>>2)&1); idx = group*128 + lane*4 + f
struct WPtrs { const float* p[18]; };

__global__ void __launch_bounds__(256) wfrag_k(WPtrs wp, float* __restrict__ out) {
    const float* W = wp.p[blockIdx.y];
    float* O = out + (size_t)blockIdx.y * 65536 + blockIdx.x * 4096;
    const int kc = blockIdx.x >> 1, nb = blockIdx.x & 1;
    const int nl = threadIdx.x >> 1;
    const int khalf = (threadIdx.x & 1) * 16;
    const int n = nb * 128 + nl;
    #pragma unroll
    for (int g = 0; g < 4; ++g) {
        int kk0 = khalf + g * 4;
        int k = kc * 32 + kk0;
        float vv[4];
        vv[0] = tf32r(W[(size_t)(k+0)*256 + n]);
        vv[1] = tf32r(W[(size_t)(k+1)*256 + n]);
        vv[2] = tf32r(W[(size_t)(k+2)*256 + n]);
        vv[3] = tf32r(W[(size_t)(k+3)*256 + n]);
        int base = ((kk0>>3)*8 + (nl>>4))*128 + (nl&7)*16
                 + ((((nl>>3)&1)<<1) | ((kk0>>2)&1));
        #pragma unroll
        for (int q = 0; q < 4; ++q) O[base + q*4] = vv[q];
    }
}

__global__ void __launch_bounds__(256) wfrag64_k(
    const float* __restrict__ W, float* __restrict__ out) {
    float* O = out + blockIdx.x * 4096;
    const int kc = blockIdx.x >> 1, nb = blockIdx.x & 1;
    const int nl = threadIdx.x >> 1;
    const int khalf = (threadIdx.x & 1) * 16;
    const int n = nb * 128 + nl;
    #pragma unroll
    for (int g = 0; g < 4; ++g) {
        int kk0 = khalf + g * 4;
        int k = kc * 32 + kk0;
        float vv[4];
        vv[0] = tf32r(W[(size_t)(k+0)*256 + n]);
        vv[1] = tf32r(W[(size_t)(k+1)*256 + n]);
        vv[2] = tf32r(W[(size_t)(k+2)*256 + n]);
        vv[3] = tf32r(W[(size_t)(k+3)*256 + n]);
        int base = ((kk0>>3)*8 + (nl>>4))*128 + (nl&7)*16
                 + ((((nl>>3)&1)<<1) | ((kk0>>2)&1));
        #pragma unroll
        for (int q = 0; q < 4; ++q) O[base + q*4] = vv[q];
    }
}

// ---------------- tensor-core GEMM body (tf32 mma.sync) ---------------------
#define GEMM_SMEM 98304

template<int KROW, bool DUAL, bool RELU, bool ROWSCALE, bool CVT, bool ROUND>
__device__ __forceinline__ void gemm_body(
    const float* __restrict__ A,  const float* __restrict__ Wf,
    const float* __restrict__ A2, const float* __restrict__ Wf2,
    const float* __restrict__ bias, const float* __restrict__ rowscale,
    float* __restrict__ C, int M, int bmblk, int nb, float* smf)
{
    const uint32_t sbase = smem_u32(smf);
    const int tid = threadIdx.x;
    const int wid = tid >> 5, lane = tid & 31;
    const int warp_m = wid & 1, warp_n = wid >> 1;   // 2M x 4N
    const int bm = bmblk * 128;

    const int a_row = tid >> 1;
    const int a_half = tid & 1;
    const int arow = bm + a_row;
    const int a_sw = a_row & 7;

    float acc[4][4][4];
    #pragma unroll
    for (int t = 0; t < 4; ++t)
        #pragma unroll
        for (int j = 0; j < 4; ++j)
            #pragma unroll
            for (int q = 0; q < 4; ++q) acc[t][j][q] = 0.f;

    const int KC = KROW / 32;
    const int NCHUNK = (DUAL ? 2 : 1) * KC;

    auto cpA = [&](int c, int s) {
        const float* Ap = (DUAL && c >= KC) ? A2 : A;
        int k0 = ((DUAL && c >= KC) ? (c - KC) : c) * 32;
        if (arow < M) {
            const float* src = Ap + (size_t)arow * KROW + k0 + a_half * 16;
            uint32_t drow = sbase + s * 32768 + a_row * 128;
            #pragma unroll
            for (int j = 0; j < 4; ++j) {
                int chunk = a_half * 4 + j;
                cp_async16(drow + ((chunk ^ a_sw) << 4), src + j * 4);
            }
        } else {
            float* drow = smf + s * 8192 + a_row * 32;
            #pragma unroll
            for (int j = 0; j < 4; ++j) {
                int chunk = a_half * 4 + j;
                *(float4*)(drow + ((chunk ^ a_sw) << 2)) =
                    make_float4(0.f, 0.f, 0.f, 0.f);
            }
        }
    };
    auto cpB = [&](int c, int s) {
        const float* Wp = (DUAL && c >= KC) ? Wf2 : Wf;
        int cc = (DUAL && c >= KC) ? (c - KC) : c;
        const float* src = Wp + ((size_t)cc * 2 + nb) * 4096 + tid * 16;
        uint32_t dst = sbase + s * 32768 + 16384 + tid * 64;
        #pragma unroll
        for (int i = 0; i < 4; ++i)
            cp_async16(dst + i * 16, src + i * 4);
    };
    auto compute_ks = [&](int s, int ks) {
        const float* a = smf + s * 8192;
        const float* b = smf + s * 8192 + 4096;
        const int lr = lane >> 2, lc = lane & 3;
        uint32_t av[4][4];
        float4 bq[2];
        #pragma unroll
        for (int t = 0; t < 4; ++t) {
            int m0 = warp_m * 64 + t * 16 + lr;
            #pragma unroll
            for (int i = 0; i < 4; ++i) {
                int row = m0 + (i & 1) * 8;
                int chunk = 2 * ks + (i >> 1);
                float v = a[row * 32 + ((chunk ^ lr) << 2) + lc];
                av[t][i] = __float_as_uint(CVT ? tf32r(v) : v);
            }
        }
        #pragma unroll
        for (int p = 0; p < 2; ++p)
            bq[p] = *(const float4*)&b[((ks * 8 + warp_n * 2 + p) * 32 + lane) * 4];
        #pragma unroll
        for (int t = 0; t < 4; ++t)
            #pragma unroll
            for (int p = 0; p < 2; ++p) {
                MMA_TF32(acc[t][p*2+0], av[t],
                         __float_as_uint(bq[p].x), __float_as_uint(bq[p].y));
                MMA_TF32(acc[t][p*2+1], av[t],
                         __float_as_uint(bq[p].z), __float_as_uint(bq[p].w));
            }
    };

    #pragma unroll
    for (int s = 0; s < 2; ++s) {
        if (s < NCHUNK) { cpA(s, s); cpB(s, s); }
        CP_COMMIT();
    }
    for (int c = 0; c < NCHUNK; ++c) {
        CP_WAIT1();
        __syncthreads();
        int sl = c + 2;
        if (sl < NCHUNK) { cpA(sl, sl % 3); cpB(sl, sl % 3); }
        CP_COMMIT();
        int s = c % 3;
        compute_ks(s, 0);
        compute_ks(s, 1);
        compute_ks(s, 2);
        compute_ks(s, 3);
    }

    // ---- epilogue ----
    const int row_base = bm + warp_m * 64 + (lane >> 2);
    const int col_base = nb * 128 + warp_n * 32 + (lane & 3) * 2;
    #pragma unroll
    for (int t = 0; t < 4; ++t) {
        int r0 = row_base + t * 16;
        int r1 = r0 + 8;
        float s0 = 1.f, s1 = 1.f;
        if (ROWSCALE) {
            s0 = (r0 < M) ? rowscale[r0] : 0.f;
            s1 = (r1 < M) ? rowscale[r1] : 0.f;
        }
        #pragma unroll
        for (int j = 0; j < 4; ++j) {
            int col = col_base + j * 8;
            float bb0 = 0.f, bb1 = 0.f;
            if (bias) { bb0 = __ldg(bias + col); bb1 = __ldg(bias + col + 1); }
            float v00 = acc[t][j][0] + bb0 * s0;
            float v01 = acc[t][j][1] + bb1 * s0;
            float v10 = acc[t][j][2] + bb0 * s1;
            float v11 = acc[t][j][3] + bb1 * s1;
            if (RELU) {
                v00 = fmaxf(v00, 0.f); v01 = fmaxf(v01, 0.f);
                v10 = fmaxf(v10, 0.f); v11 = fmaxf(v11, 0.f);
            }
            if (ROUND) {
                v00 = tf32r(v00); v01 = tf32r(v01);
                v10 = tf32r(v10); v11 = tf32r(v11);
            }
            if (r0 < M) *(float2*)(C + (size_t)r0 * 256 + col) = make_float2(v00, v01);
            if (r1 < M) *(float2*)(C + (size_t)r1 * 256 + col) = make_float2(v10, v11);
        }
    }
}

template<int KROW, bool DUAL, bool RELU, bool ROWSCALE, bool CVT, bool ROUND>
__global__ void __launch_bounds__(256, 2) gemm_mma(
    const float* __restrict__ A,  const float* __restrict__ Wf,
    const float* __restrict__ A2, const float* __restrict__ Wf2,
    const float* __restrict__ bias, const float* __restrict__ rowscale,
    float* __restrict__ C, int M)
{
    extern __shared__ float smf[];
    gemm_body<KROW,DUAL,RELU,ROWSCALE,CVT,ROUND>(
        A, Wf, A2, Wf2, bias, rowscale, C, M, blockIdx.x, blockIdx.y, smf);
}

// batched 256x256x256: tmp[z] = A[z] @ Wf[slot 14 + (z&3)]
struct MMPtrs { const float* a[8]; };
__global__ void __launch_bounds__(256, 2) mm256_k(
    MMPtrs mp, const float* __restrict__ wtbase, float* __restrict__ tmp)
{
    extern __shared__ float smf[];
    const int z = blockIdx.z;
    gemm_body<256,false,false,false,true,false>(
        mp.a[z], wtbase + (size_t)(14 + (z & 3)) * 65536,
        nullptr, nullptr, nullptr, nullptr,
        tmp + (size_t)z * 65536, 256, blockIdx.x, blockIdx.y, smf);
}

// ---------------- CSR build (by dst) -----------------------------------------
__global__ void __launch_bounds__(256) hist_k(
    const int* __restrict__ eidx, int* __restrict__ cnt) {
    int i = blockIdx.x * blockDim.x + threadIdx.x;
    if (i < NE) atomicAdd(&cnt[eidx[NE + i]], 1);
}

__global__ void __launch_bounds__(256) scan1_k(
    const int* __restrict__ cnt, int* __restrict__ bs) {
    __shared__ int sm[256];
    int i = blockIdx.x * 256 + threadIdx.x;
    sm[threadIdx.x] = (i < NN) ? cnt[i] : 0;
    __syncthreads();
    #pragma unroll
    for (int o = 128; o > 0; o >>= 1) {
        if (threadIdx.x < o) sm[threadIdx.x] += sm[threadIdx.x + o];
        __syncthreads();
    }
    if (threadIdx.x == 0) bs[blockIdx.x] = sm[0];
}

__global__ void __launch_bounds__(256) scan2_k(
    int* __restrict__ bs, int* __restrict__ rp) {
    __shared__ int sm[256];
    int t = threadIdx.x;
    int v = (t < NBK) ? bs[t] : 0;
    sm[t] = v;
    __syncthreads();
    #pragma unroll
    for (int o = 1; o < 256; o <<= 1) {
        int u = (t >= o) ? sm[t - o] : 0;
        __syncthreads();
        sm[t] += u;
        __syncthreads();
    }
    if (t < NBK) bs[t] = sm[t] - v;
    if (t == NBK - 1) rp[NN] = sm[t];
}

__global__ void __launch_bounds__(256) scan3_k(
    const int* __restrict__ bs, int* __restrict__ rp, int* __restrict__ cur) {
    __shared__ int sm[256];
    int i = blockIdx.x * 256 + threadIdx.x;
    int v = (i < NN) ? cur[i] : 0;
    sm[threadIdx.x] = v;
    __syncthreads();
    #pragma unroll
    for (int o = 1; o < 256; o <<= 1) {
        int u = (threadIdx.x >= o) ? sm[threadIdx.x - o] : 0;
        __syncthreads();
        sm[threadIdx.x] += u;
        __syncthreads();
    }
    if (i < NN) {
        int off = bs[blockIdx.x] + sm[threadIdx.x] - v;
        rp[i] = off;
        cur[i] = off;
    }
}

__global__ void __launch_bounds__(256) scatter_k(
    const int* __restrict__ eidx, int* __restrict__ cur, int* __restrict__ el) {
    int e = blockIdx.x * blockDim.x + threadIdx.x;
    if (e < NE) {
        int pos = atomicAdd(&cur[eidx[NE + e]], 1);
        el[pos] = eidx[e];
    }
}

// ---------------- SpMM gather (tf32-rounded output) --------------------------
__global__ void __launch_bounds__(256) spmm_gather_k(
    const float* __restrict__ h, const int* __restrict__ rp,
    const int* __restrict__ el, float* __restrict__ agg)
{
    int n = (blockIdx.x * 256 + threadIdx.x) >> 5;
    if (n >= NN) return;
    const int lane = threadIdx.x & 31;
    const int c = lane * 8;
    int s = rp[n], e = rp[n + 1];
    float4 a0 = make_float4(0.f,0.f,0.f,0.f);
    float4 a1 = make_float4(0.f,0.f,0.f,0.f);
    int i = s;
    for (; i + 1 < e; i += 2) {
        const float* hp0 = h + (size_t)el[i] * 256 + c;
        const float* hp1 = h + (size_t)el[i + 1] * 256 + c;
        float4 v0 = *(const float4*)hp0;
        float4 v1 = *(const float4*)(hp0 + 4);
        float4 w0 = *(const float4*)hp1;
        float4 w1 = *(const float4*)(hp1 + 4);
        a0.x += v0.x + w0.x; a0.y += v0.y + w0.y;
        a0.z += v0.z + w0.z; a0.w += v0.w + w0.w;
        a1.x += v1.x + w1.x; a1.y += v1.y + w1.y;
        a1.z += v1.z + w1.z; a1.w += v1.w + w1.w;
    }
    if (i < e) {
        const float* hp = h + (size_t)el[i] * 256 + c;
        float4 v0 = *(const float4*)hp;
        float4 v1 = *(const float4*)(hp + 4);
        a0.x += v0.x; a0.y += v0.y; a0.z += v0.z; a0.w += v0.w;
        a1.x += v1.x; a1.y += v1.y; a1.z += v1.z; a1.w += v1.w;
    }
    a0.x = tf32r(a0.x); a0.y = tf32r(a0.y); a0.z = tf32r(a0.z); a0.w = tf32r(a0.w);
    a1.x = tf32r(a1.x); a1.y = tf32r(a1.y); a1.z = tf32r(a1.z); a1.w = tf32r(a1.w);
    float* ap = agg + (size_t)n * 256 + c;
    *(float4*)ap       = a0;
    *(float4*)(ap + 4) = a1;
}

// ---------------- geo stage (tf32-rounded output) ------------------------------
__global__ void __launch_bounds__(256) geo_k(
    const float* __restrict__ x,
    const float* __restrict__ geo_w, const float* __restrict__ geo_b,
    float* __restrict__ out)
{
    __shared__ float gws[4096];
    __shared__ float gbs[32];
    for (int i = threadIdx.x; i < 4096; i += 256) gws[i] = geo_w[i];
    if (threadIdx.x < 32) gbs[threadIdx.x] = geo_b[threadIdx.x];
    __syncthreads();
    const int warp = threadIdx.x >> 5, lane = threadIdx.x & 31;
    for (int n0 = blockIdx.x * 8; n0 < NN; n0 += gridDim.x * 8) {
        int n = n0 + warp;
        if (n < NN) {
            const float* xr = x + (size_t)n * 160;
            float s = gbs[lane];
            #pragma unroll
            for (int k = 0; k < 128; ++k) s += __ldg(xr + k) * gws[k * 32 + lane];
            out[(size_t)n * 64 + lane]      = tf32r(fmaxf(s, 0.f));
            out[(size_t)n * 64 + 32 + lane] = tf32r(__ldg(xr + 128 + lane));
        }
    }
}

// ---------------- edge encoder + scatter --------------------------------------
__global__ void __launch_bounds__(256) edge_encode_k(
    const float* __restrict__ ea, const int* __restrict__ eidx,
    const float* __restrict__ w1, const float* __restrict__ b1,
    float* __restrict__ At, float* __restrict__ deg)
{
    const int tid = threadIdx.x;
    const int c0 = (tid & 63) * 4;
    const int slot = tid >> 6;
    float4 wreg[16];
    #pragma unroll
    for (int k = 0; k < 16; ++k)
        wreg[k] = *(const float4*)(w1 + k * 256 + c0);
    const float4 b1v = *(const float4*)(b1 + c0);

    __shared__ float eav[8][16];
    __shared__ int dsts[8];

    for (int base = blockIdx.x * 8; base < NE; base += gridDim.x * 8) {
        if (tid < 128) ((float*)eav)[tid] = ea[(size_t)base * 16 + tid];
        if (tid < 8) dsts[tid] = eidx[NE + base + tid];
        __syncthreads();
        #pragma unroll
        for (int g = 0; g < 2; ++g) {
            const int e = slot + g * 4;
            float4 acc = b1v;
            #pragma unroll
            for (int k = 0; k < 16; ++k) {
                float ev = eav[e][k];
                acc.x += wreg[k].x * ev;
                acc.y += wreg[k].y * ev;
                acc.z += wreg[k].z * ev;
                acc.w += wreg[k].w * ev;
            }
            acc.x = fmaxf(acc.x, 0.f); acc.y = fmaxf(acc.y, 0.f);
            acc.z = fmaxf(acc.z, 0.f); acc.w = fmaxf(acc.w, 0.f);
            int dst = dsts[e];
            redAdd4(At + (size_t)dst * 256 + c0, acc);
            if ((tid & 63) == 0) atomicAdd(deg + dst, 1.f);
        }
        __syncthreads();
    }
}

// ---------------- residual + layernorm (out pointer param) -------------------
__global__ void __launch_bounds__(256) ln_k(
    const float* h, const float* __restrict__ u,
    const float* __restrict__ g, const float* __restrict__ b, float* o)
{
    int gw = (blockIdx.x*blockDim.x + threadIdx.x) >> 5;
    int lane = threadIdx.x & 31;
    int nw = (gridDim.x*blockDim.x) >> 5;
    for (int n = gw; n < NN; n += nw) {
        const float* hp = h + (size_t)n*256;
        const float* up = u + (size_t)n*256;
        float v[8];
        float4 h0 = *(const float4*)(hp + lane*8), h1 = *(const float4*)(hp + lane*8 + 4);
        float4 u0 = *(const float4*)(up + lane*8), u1 = *(const float4*)(up + lane*8 + 4);
        v[0]=h0.x+u0.x; v[1]=h0.y+u0.y; v[2]=h0.z+u0.z; v[3]=h0.w+u0.w;
        v[4]=h1.x+u1.x; v[5]=h1.y+u1.y; v[6]=h1.z+u1.z; v[7]=h1.w+u1.w;
        float s = 0.f;
        #pragma unroll
        for (int i = 0; i < 8; ++i) s += v[i];
        #pragma unroll
        for (int oo = 16; oo > 0; oo >>= 1) s += __shfl_xor_sync(0xffffffffu, s, oo);
        float mu = s * (1.f/256.f);
        float qq = 0.f;
        #pragma unroll
        for (int i = 0; i < 8; ++i) { float d = v[i]-mu; qq += d*d; }
        #pragma unroll
        for (int oo = 16; oo > 0; oo >>= 1) qq += __shfl_xor_sync(0xffffffffu, qq, oo);
        float rstd = rsqrtf(qq*(1.f/256.f) + 1e-5f);
        #pragma unroll
        for (int i = 0; i < 8; ++i) {
            int c = lane*8 + i;
            v[i] = (v[i]-mu)*rstd*__ldg(g+c) + __ldg(b+c);
        }
        float* op = o + (size_t)n*256;
        *(float4*)(op + lane*8)     = make_float4(v[0],v[1],v[2],v[3]);
        *(float4*)(op + lane*8 + 4) = make_float4(v[4],v[5],v[6],v[7]);
    }
}

// ---------------- typed mean-pool partial sums -------------------------------
__global__ void __launch_bounds__(256) pool_k(
    const float* __restrict__ h, const int* __restrict__ batch,
    const int* __restrict__ ntype, float* __restrict__ ps, float* __restrict__ pc)
{
    __shared__ float acc[24][256];
    __shared__ float cnt[24];
    for (int i = threadIdx.x; i < 24*256; i += 256) (&acc[0][0])[i] = 0.f;
    if (threadIdx.x < 24) cnt[threadIdx.x] = 0.f;
    __syncthreads();
    int per = (NN + gridDim.x - 1) / gridDim.x;
    int start = blockIdx.x * per;
    int end = start + per; if (end > NN) end = NN;
    for (int n = start; n < end; ++n) {
        int idx = __ldg(ntype+n)*8 + __ldg(batch+n);
        acc[idx][threadIdx.x] += h[(size_t)n*256 + threadIdx.x];
        if (threadIdx.x == 0) cnt[idx] += 1.f;
    }
    __syncthreads();
    for (int i = threadIdx.x; i < 24*256; i += 256) atomicAdd(&ps[i], (&acc[0][0])[i]);
    if (threadIdx.x < 24) atomicAdd(&pc[threadIdx.x], cnt[threadIdx.x]);
}

// ---------------- small writeout: z + batch only ------------------------------
__global__ void __launch_bounds__(256) writeout_small_k(
    const float* __restrict__ ps, const float* __restrict__ pc,
    const int* __restrict__ batch, float* __restrict__ out, int out_size)
{
    const int total = 6144 + NN;
    int i = blockIdx.x * blockDim.x + threadIdx.x;
    if (i >= total) return;
    float v; int o;
    if (i < 6144) {
        int c = i & 255, kb = i >> 8, k = kb >> 3, bb = kb & 7;
        float cc = pc[kb]; if (cc < 1.f) cc = 1.f;
        v = ps[i] / cc;
        o = bb*768 + k*256 + c;
    } else {
        v = (float)batch[i - 6144];
        o = 6144 + NN*HD + (i - 6144);
    }
    if (o < out_size) out[o] = v;
}

// ---------------- launcher ----------------------------------------------------
extern "C" void kernel_launch(void* const* d_in, const int* in_sizes, int n_in,
                              void* d_out, int out_size)
{
    const float* x       = (const float*)d_in[0];
    const float* ea      = (const float*)d_in[1];
    const float* geo_w   = (const float*)d_in[2];
    const float* geo_b   = (const float*)d_in[3];
    const float* nin_w1  = (const float*)d_in[4];
    const float* nin_b1  = (const float*)d_in[5];
    const float* nin_w2  = (const float*)d_in[6];
    const float* nin_b2  = (const float*)d_in[7];
    const float* ee_w1   = (const float*)d_in[8];
    const float* ee_b1   = (const float*)d_in[9];
    const float* ee_w2   = (const float*)d_in[10];
    const float* ee_b2   = (const float*)d_in[11];
    const float* msgx    = (const float*)d_in[12];
    const float* msge    = (const float*)d_in[13];
    const float* upd_w1  = (const float*)d_in[14];
    const float* upd_b1  = (const float*)d_in[15];
    const float* upd_w2  = (const float*)d_in[16];
    const float* upd_b2  = (const float*)d_in[17];
    const float* ln_g    = (const float*)d_in[18];
    const float* ln_b    = (const float*)d_in[19];
    const int*   eidx    = (const int*)d_in[20];
    const int*   batch   = (const int*)d_in[21];
    const int*   ntype   = (const int*)d_in[22];
    float* out = (float*)d_out;

    float *h_, *d1_, *d2_, *d3_, *ae_, *deg_, *ps_, *pc_, *wt_, *wt1_;
    int *rp_, *cur_, *el_, *bs_;
    cudaGetSymbolAddress((void**)&h_,  g_h);
    cudaGetSymbolAddress((void**)&d1_, g_d1);
    cudaGetSymbolAddress((void**)&d2_, g_d2);
    cudaGetSymbolAddress((void**)&d3_, g_d3);
    cudaGetSymbolAddress((void**)&ae_, g_ae);
    cudaGetSymbolAddress((void**)&deg_, g_deg);
    cudaGetSymbolAddress((void**)&ps_, g_ps);
    cudaGetSymbolAddress((void**)&pc_, g_pc);
    cudaGetSymbolAddress((void**)&wt_, g_wt);
    cudaGetSymbolAddress((void**)&wt1_, g_wt1);
    cudaGetSymbolAddress((void**)&rp_, g_rp);
    cudaGetSymbolAddress((void**)&cur_, g_cur);
    cudaGetSymbolAddress((void**)&el_, g_el);
    cudaGetSymbolAddress((void**)&bs_, g_bs);

    cudaFuncSetAttribute((const void*)gemm_mma<64,false,true,false,false,true>,
        cudaFuncAttributeMaxDynamicSharedMemorySize, GEMM_SMEM);
    cudaFuncSetAttribute((const void*)gemm_mma<256,false,false,false,false,false>,
        cudaFuncAttributeMaxDynamicSharedMemorySize, GEMM_SMEM);
    cudaFuncSetAttribute((const void*)gemm_mma<256,false,false,true,true,true>,
        cudaFuncAttributeMaxDynamicSharedMemorySize, GEMM_SMEM);
    cudaFuncSetAttribute((const void*)gemm_mma<256,true,true,false,false,true>,
        cudaFuncAttributeMaxDynamicSharedMemorySize, GEMM_SMEM);
    cudaFuncSetAttribute((const void*)mm256_k,
        cudaFuncAttributeMaxDynamicSharedMemorySize, GEMM_SMEM);

    // --- weight precompute ----------------------------------------------------
    WPtrs wp1;
    for (int l = 0; l < 4; ++l) wp1.p[l] = upd_w1 + (size_t)l*65536;
    wfrag_k<<<dim3(16, 4), 256>>>(wp1, wt_ + (size_t)14*65536);

    MMPtrs mp;
    for (int l = 0; l < 4; ++l) {
        mp.a[l]     = msgx + (size_t)l*65536;
        mp.a[4 + l] = msge + (size_t)l*65536;
    }
    mm256_k<<<dim3(2, 2, 8), 256, GEMM_SMEM>>>(mp, wt_, d1_);

    WPtrs wp;
    wp.p[0] = nin_w2; wp.p[1] = ee_w2;
    for (int l = 0; l < 4; ++l) {
        wp.p[2 + l]  = d1_ + (size_t)l*65536;        // M1
        wp.p[6 + l]  = d1_ + (size_t)(4+l)*65536;    // E1
        wp.p[10 + l] = upd_w2 + (size_t)l*65536;
    }
    wfrag_k<<<dim3(16, 14), 256>>>(wp, wt_);
    wfrag64_k<<<4, 256>>>(nin_w1, wt1_);

    // --- CSR build (by dst) -----------------------------------------------------
    cudaMemsetAsync(cur_, 0, NN*sizeof(int));
    hist_k<<<(NE+255)/256, 256>>>(eidx, cur_);
    scan1_k<<<NBK, 256>>>(cur_, bs_);
    scan2_k<<<1, 256>>>(bs_, rp_);
    scan3_k<<<NBK, 256>>>(bs_, rp_, cur_);
    scatter_k<<<(NE+255)/256, 256>>>(eidx, cur_, el_);

    dim3 gg(391, 2);

    // node encoder
    geo_k<<<625, 256>>>(x, geo_w, geo_b, d3_);
    gemm_mma<64,false,true,false,false,true><<<gg, 256, GEMM_SMEM>>>(
        d3_, wt1_, nullptr, nullptr, nin_b1, nullptr, d1_, NN);
    gemm_mma<256,false,false,false,false,false><<<gg, 256, GEMM_SMEM>>>(
        d1_, wt_ + 0*65536, nullptr, nullptr, nin_b2, nullptr, h_, NN);

    // edge encoder scatter
    cudaMemsetAsync(d2_, 0, (size_t)NN*HD*sizeof(float));
    cudaMemsetAsync(deg_, 0, (size_t)NN*sizeof(float));
    edge_encode_k<<<1184, 256>>>(ea, eidx, ee_w1, ee_b1, d2_, deg_);
    gemm_mma<256,false,false,true,true,true><<<gg, 256, GEMM_SMEM>>>(
        d2_, wt_ + 1*65536, nullptr, nullptr, ee_b2, deg_, ae_, NN);

    float* hout = out + 6144;   // final LN output lives directly in out
    for (int l = 0; l < NL; ++l) {
        spmm_gather_k<<<6250, 256>>>(h_, rp_, el_, d1_);
        // d3 = relu(Ah@M1 + Ae@E1 + b1)   [fused msg+upd1]
        gemm_mma<256,true,true,false,false,true><<<gg, 256, GEMM_SMEM>>>(
            d1_, wt_ + (size_t)(2+l)*65536, ae_, wt_ + (size_t)(6+l)*65536,
            upd_b1 + l*256, nullptr, d3_, NN);
        // d1 = d3@upd_w2 + b2
        gemm_mma<256,false,false,false,false,false><<<gg, 256, GEMM_SMEM>>>(
            d3_, wt_ + (size_t)(10+l)*65536, nullptr, nullptr,
            upd_b2 + l*256, nullptr, d1_, NN);
        // h = LN(h + d1)  (last layer writes straight into out)
        ln_k<<<784, 256>>>(h_, d1_, ln_g + l*256, ln_b + l*256,
                           (l == NL-1) ? hout : h_);
    }

    cudaMemsetAsync(ps_, 0, 24*HD*sizeof(float));
    cudaMemsetAsync(pc_, 0, 24*sizeof(float));
    pool_k<<<512, 256>>>(hout, batch, ntype, ps_, pc_);
    writeout_small_k<<<(6144+NN+255)/256, 256>>>(ps_, pc_, batch, out, out_size);
}